// round 4
// baseline (speedup 1.0000x reference)
#include <cuda_runtime.h>
#include <cuda_fp16.h>
#include <cstdint>
#include <cstddef>

#define HW 4096
#define CIN 1088
#define CMID 136
#define CPAD 144

// ---------------- scratch (device globals; zero-initialized, no allocs) ----------------
__device__ float  g_feat[2][2][(size_t)CMID * HW];        // [a/b][n][c*HW+p]
__device__ float  g_E[2][(size_t)HW * HW];                // energy (already *100)
__device__ __half g_corr_h[2][2][(size_t)HW * HW];        // fp16 corr, [ab/ba][n], [k][l] layout
__device__ __half g_raw_h[2][2][(size_t)CIN * HW];        // [a/b][n]
__device__ __half g_fah[2][2][(size_t)CPAD * HW];         // [hi/lo][n] fa normalized, [c][p]
__device__ __half g_fbt[2][2][(size_t)HW * CPAD];         // [hi/lo][n] fb normalized, [p][c] (transposed)
__device__ float  g_rowM[2][HW], g_rowSinv[2][HW];
__device__ float  g_colM[2][HW], g_colSinv[2][HW];

// ---------------- PTX helpers (proven in R1) ----------------
__device__ __forceinline__ uint32_t smaddr(const void* p) {
    return (uint32_t)__cvta_generic_to_shared(p);
}
__device__ __forceinline__ void ldsm4(uint32_t r[4], const void* p) {
    asm volatile("ldmatrix.sync.aligned.m8n8.x4.shared.b16 {%0,%1,%2,%3}, [%4];\n"
                 : "=r"(r[0]), "=r"(r[1]), "=r"(r[2]), "=r"(r[3]) : "r"(smaddr(p)));
}
__device__ __forceinline__ void ldsm4t(uint32_t r[4], const void* p) {
    asm volatile("ldmatrix.sync.aligned.m8n8.x4.trans.shared.b16 {%0,%1,%2,%3}, [%4];\n"
                 : "=r"(r[0]), "=r"(r[1]), "=r"(r[2]), "=r"(r[3]) : "r"(smaddr(p)));
}
__device__ __forceinline__ void mma16816(float* d, const uint32_t* a, const uint32_t* b) {
    asm volatile("mma.sync.aligned.m16n8k16.row.col.f32.f16.f16.f32 "
                 "{%0,%1,%2,%3}, {%4,%5,%6,%7}, {%8,%9}, {%0,%1,%2,%3};\n"
                 : "+f"(d[0]), "+f"(d[1]), "+f"(d[2]), "+f"(d[3])
                 : "r"(a[0]), "r"(a[1]), "r"(a[2]), "r"(a[3]), "r"(b[0]), "r"(b[1]));
}
__device__ __forceinline__ void cpa16u(uint32_t sm, const void* g, int bytes) {
    asm volatile("cp.async.cg.shared.global [%0], [%1], 16, %2;\n"
                 :: "r"(sm), "l"(g), "r"(bytes));
}
#define CP_COMMIT() asm volatile("cp.async.commit_group;\n" ::: "memory")
#define CP_WAIT(n)  asm volatile("cp.async.wait_group %0;\n" :: "n"(n) : "memory")

// ---------------- K1: 1x1 conv  Y[136,4096] = W@X + b (fp32) ----------------
__global__ void conv_kernel(const float* __restrict__ fa, const float* __restrict__ fb,
                            const float* __restrict__ Wa, const float* __restrict__ ba,
                            const float* __restrict__ Wb, const float* __restrict__ bb) {
    const int t = blockIdx.z, n = blockIdx.y;
    const float* __restrict__ X = (t == 0 ? fa : fb) + (size_t)n * CIN * HW;
    const float* __restrict__ W = (t == 0 ? Wa : Wb);
    const float* __restrict__ bias = (t == 0 ? ba : bb);

    __shared__ float Wsh[CMID][33];
    __shared__ __align__(16) float Xsh[32][64];

    const int tx = threadIdx.x & 15, ty = threadIdx.x >> 4;
    const int p0 = blockIdx.x * 64;

    float acc[17][4];
#pragma unroll
    for (int i = 0; i < 17; ++i)
#pragma unroll
        for (int j = 0; j < 4; ++j) acc[i][j] = 0.f;

    for (int c0 = 0; c0 < CIN; c0 += 32) {
        for (int id = threadIdx.x; id < CMID * 32; id += 128) {
            int o = id >> 5, k = id & 31;
            Wsh[o][k] = W[(size_t)o * CIN + c0 + k];
        }
        for (int id = threadIdx.x; id < 32 * 64; id += 128) {
            int k = id >> 6, j = id & 63;
            Xsh[k][j] = X[(size_t)(c0 + k) * HW + p0 + j];
        }
        __syncthreads();
#pragma unroll
        for (int k = 0; k < 32; ++k) {
            float xv[4];
            *(float4*)xv = *(const float4*)&Xsh[k][tx * 4];
#pragma unroll
            for (int i = 0; i < 17; ++i) {
                float wv = Wsh[ty + 8 * i][k];
                acc[i][0] += wv * xv[0]; acc[i][1] += wv * xv[1];
                acc[i][2] += wv * xv[2]; acc[i][3] += wv * xv[3];
            }
        }
        __syncthreads();
    }
    float* __restrict__ Y = g_feat[t][n];
#pragma unroll
    for (int i = 0; i < 17; ++i) {
        int o = ty + 8 * i;
        float bv = bias[o];
        float4 r = make_float4(acc[i][0] + bv, acc[i][1] + bv, acc[i][2] + bv, acc[i][3] + bv);
        *(float4*)&Y[(size_t)o * HW + p0 + tx * 4] = r;
    }
}

// ---------------- K2: InstanceNorm + LeakyReLU + mean-center ----------------
__global__ void inorm_kernel() {
    const int c = blockIdx.x, n = blockIdx.y, t = blockIdx.z;
    float* __restrict__ Y = &g_feat[t][n][(size_t)c * HW];
    __shared__ float sd[HW];
    __shared__ float r1[256], r2[256];
    const int tid = threadIdx.x;

    float s = 0.f, q = 0.f;
    for (int i = tid; i < HW; i += 256) { float v = Y[i]; sd[i] = v; s += v; q += v * v; }
    r1[tid] = s; r2[tid] = q; __syncthreads();
    for (int st = 128; st > 0; st >>= 1) {
        if (tid < st) { r1[tid] += r1[tid + st]; r2[tid] += r2[tid + st]; }
        __syncthreads();
    }
    const float mean = r1[0] * (1.f / HW);
    const float var  = r2[0] * (1.f / HW) - mean * mean;
    const float inv  = rsqrtf(var + 1e-5f);
    __syncthreads();

    float s2 = 0.f;
    for (int i = tid; i < HW; i += 256) {
        float v = (sd[i] - mean) * inv;
        v = (v >= 0.f) ? v : 0.2f * v;
        sd[i] = v; s2 += v;
    }
    r1[tid] = s2; __syncthreads();
    for (int st = 128; st > 0; st >>= 1) {
        if (tid < st) r1[tid] += r1[tid + st];
        __syncthreads();
    }
    const float mean2 = r1[0] * (1.f / HW);
    for (int i = tid; i < HW; i += 256) Y[i] = sd[i] - mean2;
}

// ---------------- K3: L2-normalize + split into fp16 hi/lo operands ----------------
// fa (t=0): [c][p] layout (energy B operand); fb (t=1): [p][c] transposed (energy A operand)
__global__ void l2norm_kernel() {
    const int p = blockIdx.x * 256 + threadIdx.x;
    const int n = blockIdx.y, t = blockIdx.z;
    const float* __restrict__ F = g_feat[t][n];
    float q = 0.f;
    for (int c = 0; c < CMID; ++c) { float v = F[(size_t)c * HW + p]; q += v * v; }
    const float inv = rsqrtf(q);
    if (t == 0) {
        __half* __restrict__ hi = g_fah[0][n];
        __half* __restrict__ lo = g_fah[1][n];
        for (int c = 0; c < CMID; ++c) {
            float v = F[(size_t)c * HW + p] * inv;
            __half h = __float2half_rn(v);
            hi[(size_t)c * HW + p] = h;
            lo[(size_t)c * HW + p] = __float2half_rn(v - __half2float(h));
        }
    } else {
        __half* __restrict__ hi = g_fbt[0][n];
        __half* __restrict__ lo = g_fbt[1][n];
        for (int c = 0; c < CMID; ++c) {
            float v = F[(size_t)c * HW + p] * inv;
            __half h = __float2half_rn(v);
            hi[(size_t)p * CPAD + c] = h;
            lo[(size_t)p * CPAD + c] = __float2half_rn(v - __half2float(h));
        }
    }
}

// ---------------- K4: energy via split-fp16 HMMA ----------------
// E[k,l] = 100 * sum_c fb[c,k]*fa[c,l];  3 passes: hi*hi + hi*lo + lo*hi (one fp32 accum)
// block 128x128, warp 32x64, K chunks of 48 (3 per 144-pass), 2-stage cp.async
#define E_AS_STRIDE (128 * 56)     // halves per A stage
#define E_BS_STRIDE (48 * 136)     // halves per B stage
__global__ __launch_bounds__(256, 1) void energy_mma_kernel() {
    extern __shared__ __align__(16) __half eshm[];
    __half* As = eshm;                          // [2][128][56]
    __half* Bs = eshm + 2 * E_AS_STRIDE;        // [2][48][136]
    const uint32_t su  = smaddr(As);
    const uint32_t suB = smaddr(Bs);

    const int n = blockIdx.z;
    const int m0 = blockIdx.y * 128, l0 = blockIdx.x * 128;
    const int tid = threadIdx.x, lane = tid & 31, warp = tid >> 5;
    const int wm = warp & 3, wn = warp >> 2;
    const int r16 = lane & 15, c8 = (lane >> 4) << 3;

    const __half* Ap[3] = { g_fbt[0][n], g_fbt[0][n], g_fbt[1][n] };
    const __half* Bp[3] = { g_fah[0][n], g_fah[1][n], g_fah[0][n] };

    float acc[2][8][4];
#pragma unroll
    for (int i = 0; i < 2; ++i)
#pragma unroll
        for (int j = 0; j < 8; ++j)
#pragma unroll
            for (int k = 0; k < 4; ++k) acc[i][j][k] = 0.f;

    auto loadst = [&](int s, int q) {
        const int pass = q / 3, kc = (q % 3) * 48;
        const __half* __restrict__ A = Ap[pass];
        const __half* __restrict__ B = Bp[pass];
#pragma unroll
        for (int i = 0; i < 3; ++i) {           // A: 128 rows x 96B
            int idx = tid + i * 256;
            int row = idx / 6, cp = (idx % 6) * 8;
            cpa16u(su + (s * E_AS_STRIDE + row * 56 + cp) * 2,
                   &A[(size_t)(m0 + row) * CPAD + kc + cp], 16);
        }
#pragma unroll
        for (int i = 0; i < 3; ++i) {           // B: 48 rows x 256B
            int idx = tid + i * 256;
            int row = idx >> 4, cp = (idx & 15) * 8;
            cpa16u(suB + (s * E_BS_STRIDE + row * 136 + cp) * 2,
                   &B[(size_t)(kc + row) * HW + l0 + cp], 16);
        }
    };

    loadst(0, 0); CP_COMMIT();
    for (int q = 0; q < 9; ++q) {
        const int s = q & 1;
        if (q + 1 < 9) { loadst(s ^ 1, q + 1); CP_COMMIT(); CP_WAIT(1); }
        else CP_WAIT(0);
        __syncthreads();
#pragma unroll
        for (int ks = 0; ks < 48; ks += 16) {
            uint32_t a[2][4], b[4][4];
#pragma unroll
            for (int mi = 0; mi < 2; ++mi)
                ldsm4(a[mi], As + s * E_AS_STRIDE + (wm * 32 + mi * 16 + r16) * 56 + ks + c8);
#pragma unroll
            for (int nj = 0; nj < 4; ++nj)
                ldsm4t(b[nj], Bs + s * E_BS_STRIDE + (ks + r16) * 136 + wn * 64 + nj * 16 + c8);
#pragma unroll
            for (int mi = 0; mi < 2; ++mi)
#pragma unroll
                for (int nj = 0; nj < 4; ++nj) {
                    mma16816(acc[mi][nj * 2],     a[mi], &b[nj][0]);
                    mma16816(acc[mi][nj * 2 + 1], a[mi], &b[nj][2]);
                }
        }
        __syncthreads();
    }

    float* __restrict__ E = g_E[n];
#pragma unroll
    for (int mi = 0; mi < 2; ++mi)
#pragma unroll
        for (int nj = 0; nj < 8; ++nj) {
            int row = m0 + wm * 32 + mi * 16 + (lane >> 2);
            int col = l0 + wn * 64 + nj * 8 + (lane & 3) * 2;
            *(float2*)&E[(size_t)row * HW + col] =
                make_float2(acc[mi][nj][0] * 100.f, acc[mi][nj][1] * 100.f);
            *(float2*)&E[(size_t)(row + 8) * HW + col] =
                make_float2(acc[mi][nj][2] * 100.f, acc[mi][nj][3] * 100.f);
        }
}

// ---------------- K5a: row stats ----------------
__global__ void rowstat_kernel() {
    const int row = blockIdx.x, n = blockIdx.y;
    const float* __restrict__ e = &g_E[n][(size_t)row * HW];
    const int tid = threadIdx.x;
    float v[16];
    float m = -1e30f;
#pragma unroll
    for (int i = 0; i < 16; ++i) { v[i] = e[tid + i * 256]; m = fmaxf(m, v[i]); }
    __shared__ float red[256];
    red[tid] = m; __syncthreads();
    for (int st = 128; st > 0; st >>= 1) {
        if (tid < st) red[tid] = fmaxf(red[tid], red[tid + st]);
        __syncthreads();
    }
    m = red[0]; __syncthreads();
    float s = 0.f;
#pragma unroll
    for (int i = 0; i < 16; ++i) s += __expf(v[i] - m);
    red[tid] = s; __syncthreads();
    for (int st = 128; st > 0; st >>= 1) {
        if (tid < st) red[tid] += red[tid + st];
        __syncthreads();
    }
    if (tid == 0) { g_rowM[n][row] = m; g_rowSinv[n][row] = 1.0f / red[0]; }
}

// ---------------- K5b: column stats (online) ----------------
__global__ void colstat_kernel() {
    const int n = blockIdx.y;
    const int k0 = blockIdx.x * 64;
    const float* __restrict__ E = g_E[n];
    const int tid = threadIdx.x;
    const int tx = tid & 63, ty = tid >> 6;
    float m = -1e30f, s = 0.f;
    for (int l = ty; l < HW; l += 4) {
        float e = E[(size_t)l * HW + k0 + tx];
        float mn = fmaxf(m, e);
        s = s * __expf(m - mn) + __expf(e - mn);
        m = mn;
    }
    __shared__ float sm_m[4][64], sm_s[4][64];
    sm_m[ty][tx] = m; sm_s[ty][tx] = s; __syncthreads();
    if (ty == 0) {
        float mm = fmaxf(fmaxf(sm_m[0][tx], sm_m[1][tx]), fmaxf(sm_m[2][tx], sm_m[3][tx]));
        float S = sm_s[0][tx] * __expf(sm_m[0][tx] - mm) + sm_s[1][tx] * __expf(sm_m[1][tx] - mm)
                + sm_s[2][tx] * __expf(sm_m[2][tx] - mm) + sm_s[3][tx] * __expf(sm_m[3][tx] - mm);
        g_colM[n][k0 + tx] = mm;
        g_colSinv[n][k0 + tx] = 1.0f / S;
    }
}

// ---------------- K5c: softmax writeout (fp32 + fp16, one E pass) ----------------
__global__ void writeout_kernel(float* __restrict__ out_ab, float* __restrict__ out_ba) {
    const int c0 = blockIdx.x * 64, r0 = blockIdx.y * 64, n = blockIdx.z;
    const int tid = threadIdx.x;
    const int tx = tid & 63, ty = tid >> 6;
    const float* __restrict__ E = g_E[n];
    __half* __restrict__ Hab = g_corr_h[0][n];
    __half* __restrict__ Hba = g_corr_h[1][n];
    float* __restrict__ Oab = out_ab + (size_t)n * HW * HW;
    float* __restrict__ Oba = out_ba + (size_t)n * HW * HW;

    __shared__ float t_ba[64][65];
    __shared__ float rm_s[64], rsi_s[64];
    if (tid < 64)       rm_s[tid]       = g_rowM[n][r0 + tid];
    else if (tid < 128) rsi_s[tid - 64] = g_rowSinv[n][r0 + tid - 64];
    const float cm  = g_colM[n][c0 + tx];
    const float csi = g_colSinv[n][c0 + tx];
    __syncthreads();

#pragma unroll 4
    for (int it = 0; it < 16; ++it) {
        int r_in = it * 4 + ty;
        int R = r0 + r_in, C = c0 + tx;
        float e = E[(size_t)R * HW + C];
        float pr = __expf(e - rm_s[r_in]) * rsi_s[r_in];
        float pc = __expf(e - cm) * csi;
        size_t off = (size_t)R * HW + C;
        Oab[off] = pr;
        Hab[off] = __float2half_rn(pr);
        t_ba[tx][r_in] = pc;
    }
    __syncthreads();
#pragma unroll 4
    for (int it = 0; it < 16; ++it) {
        int c_in = it * 4 + ty;
        float p = t_ba[c_in][tx];
        size_t off = (size_t)(c0 + c_in) * HW + r0 + tx;
        Oba[off] = p;
        Hba[off] = __float2half_rn(p);
    }
}

// ---------------- K6: raw -> fp16 ----------------
__global__ void tohalf_kernel(const float* __restrict__ a_raw, const float* __restrict__ b_raw) {
    const int t = blockIdx.y;
    const float* __restrict__ src = (t == 0 ? a_raw : b_raw);
    __half* __restrict__ dst = &g_raw_h[t][0][0];
    size_t i = ((size_t)blockIdx.x * 256 + threadIdx.x) * 4;
    float4 v = *(const float4*)&src[i];
    __half2* d2 = (__half2*)&dst[i];
    d2[0] = __floats2half2_rn(v.x, v.y);
    d2[1] = __floats2half2_rn(v.z, v.w);
}

// ---------------- K7: warp matmul  C[1088,4096] = raw @ corr, 128x256 tile ----------------
#define G_AS_STRIDE (128 * 40)    // halves per A stage
#define G_BS_STRIDE (32 * 264)    // halves per B stage
#define G_NK 128
__global__ __launch_bounds__(256, 1) void wgemm_kernel(float* __restrict__ out) {
    extern __shared__ __align__(16) __half eshm[];
    __half* As = eshm;                          // [3][128][40]
    __half* Bs = eshm + 3 * G_AS_STRIDE;        // [3][32][264]
    const uint32_t su  = smaddr(As);
    const uint32_t suB = smaddr(Bs);

    const int z = blockIdx.z;
    const int dir = z >> 1, n = z & 1;
    const __half* __restrict__ A = g_raw_h[dir][n];
    const __half* __restrict__ B = g_corr_h[dir ^ 1][n];
    float* __restrict__ C = out + (size_t)4 * HW * HW
                                + (size_t)dir * 2 * CIN * HW + (size_t)n * CIN * HW;
    const int m0 = blockIdx.y * 128, n0 = blockIdx.x * 256;
    const int tid = threadIdx.x, lane = tid & 31, warp = tid >> 5;
    const int wm = warp & 1, wn = warp >> 1;
    const int r16 = lane & 15, c8 = (lane >> 4) << 3;

    float acc[4][8][4];
#pragma unroll
    for (int i = 0; i < 4; ++i)
#pragma unroll
        for (int j = 0; j < 8; ++j)
#pragma unroll
            for (int k = 0; k < 4; ++k) acc[i][j][k] = 0.f;

    auto loadst = [&](int s, int j) {
        const int k0 = j * 32;
#pragma unroll
        for (int i = 0; i < 2; ++i) {           // A: 128 rows x 64B
            int idx = tid + i * 256;
            int row = idx >> 2, cp = (idx & 3) * 8;
            int gr = m0 + row;
            int ok = gr < CIN;
            cpa16u(su + (s * G_AS_STRIDE + row * 40 + cp) * 2,
                   &A[(size_t)(ok ? gr : 0) * HW + k0 + cp], ok ? 16 : 0);
        }
#pragma unroll
        for (int i = 0; i < 4; ++i) {           // B: 32 rows x 512B
            int idx = tid + i * 256;
            int row = idx >> 5, cp = (idx & 31) * 8;
            cpa16u(suB + (s * G_BS_STRIDE + row * 264 + cp) * 2,
                   &B[(size_t)(k0 + row) * HW + n0 + cp], 16);
        }
    };

    loadst(0, 0); CP_COMMIT();
    loadst(1, 1); CP_COMMIT();

    for (int j = 0; j < G_NK; ++j) {
        const int s = j % 3;
        if (j + 2 < G_NK) { loadst((j + 2) % 3, j + 2); CP_COMMIT(); CP_WAIT(2); }
        else if (j + 1 < G_NK) CP_WAIT(1);
        else CP_WAIT(0);
        __syncthreads();
#pragma unroll
        for (int ks = 0; ks < 32; ks += 16) {
            uint32_t a[4][4], b[4][4];
#pragma unroll
            for (int mi = 0; mi < 4; ++mi)
                ldsm4(a[mi], As + s * G_AS_STRIDE + (wm * 64 + mi * 16 + r16) * 40 + ks + c8);
#pragma unroll
            for (int nj = 0; nj < 4; ++nj)
                ldsm4t(b[nj], Bs + s * G_BS_STRIDE + (ks + r16) * 264 + wn * 64 + nj * 16 + c8);
#pragma unroll
            for (int mi = 0; mi < 4; ++mi)
#pragma unroll
                for (int nj = 0; nj < 4; ++nj) {
                    mma16816(acc[mi][nj * 2],     a[mi], &b[nj][0]);
                    mma16816(acc[mi][nj * 2 + 1], a[mi], &b[nj][2]);
                }
        }
        __syncthreads();
    }

#pragma unroll
    for (int mi = 0; mi < 4; ++mi)
#pragma unroll
        for (int nj = 0; nj < 8; ++nj) {
            int row = m0 + wm * 64 + mi * 16 + (lane >> 2);
            int col = n0 + wn * 64 + nj * 8 + (lane & 3) * 2;
            if (row < CIN)
                *(float2*)&C[(size_t)row * HW + col] = make_float2(acc[mi][nj][0], acc[mi][nj][1]);
            if (row + 8 < CIN)
                *(float2*)&C[(size_t)(row + 8) * HW + col] = make_float2(acc[mi][nj][2], acc[mi][nj][3]);
        }
}

// ---------------- launch ----------------
extern "C" void kernel_launch(void* const* d_in, const int* in_sizes, int n_in,
                              void* d_out, int out_size) {
    const float* fa    = (const float*)d_in[0];
    const float* fb    = (const float*)d_in[1];
    const float* a_raw = (const float*)d_in[2];
    const float* b_raw = (const float*)d_in[3];
    const float* Wa    = (const float*)d_in[4];
    const float* ba    = (const float*)d_in[5];
    const float* Wb    = (const float*)d_in[6];
    const float* bb    = (const float*)d_in[7];
    float* out = (float*)d_out;

    const int e_smem = (2 * E_AS_STRIDE + 2 * E_BS_STRIDE) * 2;     // 54784
    const int g_smem = (3 * G_AS_STRIDE + 3 * G_BS_STRIDE) * 2;     // 81408
    cudaFuncSetAttribute(energy_mma_kernel, cudaFuncAttributeMaxDynamicSharedMemorySize, e_smem);
    cudaFuncSetAttribute(wgemm_kernel, cudaFuncAttributeMaxDynamicSharedMemorySize, g_smem);

    conv_kernel<<<dim3(64, 2, 2), 128>>>(fa, fb, Wa, ba, Wb, bb);
    inorm_kernel<<<dim3(CMID, 2, 2), 256>>>();
    l2norm_kernel<<<dim3(HW / 256, 2, 2), 256>>>();
    energy_mma_kernel<<<dim3(32, 32, 2), 256, e_smem>>>();
    tohalf_kernel<<<dim3(8704, 2), 256>>>(a_raw, b_raw);
    rowstat_kernel<<<dim3(HW, 2), 256>>>();
    colstat_kernel<<<dim3(64, 2), 256>>>();
    writeout_kernel<<<dim3(64, 64, 2), 256>>>(out, out + (size_t)2 * HW * HW);
    wgemm_kernel<<<dim3(16, 9, 4), 256, g_smem>>>(out);
}

// round 5
// speedup vs baseline: 1.0591x; 1.0591x over previous
#include <cuda_runtime.h>
#include <cuda_fp16.h>
#include <cstdint>
#include <cstddef>

#define HW 4096
#define CIN 1088
#define CMID 136
#define CPAD 144

// ---------------- scratch (device globals; zero-initialized, no allocs) ----------------
__device__ float  g_feat[2][2][(size_t)CMID * HW];        // [a/b][n][c*HW+p]
__device__ float  g_E[2][(size_t)HW * HW];                // energy (already *100)
__device__ __half g_corr_h[2][2][(size_t)HW * HW];        // fp16 corr, [ab/ba][n], [k][l]
__device__ __half g_raw_h[2][2][(size_t)CIN * HW];        // [a/b][n]
__device__ __half g_fh[2][2][2][(size_t)CPAD * HW];       // [a/b][hi/lo][n], [c][p]; pad rows stay 0
__device__ float  g_rowM[2][HW], g_rowSinv[2][HW];
__device__ float  g_colM[2][HW], g_colSinv[2][HW];

// ---------------- PTX helpers ----------------
__device__ __forceinline__ uint32_t smaddr(const void* p) {
    return (uint32_t)__cvta_generic_to_shared(p);
}
__device__ __forceinline__ void ldsm4(uint32_t r[4], const void* p) {
    asm volatile("ldmatrix.sync.aligned.m8n8.x4.shared.b16 {%0,%1,%2,%3}, [%4];\n"
                 : "=r"(r[0]), "=r"(r[1]), "=r"(r[2]), "=r"(r[3]) : "r"(smaddr(p)));
}
__device__ __forceinline__ void ldsm4t(uint32_t r[4], const void* p) {
    asm volatile("ldmatrix.sync.aligned.m8n8.x4.trans.shared.b16 {%0,%1,%2,%3}, [%4];\n"
                 : "=r"(r[0]), "=r"(r[1]), "=r"(r[2]), "=r"(r[3]) : "r"(smaddr(p)));
}
__device__ __forceinline__ void mma16816(float* d, const uint32_t* a, const uint32_t* b) {
    asm volatile("mma.sync.aligned.m16n8k16.row.col.f32.f16.f16.f32 "
                 "{%0,%1,%2,%3}, {%4,%5,%6,%7}, {%8,%9}, {%0,%1,%2,%3};\n"
                 : "+f"(d[0]), "+f"(d[1]), "+f"(d[2]), "+f"(d[3])
                 : "r"(a[0]), "r"(a[1]), "r"(a[2]), "r"(a[3]), "r"(b[0]), "r"(b[1]));
}
__device__ __forceinline__ void cpa16u(uint32_t sm, const void* g, int bytes) {
    asm volatile("cp.async.cg.shared.global [%0], [%1], 16, %2;\n"
                 :: "r"(sm), "l"(g), "r"(bytes));
}
#define CP_COMMIT() asm volatile("cp.async.commit_group;\n" ::: "memory")
#define CP_WAIT(n)  asm volatile("cp.async.wait_group %0;\n" :: "n"(n) : "memory")

// ---------------- K1: 1x1 conv  Y[136,4096] = W@X + b (fp32) ----------------
__global__ void conv_kernel(const float* __restrict__ fa, const float* __restrict__ fb,
                            const float* __restrict__ Wa, const float* __restrict__ ba,
                            const float* __restrict__ Wb, const float* __restrict__ bb) {
    const int t = blockIdx.z, n = blockIdx.y;
    const float* __restrict__ X = (t == 0 ? fa : fb) + (size_t)n * CIN * HW;
    const float* __restrict__ W = (t == 0 ? Wa : Wb);
    const float* __restrict__ bias = (t == 0 ? ba : bb);

    __shared__ float Wsh[CMID][33];
    __shared__ __align__(16) float Xsh[32][64];

    const int tx = threadIdx.x & 15, ty = threadIdx.x >> 4;
    const int p0 = blockIdx.x * 64;

    float acc[17][4];
#pragma unroll
    for (int i = 0; i < 17; ++i)
#pragma unroll
        for (int j = 0; j < 4; ++j) acc[i][j] = 0.f;

    for (int c0 = 0; c0 < CIN; c0 += 32) {
        for (int id = threadIdx.x; id < CMID * 32; id += 128) {
            int o = id >> 5, k = id & 31;
            Wsh[o][k] = W[(size_t)o * CIN + c0 + k];
        }
        for (int id = threadIdx.x; id < 32 * 64; id += 128) {
            int k = id >> 6, j = id & 63;
            Xsh[k][j] = X[(size_t)(c0 + k) * HW + p0 + j];
        }
        __syncthreads();
#pragma unroll
        for (int k = 0; k < 32; ++k) {
            float xv[4];
            *(float4*)xv = *(const float4*)&Xsh[k][tx * 4];
#pragma unroll
            for (int i = 0; i < 17; ++i) {
                float wv = Wsh[ty + 8 * i][k];
                acc[i][0] += wv * xv[0]; acc[i][1] += wv * xv[1];
                acc[i][2] += wv * xv[2]; acc[i][3] += wv * xv[3];
            }
        }
        __syncthreads();
    }
    float* __restrict__ Y = g_feat[t][n];
#pragma unroll
    for (int i = 0; i < 17; ++i) {
        int o = ty + 8 * i;
        float bv = bias[o];
        float4 r = make_float4(acc[i][0] + bv, acc[i][1] + bv, acc[i][2] + bv, acc[i][3] + bv);
        *(float4*)&Y[(size_t)o * HW + p0 + tx * 4] = r;
    }
}

// ---------------- K2: InstanceNorm + LeakyReLU + mean-center ----------------
__global__ void inorm_kernel() {
    const int c = blockIdx.x, n = blockIdx.y, t = blockIdx.z;
    float* __restrict__ Y = &g_feat[t][n][(size_t)c * HW];
    __shared__ float sd[HW];
    __shared__ float r1[256], r2[256];
    const int tid = threadIdx.x;

    float s = 0.f, q = 0.f;
    for (int i = tid; i < HW; i += 256) { float v = Y[i]; sd[i] = v; s += v; q += v * v; }
    r1[tid] = s; r2[tid] = q; __syncthreads();
    for (int st = 128; st > 0; st >>= 1) {
        if (tid < st) { r1[tid] += r1[tid + st]; r2[tid] += r2[tid + st]; }
        __syncthreads();
    }
    const float mean = r1[0] * (1.f / HW);
    const float var  = r2[0] * (1.f / HW) - mean * mean;
    const float inv  = rsqrtf(var + 1e-5f);
    __syncthreads();

    float s2 = 0.f;
    for (int i = tid; i < HW; i += 256) {
        float v = (sd[i] - mean) * inv;
        v = (v >= 0.f) ? v : 0.2f * v;
        sd[i] = v; s2 += v;
    }
    r1[tid] = s2; __syncthreads();
    for (int st = 128; st > 0; st >>= 1) {
        if (tid < st) r1[tid] += r1[tid + st];
        __syncthreads();
    }
    const float mean2 = r1[0] * (1.f / HW);
    for (int i = tid; i < HW; i += 256) Y[i] = sd[i] - mean2;
}

// ---------------- K3: L2-normalize + split hi/lo (coalesced [c][p]) ----------------
__global__ void l2norm_kernel() {
    const int p = blockIdx.x * 256 + threadIdx.x;
    const int n = blockIdx.y, t = blockIdx.z;
    const float* __restrict__ F = g_feat[t][n];
    float q = 0.f;
    for (int c = 0; c < CMID; ++c) { float v = F[(size_t)c * HW + p]; q += v * v; }
    const float inv = rsqrtf(q);
    __half* __restrict__ hi = g_fh[t][0][n];
    __half* __restrict__ lo = g_fh[t][1][n];
    for (int c = 0; c < CMID; ++c) {
        float v = F[(size_t)c * HW + p] * inv;
        __half h = __float2half_rn(v);
        hi[(size_t)c * HW + p] = h;
        lo[(size_t)c * HW + p] = __float2half_rn(v - __half2float(h));
    }
}

// ---------------- K4: energy via split-fp16 HMMA ----------------
// E[k,l] = 100 * sum_c fb[c,k]*fa[c,l]; passes hh + h*lo + lo*h, one fp32 accum.
// Both operands [c][p]; A via ldmatrix.trans. 512 thr, 16 warps (4x4), warp 32x32.
#define E_ST (48 * 136)   // halves per stage per matrix
__global__ __launch_bounds__(512, 1) void energy_mma_kernel() {
    extern __shared__ __align__(16) __half eshm[];
    __half* As = eshm;                    // [2][48][136]
    __half* Bs = eshm + 2 * E_ST;         // [2][48][136]

    const int n = blockIdx.z;
    const int m0 = blockIdx.y * 128, l0 = blockIdx.x * 128;
    const int tid = threadIdx.x, lane = tid & 31, warp = tid >> 5;
    const int wm = warp & 3, wn = warp >> 2;
    const int r16 = lane & 15, c8 = (lane >> 4) << 3;
    // A-trans ldmatrix addressing (fragment a0..a3 of m16k16 from [k][m] tile)
    const int arow = (lane & 7) + ((lane >> 4) & 1) * 8;
    const int acol = ((lane >> 3) & 1) * 8;

    const __half* Ap[3] = { g_fh[1][0][n], g_fh[1][0][n], g_fh[1][1][n] };
    const __half* Bp[3] = { g_fh[0][0][n], g_fh[0][1][n], g_fh[0][0][n] };

    float acc[2][4][4];
#pragma unroll
    for (int i = 0; i < 2; ++i)
#pragma unroll
        for (int j = 0; j < 4; ++j)
#pragma unroll
            for (int k = 0; k < 4; ++k) acc[i][j][k] = 0.f;

    const uint32_t su = smaddr(eshm);
    auto loadst = [&](int s, int q) {
        const int pass = q / 3, kc = (q % 3) * 48;
        const __half* __restrict__ A = Ap[pass];
        const __half* __restrict__ B = Bp[pass];
#pragma unroll
        for (int i = 0; i < 3; ++i) {
            int idx = tid + i * 512;
            if (idx < 768) {
                int row = idx >> 4, cp = (idx & 15) * 8;
                cpa16u(su + (s * E_ST + row * 136 + cp) * 2,
                       &A[(size_t)(kc + row) * HW + m0 + cp], 16);
            } else {
                int ix = idx - 768;
                int row = ix >> 4, cp = (ix & 15) * 8;
                cpa16u(su + (2 * E_ST + s * E_ST + row * 136 + cp) * 2,
                       &B[(size_t)(kc + row) * HW + l0 + cp], 16);
            }
        }
    };

    loadst(0, 0); CP_COMMIT();
    for (int q = 0; q < 9; ++q) {
        const int s = q & 1;
        if (q + 1 < 9) { loadst(s ^ 1, q + 1); CP_COMMIT(); CP_WAIT(1); }
        else CP_WAIT(0);
        __syncthreads();
#pragma unroll
        for (int ks = 0; ks < 48; ks += 16) {
            uint32_t a[2][4], b[2][4];
#pragma unroll
            for (int mi = 0; mi < 2; ++mi)
                ldsm4t(a[mi], As + s * E_ST + (ks + arow) * 136 + wm * 32 + mi * 16 + acol);
#pragma unroll
            for (int nj = 0; nj < 2; ++nj)
                ldsm4t(b[nj], Bs + s * E_ST + (ks + r16) * 136 + wn * 32 + nj * 16 + c8);
#pragma unroll
            for (int mi = 0; mi < 2; ++mi)
#pragma unroll
                for (int nj = 0; nj < 2; ++nj) {
                    mma16816(acc[mi][nj * 2],     a[mi], &b[nj][0]);
                    mma16816(acc[mi][nj * 2 + 1], a[mi], &b[nj][2]);
                }
        }
        __syncthreads();
    }

    float* __restrict__ E = g_E[n];
#pragma unroll
    for (int mi = 0; mi < 2; ++mi)
#pragma unroll
        for (int j = 0; j < 4; ++j) {
            int row = m0 + wm * 32 + mi * 16 + (lane >> 2);
            int col = l0 + wn * 32 + j * 8 + (lane & 3) * 2;
            *(float2*)&E[(size_t)row * HW + col] =
                make_float2(acc[mi][j][0] * 100.f, acc[mi][j][1] * 100.f);
            *(float2*)&E[(size_t)(row + 8) * HW + col] =
                make_float2(acc[mi][j][2] * 100.f, acc[mi][j][3] * 100.f);
        }
}

// ---------------- K5a: row stats ----------------
__global__ void rowstat_kernel() {
    const int row = blockIdx.x, n = blockIdx.y;
    const float* __restrict__ e = &g_E[n][(size_t)row * HW];
    const int tid = threadIdx.x;
    float v[16];
    float m = -1e30f;
#pragma unroll
    for (int i = 0; i < 16; ++i) { v[i] = e[tid + i * 256]; m = fmaxf(m, v[i]); }
    __shared__ float red[256];
    red[tid] = m; __syncthreads();
    for (int st = 128; st > 0; st >>= 1) {
        if (tid < st) red[tid] = fmaxf(red[tid], red[tid + st]);
        __syncthreads();
    }
    m = red[0]; __syncthreads();
    float s = 0.f;
#pragma unroll
    for (int i = 0; i < 16; ++i) s += __expf(v[i] - m);
    red[tid] = s; __syncthreads();
    for (int st = 128; st > 0; st >>= 1) {
        if (tid < st) red[tid] += red[tid + st];
        __syncthreads();
    }
    if (tid == 0) { g_rowM[n][row] = m; g_rowSinv[n][row] = 1.0f / red[0]; }
}

// ---------------- K5b: column stats (online) ----------------
__global__ void colstat_kernel() {
    const int n = blockIdx.y;
    const int k0 = blockIdx.x * 64;
    const float* __restrict__ E = g_E[n];
    const int tid = threadIdx.x;
    const int tx = tid & 63, ty = tid >> 6;
    float m = -1e30f, s = 0.f;
    for (int l = ty; l < HW; l += 4) {
        float e = E[(size_t)l * HW + k0 + tx];
        float mn = fmaxf(m, e);
        s = s * __expf(m - mn) + __expf(e - mn);
        m = mn;
    }
    __shared__ float sm_m[4][64], sm_s[4][64];
    sm_m[ty][tx] = m; sm_s[ty][tx] = s; __syncthreads();
    if (ty == 0) {
        float mm = fmaxf(fmaxf(sm_m[0][tx], sm_m[1][tx]), fmaxf(sm_m[2][tx], sm_m[3][tx]));
        float S = sm_s[0][tx] * __expf(sm_m[0][tx] - mm) + sm_s[1][tx] * __expf(sm_m[1][tx] - mm)
                + sm_s[2][tx] * __expf(sm_m[2][tx] - mm) + sm_s[3][tx] * __expf(sm_m[3][tx] - mm);
        g_colM[n][k0 + tx] = mm;
        g_colSinv[n][k0 + tx] = 1.0f / S;
    }
}

// ---------------- K5c: softmax writeout (fp32 + fp16, one E pass) ----------------
__global__ void writeout_kernel(float* __restrict__ out_ab, float* __restrict__ out_ba) {
    const int c0 = blockIdx.x * 64, r0 = blockIdx.y * 64, n = blockIdx.z;
    const int tid = threadIdx.x;
    const int tx = tid & 63, ty = tid >> 6;
    const float* __restrict__ E = g_E[n];
    __half* __restrict__ Hab = g_corr_h[0][n];
    __half* __restrict__ Hba = g_corr_h[1][n];
    float* __restrict__ Oab = out_ab + (size_t)n * HW * HW;
    float* __restrict__ Oba = out_ba + (size_t)n * HW * HW;

    __shared__ float t_ba[64][65];
    __shared__ float rm_s[64], rsi_s[64];
    if (tid < 64)       rm_s[tid]       = g_rowM[n][r0 + tid];
    else if (tid < 128) rsi_s[tid - 64] = g_rowSinv[n][r0 + tid - 64];
    const float cm  = g_colM[n][c0 + tx];
    const float csi = g_colSinv[n][c0 + tx];
    __syncthreads();

#pragma unroll 4
    for (int it = 0; it < 16; ++it) {
        int r_in = it * 4 + ty;
        int R = r0 + r_in, C = c0 + tx;
        float e = E[(size_t)R * HW + C];
        float pr = __expf(e - rm_s[r_in]) * rsi_s[r_in];
        float pc = __expf(e - cm) * csi;
        size_t off = (size_t)R * HW + C;
        Oab[off] = pr;
        Hab[off] = __float2half_rn(pr);
        t_ba[tx][r_in] = pc;
    }
    __syncthreads();
#pragma unroll 4
    for (int it = 0; it < 16; ++it) {
        int c_in = it * 4 + ty;
        float p = t_ba[c_in][tx];
        size_t off = (size_t)(c0 + c_in) * HW + r0 + tx;
        Oba[off] = p;
        Hba[off] = __float2half_rn(p);
    }
}

// ---------------- K6: raw -> fp16 ----------------
__global__ void tohalf_kernel(const float* __restrict__ a_raw, const float* __restrict__ b_raw) {
    const int t = blockIdx.y;
    const float* __restrict__ src = (t == 0 ? a_raw : b_raw);
    __half* __restrict__ dst = &g_raw_h[t][0][0];
    size_t i = ((size_t)blockIdx.x * 256 + threadIdx.x) * 4;
    float4 v = *(const float4*)&src[i];
    __half2* d2 = (__half2*)&dst[i];
    d2[0] = __floats2half2_rn(v.x, v.y);
    d2[1] = __floats2half2_rn(v.z, v.w);
}

// ---------------- K7: warp matmul  C[1088,4096] = raw @ corr ----------------
// 512 thr, 16 warps (4x4), block 128x256, warp 32x64, 3-stage cp.async
#define G_AS (128 * 40)
#define G_BS (32 * 264)
#define G_NK 128
__global__ __launch_bounds__(512, 1) void wgemm_kernel(float* __restrict__ out) {
    extern __shared__ __align__(16) __half gshm[];
    __half* As = gshm;                    // [3][128][40]
    __half* Bs = gshm + 3 * G_AS;         // [3][32][264]
    const uint32_t su = smaddr(gshm);

    const int z = blockIdx.z;
    const int dir = z >> 1, n = z & 1;
    const __half* __restrict__ A = g_raw_h[dir][n];
    const __half* __restrict__ B = g_corr_h[dir ^ 1][n];
    float* __restrict__ C = out + (size_t)4 * HW * HW
                                + (size_t)dir * 2 * CIN * HW + (size_t)n * CIN * HW;
    const int m0 = blockIdx.y * 128, n0 = blockIdx.x * 256;
    const int tid = threadIdx.x, lane = tid & 31, warp = tid >> 5;
    const int wm = warp & 3, wn = warp >> 2;
    const int r16 = lane & 15, c8 = (lane >> 4) << 3;

    float acc[2][8][4];
#pragma unroll
    for (int i = 0; i < 2; ++i)
#pragma unroll
        for (int j = 0; j < 8; ++j)
#pragma unroll
            for (int k = 0; k < 4; ++k) acc[i][j][k] = 0.f;

    auto loadst = [&](int s, int j) {
        const int k0 = j * 32;
#pragma unroll
        for (int i = 0; i < 3; ++i) {
            int idx = tid + i * 512;
            if (idx < 512) {
                int row = idx >> 2, cp = (idx & 3) * 8;
                int gr = m0 + row;
                int ok = gr < CIN;
                cpa16u(su + (s * G_AS + row * 40 + cp) * 2,
                       &A[(size_t)(ok ? gr : 0) * HW + k0 + cp], ok ? 16 : 0);
            } else {
                int ix = idx - 512;
                int row = ix >> 5, cp = (ix & 31) * 8;
                cpa16u(su + (3 * G_AS + s * G_BS + row * 264 + cp) * 2,
                       &B[(size_t)(k0 + row) * HW + n0 + cp], 16);
            }
        }
    };

    loadst(0, 0); CP_COMMIT();
    loadst(1, 1); CP_COMMIT();

    for (int j = 0; j < G_NK; ++j) {
        const int s = j % 3;
        if (j + 2 < G_NK) { loadst((j + 2) % 3, j + 2); CP_COMMIT(); CP_WAIT(2); }
        else if (j + 1 < G_NK) CP_WAIT(1);
        else CP_WAIT(0);
        __syncthreads();
#pragma unroll
        for (int ks = 0; ks < 32; ks += 16) {
            uint32_t a[2][4], b[4][4];
#pragma unroll
            for (int mi = 0; mi < 2; ++mi)
                ldsm4(a[mi], As + s * G_AS + (wm * 32 + mi * 16 + r16) * 40 + ks + c8);
#pragma unroll
            for (int nj = 0; nj < 4; ++nj)
                ldsm4t(b[nj], Bs + s * G_BS + (ks + r16) * 264 + wn * 64 + nj * 16 + c8);
#pragma unroll
            for (int mi = 0; mi < 2; ++mi)
#pragma unroll
                for (int nj = 0; nj < 4; ++nj) {
                    mma16816(acc[mi][nj * 2],     a[mi], &b[nj][0]);
                    mma16816(acc[mi][nj * 2 + 1], a[mi], &b[nj][2]);
                }
        }
        __syncthreads();
    }

#pragma unroll
    for (int mi = 0; mi < 2; ++mi)
#pragma unroll
        for (int nj = 0; nj < 8; ++nj) {
            int row = m0 + wm * 32 + mi * 16 + (lane >> 2);
            int col = n0 + wn * 64 + nj * 8 + (lane & 3) * 2;
            if (row < CIN)
                *(float2*)&C[(size_t)row * HW + col] = make_float2(acc[mi][nj][0], acc[mi][nj][1]);
            if (row + 8 < CIN)
                *(float2*)&C[(size_t)(row + 8) * HW + col] = make_float2(acc[mi][nj][2], acc[mi][nj][3]);
        }
}

// ---------------- launch ----------------
extern "C" void kernel_launch(void* const* d_in, const int* in_sizes, int n_in,
                              void* d_out, int out_size) {
    const float* fa    = (const float*)d_in[0];
    const float* fb    = (const float*)d_in[1];
    const float* a_raw = (const float*)d_in[2];
    const float* b_raw = (const float*)d_in[3];
    const float* Wa    = (const float*)d_in[4];
    const float* ba    = (const float*)d_in[5];
    const float* Wb    = (const float*)d_in[6];
    const float* bb    = (const float*)d_in[7];
    float* out = (float*)d_out;

    const int e_smem = 4 * E_ST * 2;                     // 52224
    const int g_smem = (3 * G_AS + 3 * G_BS) * 2;        // 81408
    cudaFuncSetAttribute(energy_mma_kernel, cudaFuncAttributeMaxDynamicSharedMemorySize, e_smem);
    cudaFuncSetAttribute(wgemm_kernel, cudaFuncAttributeMaxDynamicSharedMemorySize, g_smem);

    conv_kernel<<<dim3(64, 2, 2), 128>>>(fa, fb, Wa, ba, Wb, bb);
    inorm_kernel<<<dim3(CMID, 2, 2), 256>>>();
    l2norm_kernel<<<dim3(HW / 256, 2, 2), 256>>>();
    energy_mma_kernel<<<dim3(32, 32, 2), 512, e_smem>>>();
    tohalf_kernel<<<dim3(8704, 2), 256>>>(a_raw, b_raw);
    rowstat_kernel<<<dim3(HW, 2), 256>>>();
    colstat_kernel<<<dim3(64, 2), 256>>>();
    writeout_kernel<<<dim3(64, 64, 2), 256>>>(out, out + (size_t)2 * HW * HW);
    wgemm_kernel<<<dim3(16, 9, 4), 512, g_smem>>>(out);
}

// round 6
// speedup vs baseline: 1.4558x; 1.3747x over previous
#include <cuda_runtime.h>
#include <cuda_fp16.h>
#include <cstdint>
#include <cstddef>

#define HW 4096
#define CIN 1088
#define CMID 136
#define CPAD 144

// ---------------- scratch (device globals; zero-initialized, no allocs) ----------------
__device__ float  g_feat[2][2][(size_t)CMID * HW];        // [a/b][n][c*HW+p]
__device__ float  g_E[2][(size_t)HW * HW];                // energy (already *100)
__device__ __half g_corr_h[2][2][(size_t)HW * HW];        // fp16 corr, [ab/ba][n], [k][l]
__device__ __half g_raw_h[2][2][(size_t)CIN * HW];        // [a/b][n]
__device__ __half g_fh[2][2][2][(size_t)CPAD * HW];       // [a/b][hi/lo][n], [c][p]
__device__ float  g_rowM[2][HW], g_rowSinv[2][HW];
__device__ float  g_colM[2][HW], g_colSinv[2][HW];
__device__ float  g_colPm[2][128][HW];                    // per-32-row-block col partial max
__device__ float  g_colPs[2][128][HW];                    // per-block col partial sum

// ---------------- PTX helpers ----------------
__device__ __forceinline__ uint32_t smaddr(const void* p) {
    return (uint32_t)__cvta_generic_to_shared(p);
}
__device__ __forceinline__ void ldsm4(uint32_t r[4], const void* p) {
    asm volatile("ldmatrix.sync.aligned.m8n8.x4.shared.b16 {%0,%1,%2,%3}, [%4];\n"
                 : "=r"(r[0]), "=r"(r[1]), "=r"(r[2]), "=r"(r[3]) : "r"(smaddr(p)));
}
__device__ __forceinline__ void ldsm4t(uint32_t r[4], const void* p) {
    asm volatile("ldmatrix.sync.aligned.m8n8.x4.trans.shared.b16 {%0,%1,%2,%3}, [%4];\n"
                 : "=r"(r[0]), "=r"(r[1]), "=r"(r[2]), "=r"(r[3]) : "r"(smaddr(p)));
}
__device__ __forceinline__ void mma16816(float* d, const uint32_t* a, const uint32_t* b) {
    asm volatile("mma.sync.aligned.m16n8k16.row.col.f32.f16.f16.f32 "
                 "{%0,%1,%2,%3}, {%4,%5,%6,%7}, {%8,%9}, {%0,%1,%2,%3};\n"
                 : "+f"(d[0]), "+f"(d[1]), "+f"(d[2]), "+f"(d[3])
                 : "r"(a[0]), "r"(a[1]), "r"(a[2]), "r"(a[3]), "r"(b[0]), "r"(b[1]));
}
__device__ __forceinline__ void cpa16u(uint32_t sm, const void* g, int bytes) {
    asm volatile("cp.async.cg.shared.global [%0], [%1], 16, %2;\n"
                 :: "r"(sm), "l"(g), "r"(bytes));
}
#define CP_COMMIT() asm volatile("cp.async.commit_group;\n" ::: "memory")
#define CP_WAIT(n)  asm volatile("cp.async.wait_group %0;\n" :: "n"(n) : "memory")

// ---------------- K1: 1x1 conv via split-fp16 HMMA ----------------
// Y[136,4096] = W[136,1088]@X[1088,4096] + b; in-kernel fp32->hi/lo split.
// Block tile 48(M) x 256(N), 8 warps (warp tile 48x32), K-chunk 32, 3 passes/chunk.
__global__ __launch_bounds__(256, 1) void conv_mma_kernel(
    const float* __restrict__ fa, const float* __restrict__ fb,
    const float* __restrict__ Wa, const float* __restrict__ ba,
    const float* __restrict__ Wb, const float* __restrict__ bb) {
    extern __shared__ __align__(16) char csm[];
    float*  Xf  = (float*)csm;                      // [32][256]
    float*  Wf  = Xf + 32 * 256;                    // [48][32]
    __half* Xhl = (__half*)(Wf + 48 * 32);          // [2 stage][2 hl][32][264]
    __half* Whl = Xhl + 2 * 2 * 32 * 264;           // [2 stage][2 hl][48][40]

    const int t = blockIdx.z >> 1, n = blockIdx.z & 1;
    const float* __restrict__ X = (t == 0 ? fa : fb) + (size_t)n * CIN * HW;
    const float* __restrict__ W = (t == 0 ? Wa : Wb);
    const float* __restrict__ bias = (t == 0 ? ba : bb);
    const int m0 = blockIdx.y * 48, n0 = blockIdx.x * 256;
    const int tid = threadIdx.x, lane = tid & 31, warp = tid >> 5;
    const int r16 = lane & 15, c8 = (lane >> 4) << 3;

    float acc[3][4][4];
#pragma unroll
    for (int i = 0; i < 3; ++i)
#pragma unroll
        for (int j = 0; j < 4; ++j)
#pragma unroll
            for (int k = 0; k < 4; ++k) acc[i][j][k] = 0.f;

    auto cpX = [&](int kc) {
#pragma unroll
        for (int i = 0; i < 8; ++i) {               // X: 32 rows x 1KB
            int idx = tid + i * 256;
            int row = idx >> 6, seg = (idx & 63) * 4;
            cpa16u(smaddr(&Xf[row * 256 + seg]), &X[(size_t)(kc + row) * HW + n0 + seg], 16);
        }
#pragma unroll
        for (int i = 0; i < 2; ++i) {               // W: 48 rows x 128B
            int idx = tid + i * 256;
            if (idx < 384) {
                int row = idx >> 3, seg = (idx & 7) * 4;
                int o = m0 + row;
                int ok = o < CMID;
                cpa16u(smaddr(&Wf[row * 32 + seg]), &W[(size_t)(ok ? o : 0) * CIN + kc + seg], ok ? 16 : 0);
            }
        }
    };
    auto convert = [&](int s) {
        __half* Xh = Xhl + s * (2 * 32 * 264);
        __half* Xl = Xh + 32 * 264;
#pragma unroll
        for (int i = 0; i < 32; ++i) {
            int idx = tid + i * 256;
            int row = idx >> 8, col = idx & 255;
            float v = Xf[row * 256 + col];
            __half h = __float2half_rn(v);
            Xh[row * 264 + col] = h;
            Xl[row * 264 + col] = __float2half_rn(v - __half2float(h));
        }
        __half* Wh = Whl + s * (2 * 48 * 40);
        __half* Wl = Wh + 48 * 40;
#pragma unroll
        for (int i = 0; i < 6; ++i) {
            int idx = tid + i * 256;
            if (idx < 1536) {
                int row = idx >> 5, col = idx & 31;
                float v = Wf[row * 32 + col];
                __half h = __float2half_rn(v);
                Wh[row * 40 + col] = h;
                Wl[row * 40 + col] = __float2half_rn(v - __half2float(h));
            }
        }
    };

    cpX(0); CP_COMMIT();
    for (int j = 0; j < 34; ++j) {
        const int s = j & 1;
        CP_WAIT(0);
        __syncthreads();
        convert(s);
        __syncthreads();
        if (j + 1 < 34) cpX((j + 1) * 32);
        CP_COMMIT();

        const __half* Xh = Xhl + s * (2 * 32 * 264);
        const __half* Xl = Xh + 32 * 264;
        const __half* Wh = Whl + s * (2 * 48 * 40);
        const __half* Wl = Wh + 48 * 40;
#pragma unroll
        for (int ks = 0; ks < 32; ks += 16) {
            uint32_t ah[3][4], al[3][4], bh[2][4], bl[2][4];
#pragma unroll
            for (int mi = 0; mi < 3; ++mi) {
                ldsm4(ah[mi], &Wh[(mi * 16 + r16) * 40 + ks + c8]);
                ldsm4(al[mi], &Wl[(mi * 16 + r16) * 40 + ks + c8]);
            }
#pragma unroll
            for (int nj = 0; nj < 2; ++nj) {
                ldsm4t(bh[nj], &Xh[(ks + r16) * 264 + warp * 32 + nj * 16 + c8]);
                ldsm4t(bl[nj], &Xl[(ks + r16) * 264 + warp * 32 + nj * 16 + c8]);
            }
#pragma unroll
            for (int mi = 0; mi < 3; ++mi)
#pragma unroll
                for (int nj = 0; nj < 2; ++nj) {
                    mma16816(acc[mi][nj * 2],     ah[mi], &bh[nj][0]);
                    mma16816(acc[mi][nj * 2 + 1], ah[mi], &bh[nj][2]);
                    mma16816(acc[mi][nj * 2],     ah[mi], &bl[nj][0]);
                    mma16816(acc[mi][nj * 2 + 1], ah[mi], &bl[nj][2]);
                    mma16816(acc[mi][nj * 2],     al[mi], &bh[nj][0]);
                    mma16816(acc[mi][nj * 2 + 1], al[mi], &bh[nj][2]);
                }
        }
        __syncthreads();
    }

    float* __restrict__ Y = g_feat[t][n];
#pragma unroll
    for (int mi = 0; mi < 3; ++mi)
#pragma unroll
        for (int g = 0; g < 4; ++g) {
            int r0 = m0 + mi * 16 + (lane >> 2);
            int col = n0 + warp * 32 + (g >> 1) * 16 + (g & 1) * 8 + (lane & 3) * 2;
            if (r0 < CMID) {
                float bv = bias[r0];
                *(float2*)&Y[(size_t)r0 * HW + col] =
                    make_float2(acc[mi][g][0] + bv, acc[mi][g][1] + bv);
            }
            if (r0 + 8 < CMID) {
                float bv = bias[r0 + 8];
                *(float2*)&Y[(size_t)(r0 + 8) * HW + col] =
                    make_float2(acc[mi][g][2] + bv, acc[mi][g][3] + bv);
            }
        }
}

// ---------------- K2: InstanceNorm + LeakyReLU + mean-center ----------------
__global__ void inorm_kernel() {
    const int c = blockIdx.x, n = blockIdx.y, t = blockIdx.z;
    float* __restrict__ Y = &g_feat[t][n][(size_t)c * HW];
    __shared__ float sd[HW];
    __shared__ float r1[256], r2[256];
    const int tid = threadIdx.x;

    float s = 0.f, q = 0.f;
    for (int i = tid; i < HW; i += 256) { float v = Y[i]; sd[i] = v; s += v; q += v * v; }
    r1[tid] = s; r2[tid] = q; __syncthreads();
    for (int st = 128; st > 0; st >>= 1) {
        if (tid < st) { r1[tid] += r1[tid + st]; r2[tid] += r2[tid + st]; }
        __syncthreads();
    }
    const float mean = r1[0] * (1.f / HW);
    const float var  = r2[0] * (1.f / HW) - mean * mean;
    const float inv  = rsqrtf(var + 1e-5f);
    __syncthreads();

    float s2 = 0.f;
    for (int i = tid; i < HW; i += 256) {
        float v = (sd[i] - mean) * inv;
        v = (v >= 0.f) ? v : 0.2f * v;
        sd[i] = v; s2 += v;
    }
    r1[tid] = s2; __syncthreads();
    for (int st = 128; st > 0; st >>= 1) {
        if (tid < st) r1[tid] += r1[tid + st];
        __syncthreads();
    }
    const float mean2 = r1[0] * (1.f / HW);
    for (int i = tid; i < HW; i += 256) Y[i] = sd[i] - mean2;
}

// ---------------- K3: L2-normalize + split hi/lo (coalesced [c][p]) ----------------
__global__ void l2norm_kernel() {
    const int p = blockIdx.x * 256 + threadIdx.x;
    const int n = blockIdx.y, t = blockIdx.z;
    const float* __restrict__ F = g_feat[t][n];
    float q = 0.f;
    for (int c = 0; c < CMID; ++c) { float v = F[(size_t)c * HW + p]; q += v * v; }
    const float inv = rsqrtf(q);
    __half* __restrict__ hi = g_fh[t][0][n];
    __half* __restrict__ lo = g_fh[t][1][n];
    for (int c = 0; c < CMID; ++c) {
        float v = F[(size_t)c * HW + p] * inv;
        __half h = __float2half_rn(v);
        hi[(size_t)c * HW + p] = h;
        lo[(size_t)c * HW + p] = __float2half_rn(v - __half2float(h));
    }
}

// ---------------- K4: energy via split-fp16 HMMA (unchanged from R4) ----------------
#define E_ST (48 * 136)
__global__ __launch_bounds__(512, 1) void energy_mma_kernel() {
    extern __shared__ __align__(16) __half eshm[];
    __half* As = eshm;
    __half* Bs = eshm + 2 * E_ST;

    const int n = blockIdx.z;
    const int m0 = blockIdx.y * 128, l0 = blockIdx.x * 128;
    const int tid = threadIdx.x, lane = tid & 31, warp = tid >> 5;
    const int wm = warp & 3, wn = warp >> 2;
    const int r16 = lane & 15, c8 = (lane >> 4) << 3;
    const int arow = (lane & 7) + ((lane >> 4) & 1) * 8;
    const int acol = ((lane >> 3) & 1) * 8;

    const __half* Ap[3] = { g_fh[1][0][n], g_fh[1][0][n], g_fh[1][1][n] };
    const __half* Bp[3] = { g_fh[0][0][n], g_fh[0][1][n], g_fh[0][0][n] };

    float acc[2][4][4];
#pragma unroll
    for (int i = 0; i < 2; ++i)
#pragma unroll
        for (int j = 0; j < 4; ++j)
#pragma unroll
            for (int k = 0; k < 4; ++k) acc[i][j][k] = 0.f;

    const uint32_t su = smaddr(eshm);
    auto loadst = [&](int s, int q) {
        const int pass = q / 3, kc = (q % 3) * 48;
        const __half* __restrict__ A = Ap[pass];
        const __half* __restrict__ B = Bp[pass];
#pragma unroll
        for (int i = 0; i < 3; ++i) {
            int idx = tid + i * 512;
            if (idx < 768) {
                int row = idx >> 4, cp = (idx & 15) * 8;
                cpa16u(su + (s * E_ST + row * 136 + cp) * 2,
                       &A[(size_t)(kc + row) * HW + m0 + cp], 16);
            } else {
                int ix = idx - 768;
                int row = ix >> 4, cp = (ix & 15) * 8;
                cpa16u(su + (2 * E_ST + s * E_ST + row * 136 + cp) * 2,
                       &B[(size_t)(kc + row) * HW + l0 + cp], 16);
            }
        }
    };

    loadst(0, 0); CP_COMMIT();
    for (int q = 0; q < 9; ++q) {
        const int s = q & 1;
        if (q + 1 < 9) { loadst(s ^ 1, q + 1); CP_COMMIT(); CP_WAIT(1); }
        else CP_WAIT(0);
        __syncthreads();
#pragma unroll
        for (int ks = 0; ks < 48; ks += 16) {
            uint32_t a[2][4], b[2][4];
#pragma unroll
            for (int mi = 0; mi < 2; ++mi)
                ldsm4t(a[mi], As + s * E_ST + (ks + arow) * 136 + wm * 32 + mi * 16 + acol);
#pragma unroll
            for (int nj = 0; nj < 2; ++nj)
                ldsm4t(b[nj], Bs + s * E_ST + (ks + r16) * 136 + wn * 32 + nj * 16 + c8);
#pragma unroll
            for (int mi = 0; mi < 2; ++mi)
#pragma unroll
                for (int nj = 0; nj < 2; ++nj) {
                    mma16816(acc[mi][nj * 2],     a[mi], &b[nj][0]);
                    mma16816(acc[mi][nj * 2 + 1], a[mi], &b[nj][2]);
                }
        }
        __syncthreads();
    }

    float* __restrict__ E = g_E[n];
#pragma unroll
    for (int mi = 0; mi < 2; ++mi)
#pragma unroll
        for (int j = 0; j < 4; ++j) {
            int row = m0 + wm * 32 + mi * 16 + (lane >> 2);
            int col = l0 + wn * 32 + j * 8 + (lane & 3) * 2;
            *(float2*)&E[(size_t)row * HW + col] =
                make_float2(acc[mi][j][0] * 100.f, acc[mi][j][1] * 100.f);
            *(float2*)&E[(size_t)(row + 8) * HW + col] =
                make_float2(acc[mi][j][2] * 100.f, acc[mi][j][3] * 100.f);
        }
}

// ---------------- K5: fused row+col stats (single E pass) ----------------
// 32 rows per block; row stats final, col stats partial -> combine kernel.
__global__ __launch_bounds__(256, 2) void rowcol_kernel() {
    const int rb = blockIdx.x, n = blockIdx.y;
    const float* __restrict__ E = g_E[n];
    const int tid = threadIdx.x;
    float cm[16], cs[16];
#pragma unroll
    for (int q = 0; q < 16; ++q) { cm[q] = -1e30f; cs[q] = 0.f; }
    __shared__ float sm[8], ss[8];

    for (int r = 0; r < 32; ++r) {
        const float* __restrict__ e = &E[(size_t)(rb * 32 + r) * HW];
        float v[16];
        float m = -1e30f;
#pragma unroll
        for (int q = 0; q < 16; ++q) { v[q] = e[tid + q * 256]; m = fmaxf(m, v[q]); }
        float s = 0.f;
#pragma unroll
        for (int q = 0; q < 16; ++q) s += __expf(v[q] - m);
        // col online update
#pragma unroll
        for (int q = 0; q < 16; ++q) {
            float mn = fmaxf(cm[q], v[q]);
            cs[q] = cs[q] * __expf(cm[q] - mn) + __expf(v[q] - mn);
            cm[q] = mn;
        }
        // row reduce across 256 threads (online merge)
#pragma unroll
        for (int o = 16; o; o >>= 1) {
            float m2 = __shfl_xor_sync(0xFFFFFFFFu, m, o);
            float s2 = __shfl_xor_sync(0xFFFFFFFFu, s, o);
            float M = fmaxf(m, m2);
            s = s * __expf(m - M) + s2 * __expf(m2 - M);
            m = M;
        }
        if ((tid & 31) == 0) { sm[tid >> 5] = m; ss[tid >> 5] = s; }
        __syncthreads();
        if (tid == 0) {
            float M = sm[0], S = ss[0];
#pragma unroll
            for (int w = 1; w < 8; ++w) {
                float M2 = fmaxf(M, sm[w]);
                S = S * __expf(M - M2) + ss[w] * __expf(sm[w] - M2);
                M = M2;
            }
            g_rowM[n][rb * 32 + r] = M;
            g_rowSinv[n][rb * 32 + r] = 1.0f / S;
        }
        __syncthreads();
    }
#pragma unroll
    for (int q = 0; q < 16; ++q) {
        g_colPm[n][rb][tid + q * 256] = cm[q];
        g_colPs[n][rb][tid + q * 256] = cs[q];
    }
}

__global__ void colcombine_kernel() {
    const int c = blockIdx.x * 256 + threadIdx.x;
    const int n = blockIdx.y;
    float M = -1e30f, S = 0.f;
    for (int rb = 0; rb < 128; ++rb) {
        float m = g_colPm[n][rb][c], s = g_colPs[n][rb][c];
        float M2 = fmaxf(M, m);
        S = S * __expf(M - M2) + s * __expf(m - M2);
        M = M2;
    }
    g_colM[n][c] = M;
    g_colSinv[n][c] = 1.0f / S;
}

// ---------------- K6: softmax writeout (fp32 + fp16, one E pass) ----------------
__global__ void writeout_kernel(float* __restrict__ out_ab, float* __restrict__ out_ba) {
    const int c0 = blockIdx.x * 64, r0 = blockIdx.y * 64, n = blockIdx.z;
    const int tid = threadIdx.x;
    const int tx = tid & 63, ty = tid >> 6;
    const float* __restrict__ E = g_E[n];
    __half* __restrict__ Hab = g_corr_h[0][n];
    __half* __restrict__ Hba = g_corr_h[1][n];
    float* __restrict__ Oab = out_ab + (size_t)n * HW * HW;
    float* __restrict__ Oba = out_ba + (size_t)n * HW * HW;

    __shared__ float t_ba[64][65];
    __shared__ float rm_s[64], rsi_s[64];
    if (tid < 64)       rm_s[tid]       = g_rowM[n][r0 + tid];
    else if (tid < 128) rsi_s[tid - 64] = g_rowSinv[n][r0 + tid - 64];
    const float cm  = g_colM[n][c0 + tx];
    const float csi = g_colSinv[n][c0 + tx];
    __syncthreads();

#pragma unroll 4
    for (int it = 0; it < 16; ++it) {
        int r_in = it * 4 + ty;
        int R = r0 + r_in, C = c0 + tx;
        float e = E[(size_t)R * HW + C];
        float pr = __expf(e - rm_s[r_in]) * rsi_s[r_in];
        float pc = __expf(e - cm) * csi;
        size_t off = (size_t)R * HW + C;
        Oab[off] = pr;
        Hab[off] = __float2half_rn(pr);
        t_ba[tx][r_in] = pc;
    }
    __syncthreads();
#pragma unroll 4
    for (int it = 0; it < 16; ++it) {
        int c_in = it * 4 + ty;
        float p = t_ba[c_in][tx];
        size_t off = (size_t)(c0 + c_in) * HW + r0 + tx;
        Oba[off] = p;
        Hba[off] = __float2half_rn(p);
    }
}

// ---------------- K7: raw -> fp16 ----------------
__global__ void tohalf_kernel(const float* __restrict__ a_raw, const float* __restrict__ b_raw) {
    const int t = blockIdx.y;
    const float* __restrict__ src = (t == 0 ? a_raw : b_raw);
    __half* __restrict__ dst = &g_raw_h[t][0][0];
    size_t i = ((size_t)blockIdx.x * 256 + threadIdx.x) * 4;
    float4 v = *(const float4*)&src[i];
    __half2* d2 = (__half2*)&dst[i];
    d2[0] = __floats2half2_rn(v.x, v.y);
    d2[1] = __floats2half2_rn(v.z, v.w);
}

// ---------------- K8: warp matmul  C[1088,4096] = raw @ corr (unchanged from R4) ----------------
#define G_AS (128 * 40)
#define G_BS (32 * 264)
#define G_NK 128
__global__ __launch_bounds__(512, 1) void wgemm_kernel(float* __restrict__ out) {
    extern __shared__ __align__(16) __half gshm[];
    __half* As = gshm;
    __half* Bs = gshm + 3 * G_AS;
    const uint32_t su = smaddr(gshm);

    const int z = blockIdx.z;
    const int dir = z >> 1, n = z & 1;
    const __half* __restrict__ A = g_raw_h[dir][n];
    const __half* __restrict__ B = g_corr_h[dir ^ 1][n];
    float* __restrict__ C = out + (size_t)4 * HW * HW
                                + (size_t)dir * 2 * CIN * HW + (size_t)n * CIN * HW;
    const int m0 = blockIdx.y * 128, n0 = blockIdx.x * 256;
    const int tid = threadIdx.x, lane = tid & 31, warp = tid >> 5;
    const int wm = warp & 3, wn = warp >> 2;
    const int r16 = lane & 15, c8 = (lane >> 4) << 3;

    float acc[2][8][4];
#pragma unroll
    for (int i = 0; i < 2; ++i)
#pragma unroll
        for (int j = 0; j < 8; ++j)
#pragma unroll
            for (int k = 0; k < 4; ++k) acc[i][j][k] = 0.f;

    auto loadst = [&](int s, int j) {
        const int k0 = j * 32;
#pragma unroll
        for (int i = 0; i < 3; ++i) {
            int idx = tid + i * 512;
            if (idx < 512) {
                int row = idx >> 2, cp = (idx & 3) * 8;
                int gr = m0 + row;
                int ok = gr < CIN;
                cpa16u(su + (s * G_AS + row * 40 + cp) * 2,
                       &A[(size_t)(ok ? gr : 0) * HW + k0 + cp], ok ? 16 : 0);
            } else {
                int ix = idx - 512;
                int row = ix >> 5, cp = (ix & 31) * 8;
                cpa16u(su + (3 * G_AS + s * G_BS + row * 264 + cp) * 2,
                       &B[(size_t)(k0 + row) * HW + n0 + cp], 16);
            }
        }
    };

    loadst(0, 0); CP_COMMIT();
    loadst(1, 1); CP_COMMIT();

    for (int j = 0; j < G_NK; ++j) {
        const int s = j % 3;
        if (j + 2 < G_NK) { loadst((j + 2) % 3, j + 2); CP_COMMIT(); CP_WAIT(2); }
        else if (j + 1 < G_NK) CP_WAIT(1);
        else CP_WAIT(0);
        __syncthreads();
#pragma unroll
        for (int ks = 0; ks < 32; ks += 16) {
            uint32_t a[2][4], b[4][4];
#pragma unroll
            for (int mi = 0; mi < 2; ++mi)
                ldsm4(a[mi], As + s * G_AS + (wm * 32 + mi * 16 + r16) * 40 + ks + c8);
#pragma unroll
            for (int nj = 0; nj < 4; ++nj)
                ldsm4t(b[nj], Bs + s * G_BS + (ks + r16) * 264 + wn * 64 + nj * 16 + c8);
#pragma unroll
            for (int mi = 0; mi < 2; ++mi)
#pragma unroll
                for (int nj = 0; nj < 4; ++nj) {
                    mma16816(acc[mi][nj * 2],     a[mi], &b[nj][0]);
                    mma16816(acc[mi][nj * 2 + 1], a[mi], &b[nj][2]);
                }
        }
        __syncthreads();
    }

#pragma unroll
    for (int mi = 0; mi < 2; ++mi)
#pragma unroll
        for (int nj = 0; nj < 8; ++nj) {
            int row = m0 + wm * 32 + mi * 16 + (lane >> 2);
            int col = n0 + wn * 64 + nj * 8 + (lane & 3) * 2;
            if (row < CIN)
                *(float2*)&C[(size_t)row * HW + col] = make_float2(acc[mi][nj][0], acc[mi][nj][1]);
            if (row + 8 < CIN)
                *(float2*)&C[(size_t)(row + 8) * HW + col] = make_float2(acc[mi][nj][2], acc[mi][nj][3]);
        }
}

// ---------------- launch ----------------
extern "C" void kernel_launch(void* const* d_in, const int* in_sizes, int n_in,
                              void* d_out, int out_size) {
    const float* fa    = (const float*)d_in[0];
    const float* fb    = (const float*)d_in[1];
    const float* a_raw = (const float*)d_in[2];
    const float* b_raw = (const float*)d_in[3];
    const float* Wa    = (const float*)d_in[4];
    const float* ba    = (const float*)d_in[5];
    const float* Wb    = (const float*)d_in[6];
    const float* bb    = (const float*)d_in[7];
    float* out = (float*)d_out;

    const int c_smem = 32 * 256 * 4 + 48 * 32 * 4 + 2 * 2 * 32 * 264 * 2 + 2 * 2 * 48 * 40 * 2; // 121856
    const int e_smem = 4 * E_ST * 2;                     // 52224
    const int g_smem = (3 * G_AS + 3 * G_BS) * 2;        // 81408
    cudaFuncSetAttribute(conv_mma_kernel, cudaFuncAttributeMaxDynamicSharedMemorySize, c_smem);
    cudaFuncSetAttribute(energy_mma_kernel, cudaFuncAttributeMaxDynamicSharedMemorySize, e_smem);
    cudaFuncSetAttribute(wgemm_kernel, cudaFuncAttributeMaxDynamicSharedMemorySize, g_smem);

    conv_mma_kernel<<<dim3(16, 3, 4), 256, c_smem>>>(fa, fb, Wa, ba, Wb, bb);
    inorm_kernel<<<dim3(CMID, 2, 2), 256>>>();
    l2norm_kernel<<<dim3(HW / 256, 2, 2), 256>>>();
    energy_mma_kernel<<<dim3(32, 32, 2), 512, e_smem>>>();
    tohalf_kernel<<<dim3(8704, 2), 256>>>(a_raw, b_raw);
    rowcol_kernel<<<dim3(128, 2), 256>>>();
    colcombine_kernel<<<dim3(HW / 256, 2), 256>>>();
    writeout_kernel<<<dim3(64, 64, 2), 256>>>(out, out + (size_t)2 * HW * HW);
    wgemm_kernel<<<dim3(16, 9, 4), 512, g_smem>>>(out);
}

// round 7
// speedup vs baseline: 1.5583x; 1.0704x over previous
#include <cuda_runtime.h>
#include <cuda_fp16.h>
#include <cstdint>
#include <cstddef>

#define HW 4096
#define CIN 1088
#define CMID 136
#define CPAD 144

// ---------------- scratch (device globals; zero-initialized, no allocs) ----------------
__device__ float  g_feat[2][2][(size_t)CMID * HW];        // [a/b][n][c*HW+p]
__device__ float  g_E[2][(size_t)HW * HW];                // energy (already *100)
__device__ __half g_corr_h[2][2][(size_t)HW * HW];        // fp16 corr, [ab/ba][n], [k][l]
__device__ __half g_raw_h[2][2][(size_t)CIN * HW];        // [a/b][n]
__device__ __half g_fh[2][2][2][(size_t)CPAD * HW];       // [a/b][hi/lo][n], [c][p]
__device__ float  g_rowM[2][HW], g_rowSinv[2][HW];
__device__ float  g_colM[2][HW], g_colSinv[2][HW];
__device__ float  g_colPm[2][128][HW];
__device__ float  g_colPs[2][128][HW];

// ---------------- PTX helpers ----------------
__device__ __forceinline__ uint32_t smaddr(const void* p) {
    return (uint32_t)__cvta_generic_to_shared(p);
}
__device__ __forceinline__ void ldsm4(uint32_t r[4], const void* p) {
    asm volatile("ldmatrix.sync.aligned.m8n8.x4.shared.b16 {%0,%1,%2,%3}, [%4];\n"
                 : "=r"(r[0]), "=r"(r[1]), "=r"(r[2]), "=r"(r[3]) : "r"(smaddr(p)));
}
__device__ __forceinline__ void ldsm4t(uint32_t r[4], const void* p) {
    asm volatile("ldmatrix.sync.aligned.m8n8.x4.trans.shared.b16 {%0,%1,%2,%3}, [%4];\n"
                 : "=r"(r[0]), "=r"(r[1]), "=r"(r[2]), "=r"(r[3]) : "r"(smaddr(p)));
}
__device__ __forceinline__ void mma16816(float* d, const uint32_t* a, const uint32_t* b) {
    asm volatile("mma.sync.aligned.m16n8k16.row.col.f32.f16.f16.f32 "
                 "{%0,%1,%2,%3}, {%4,%5,%6,%7}, {%8,%9}, {%0,%1,%2,%3};\n"
                 : "+f"(d[0]), "+f"(d[1]), "+f"(d[2]), "+f"(d[3])
                 : "r"(a[0]), "r"(a[1]), "r"(a[2]), "r"(a[3]), "r"(b[0]), "r"(b[1]));
}
__device__ __forceinline__ void cpa16u(uint32_t sm, const void* g, int bytes) {
    asm volatile("cp.async.cg.shared.global [%0], [%1], 16, %2;\n"
                 :: "r"(sm), "l"(g), "r"(bytes));
}
#define CP_COMMIT() asm volatile("cp.async.commit_group;\n" ::: "memory")
#define CP_WAIT(n)  asm volatile("cp.async.wait_group %0;\n" :: "n"(n) : "memory")

// ---------------- K1: 1x1 conv via split-fp16 HMMA (unchanged from R5) ----------------
__global__ __launch_bounds__(256, 1) void conv_mma_kernel(
    const float* __restrict__ fa, const float* __restrict__ fb,
    const float* __restrict__ Wa, const float* __restrict__ ba,
    const float* __restrict__ Wb, const float* __restrict__ bb) {
    extern __shared__ __align__(16) char csm[];
    float*  Xf  = (float*)csm;
    float*  Wf  = Xf + 32 * 256;
    __half* Xhl = (__half*)(Wf + 48 * 32);
    __half* Whl = Xhl + 2 * 2 * 32 * 264;

    const int t = blockIdx.z >> 1, n = blockIdx.z & 1;
    const float* __restrict__ X = (t == 0 ? fa : fb) + (size_t)n * CIN * HW;
    const float* __restrict__ W = (t == 0 ? Wa : Wb);
    const float* __restrict__ bias = (t == 0 ? ba : bb);
    const int m0 = blockIdx.y * 48, n0 = blockIdx.x * 256;
    const int tid = threadIdx.x, lane = tid & 31, warp = tid >> 5;
    const int r16 = lane & 15, c8 = (lane >> 4) << 3;

    float acc[3][4][4];
#pragma unroll
    for (int i = 0; i < 3; ++i)
#pragma unroll
        for (int j = 0; j < 4; ++j)
#pragma unroll
            for (int k = 0; k < 4; ++k) acc[i][j][k] = 0.f;

    auto cpX = [&](int kc) {
#pragma unroll
        for (int i = 0; i < 8; ++i) {
            int idx = tid + i * 256;
            int row = idx >> 6, seg = (idx & 63) * 4;
            cpa16u(smaddr(&Xf[row * 256 + seg]), &X[(size_t)(kc + row) * HW + n0 + seg], 16);
        }
#pragma unroll
        for (int i = 0; i < 2; ++i) {
            int idx = tid + i * 256;
            if (idx < 384) {
                int row = idx >> 3, seg = (idx & 7) * 4;
                int o = m0 + row;
                int ok = o < CMID;
                cpa16u(smaddr(&Wf[row * 32 + seg]), &W[(size_t)(ok ? o : 0) * CIN + kc + seg], ok ? 16 : 0);
            }
        }
    };
    auto convert = [&](int s) {
        __half* Xh = Xhl + s * (2 * 32 * 264);
        __half* Xl = Xh + 32 * 264;
#pragma unroll
        for (int i = 0; i < 32; ++i) {
            int idx = tid + i * 256;
            int row = idx >> 8, col = idx & 255;
            float v = Xf[row * 256 + col];
            __half h = __float2half_rn(v);
            Xh[row * 264 + col] = h;
            Xl[row * 264 + col] = __float2half_rn(v - __half2float(h));
        }
        __half* Wh = Whl + s * (2 * 48 * 40);
        __half* Wl = Wh + 48 * 40;
#pragma unroll
        for (int i = 0; i < 6; ++i) {
            int idx = tid + i * 256;
            if (idx < 1536) {
                int row = idx >> 5, col = idx & 31;
                float v = Wf[row * 32 + col];
                __half h = __float2half_rn(v);
                Wh[row * 40 + col] = h;
                Wl[row * 40 + col] = __float2half_rn(v - __half2float(h));
            }
        }
    };

    cpX(0); CP_COMMIT();
    for (int j = 0; j < 34; ++j) {
        const int s = j & 1;
        CP_WAIT(0);
        __syncthreads();
        convert(s);
        __syncthreads();
        if (j + 1 < 34) cpX((j + 1) * 32);
        CP_COMMIT();

        const __half* Xh = Xhl + s * (2 * 32 * 264);
        const __half* Xl = Xh + 32 * 264;
        const __half* Wh = Whl + s * (2 * 48 * 40);
        const __half* Wl = Wh + 48 * 40;
#pragma unroll
        for (int ks = 0; ks < 32; ks += 16) {
            uint32_t ah[3][4], al[3][4], bh[2][4], bl[2][4];
#pragma unroll
            for (int mi = 0; mi < 3; ++mi) {
                ldsm4(ah[mi], &Wh[(mi * 16 + r16) * 40 + ks + c8]);
                ldsm4(al[mi], &Wl[(mi * 16 + r16) * 40 + ks + c8]);
            }
#pragma unroll
            for (int nj = 0; nj < 2; ++nj) {
                ldsm4t(bh[nj], &Xh[(ks + r16) * 264 + warp * 32 + nj * 16 + c8]);
                ldsm4t(bl[nj], &Xl[(ks + r16) * 264 + warp * 32 + nj * 16 + c8]);
            }
#pragma unroll
            for (int mi = 0; mi < 3; ++mi)
#pragma unroll
                for (int nj = 0; nj < 2; ++nj) {
                    mma16816(acc[mi][nj * 2],     ah[mi], &bh[nj][0]);
                    mma16816(acc[mi][nj * 2 + 1], ah[mi], &bh[nj][2]);
                    mma16816(acc[mi][nj * 2],     ah[mi], &bl[nj][0]);
                    mma16816(acc[mi][nj * 2 + 1], ah[mi], &bl[nj][2]);
                    mma16816(acc[mi][nj * 2],     al[mi], &bh[nj][0]);
                    mma16816(acc[mi][nj * 2 + 1], al[mi], &bh[nj][2]);
                }
        }
        __syncthreads();
    }

    float* __restrict__ Y = g_feat[t][n];
#pragma unroll
    for (int mi = 0; mi < 3; ++mi)
#pragma unroll
        for (int g = 0; g < 4; ++g) {
            int r0 = m0 + mi * 16 + (lane >> 2);
            int col = n0 + warp * 32 + (g >> 1) * 16 + (g & 1) * 8 + (lane & 3) * 2;
            if (r0 < CMID) {
                float bv = bias[r0];
                *(float2*)&Y[(size_t)r0 * HW + col] =
                    make_float2(acc[mi][g][0] + bv, acc[mi][g][1] + bv);
            }
            if (r0 + 8 < CMID) {
                float bv = bias[r0 + 8];
                *(float2*)&Y[(size_t)(r0 + 8) * HW + col] =
                    make_float2(acc[mi][g][2] + bv, acc[mi][g][3] + bv);
            }
        }
}

// ---------------- K2: InstanceNorm + LeakyReLU + mean-center ----------------
__global__ void inorm_kernel() {
    const int c = blockIdx.x, n = blockIdx.y, t = blockIdx.z;
    float* __restrict__ Y = &g_feat[t][n][(size_t)c * HW];
    __shared__ float sd[HW];
    __shared__ float r1[256], r2[256];
    const int tid = threadIdx.x;

    float s = 0.f, q = 0.f;
    for (int i = tid; i < HW; i += 256) { float v = Y[i]; sd[i] = v; s += v; q += v * v; }
    r1[tid] = s; r2[tid] = q; __syncthreads();
    for (int st = 128; st > 0; st >>= 1) {
        if (tid < st) { r1[tid] += r1[tid + st]; r2[tid] += r2[tid + st]; }
        __syncthreads();
    }
    const float mean = r1[0] * (1.f / HW);
    const float var  = r2[0] * (1.f / HW) - mean * mean;
    const float inv  = rsqrtf(var + 1e-5f);
    __syncthreads();

    float s2 = 0.f;
    for (int i = tid; i < HW; i += 256) {
        float v = (sd[i] - mean) * inv;
        v = (v >= 0.f) ? v : 0.2f * v;
        sd[i] = v; s2 += v;
    }
    r1[tid] = s2; __syncthreads();
    for (int st = 128; st > 0; st >>= 1) {
        if (tid < st) r1[tid] += r1[tid + st];
        __syncthreads();
    }
    const float mean2 = r1[0] * (1.f / HW);
    for (int i = tid; i < HW; i += 256) Y[i] = sd[i] - mean2;
}

// ---------------- K3: L2-normalize + split hi/lo ----------------
__global__ void l2norm_kernel() {
    const int p = blockIdx.x * 256 + threadIdx.x;
    const int n = blockIdx.y, t = blockIdx.z;
    const float* __restrict__ F = g_feat[t][n];
    float q = 0.f;
    for (int c = 0; c < CMID; ++c) { float v = F[(size_t)c * HW + p]; q += v * v; }
    const float inv = rsqrtf(q);
    __half* __restrict__ hi = g_fh[t][0][n];
    __half* __restrict__ lo = g_fh[t][1][n];
    for (int c = 0; c < CMID; ++c) {
        float v = F[(size_t)c * HW + p] * inv;
        __half h = __float2half_rn(v);
        hi[(size_t)c * HW + p] = h;
        lo[(size_t)c * HW + p] = __float2half_rn(v - __half2float(h));
    }
}

// ---------------- K4: energy via split-fp16 HMMA ----------------
// block 128(m) x 256(l), 16 warps (4x4), warp 32x64, 3-stage, frag-pipelined.
#define E_AST (48 * 136)
#define E_BST (48 * 264)
__global__ __launch_bounds__(512, 1) void energy_mma_kernel() {
    extern __shared__ __align__(16) __half eshm[];
    __half* As = eshm;                         // [3][48][136]
    __half* Bs = eshm + 3 * E_AST;             // [3][48][264]

    const int n = blockIdx.z;
    const int m0 = blockIdx.y * 128, l0 = blockIdx.x * 256;
    const int tid = threadIdx.x, lane = tid & 31, warp = tid >> 5;
    const int wm = warp & 3, wn = warp >> 2;
    const int r16 = lane & 15, c8 = (lane >> 4) << 3;
    const int arow = (lane & 7) + ((lane >> 4) & 1) * 8;
    const int acol = ((lane >> 3) & 1) * 8;

    const __half* Ap[3] = { g_fh[1][0][n], g_fh[1][0][n], g_fh[1][1][n] };
    const __half* Bp[3] = { g_fh[0][0][n], g_fh[0][1][n], g_fh[0][0][n] };

    float acc[2][8][4];
#pragma unroll
    for (int i = 0; i < 2; ++i)
#pragma unroll
        for (int j = 0; j < 8; ++j)
#pragma unroll
            for (int k = 0; k < 4; ++k) acc[i][j][k] = 0.f;

    const uint32_t su = smaddr(eshm);
    auto loadst = [&](int st, int q) {
        const int pass = q / 3, kc = (q % 3) * 48;
        const __half* __restrict__ A = Ap[pass];
        const __half* __restrict__ B = Bp[pass];
#pragma unroll
        for (int i = 0; i < 5; ++i) {
            int idx = tid + i * 512;
            if (idx < 768) {
                int row = idx >> 4, cp = (idx & 15) * 8;
                cpa16u(su + (st * E_AST + row * 136 + cp) * 2,
                       &A[(size_t)(kc + row) * HW + m0 + cp], 16);
            } else if (idx < 2304) {
                int ix = idx - 768;
                int row = ix >> 5, cp = (ix & 31) * 8;
                cpa16u(su + (3 * E_AST + st * E_BST + row * 264 + cp) * 2,
                       &B[(size_t)(kc + row) * HW + l0 + cp], 16);
            }
        }
    };

    auto ldfrag = [&](int st, int ks, uint32_t a[2][4], uint32_t b[4][4]) {
#pragma unroll
        for (int mi = 0; mi < 2; ++mi)
            ldsm4t(a[mi], As + st * E_AST + (ks + arow) * 136 + wm * 32 + mi * 16 + acol);
#pragma unroll
        for (int nj = 0; nj < 4; ++nj)
            ldsm4t(b[nj], Bs + st * E_BST + (ks + r16) * 264 + wn * 64 + nj * 16 + c8);
    };
    auto mmag = [&](uint32_t a[2][4], uint32_t b[4][4]) {
#pragma unroll
        for (int mi = 0; mi < 2; ++mi)
#pragma unroll
            for (int nj = 0; nj < 4; ++nj) {
                mma16816(acc[mi][nj * 2],     a[mi], &b[nj][0]);
                mma16816(acc[mi][nj * 2 + 1], a[mi], &b[nj][2]);
            }
    };

    loadst(0, 0); CP_COMMIT();
    loadst(1, 1); CP_COMMIT();
    for (int q = 0; q < 9; ++q) {
        const int st = q % 3;
        CP_WAIT(1);
        __syncthreads();
        if (q + 2 < 9) loadst((q + 2) % 3, q + 2);
        CP_COMMIT();

        uint32_t a[2][2][4], b[2][4][4];
        ldfrag(st, 0, a[0], b[0]);
        ldfrag(st, 16, a[1], b[1]);
        mmag(a[0], b[0]);
        ldfrag(st, 32, a[0], b[0]);
        mmag(a[1], b[1]);
        mmag(a[0], b[0]);
        __syncthreads();
    }

    float* __restrict__ E = g_E[n];
#pragma unroll
    for (int mi = 0; mi < 2; ++mi)
#pragma unroll
        for (int nj = 0; nj < 8; ++nj) {
            int row = m0 + wm * 32 + mi * 16 + (lane >> 2);
            int col = l0 + wn * 64 + nj * 8 + (lane & 3) * 2;
            *(float2*)&E[(size_t)row * HW + col] =
                make_float2(acc[mi][nj][0] * 100.f, acc[mi][nj][1] * 100.f);
            *(float2*)&E[(size_t)(row + 8) * HW + col] =
                make_float2(acc[mi][nj][2] * 100.f, acc[mi][nj][3] * 100.f);
        }
}

// ---------------- K5: fused row+col stats (single E pass) ----------------
__global__ __launch_bounds__(256, 2) void rowcol_kernel() {
    const int rb = blockIdx.x, n = blockIdx.y;
    const float* __restrict__ E = g_E[n];
    const int tid = threadIdx.x;
    float cm[16], cs[16];
#pragma unroll
    for (int q = 0; q < 16; ++q) { cm[q] = -1e30f; cs[q] = 0.f; }
    __shared__ float sm[8], ss[8];

    for (int r = 0; r < 32; ++r) {
        const float* __restrict__ e = &E[(size_t)(rb * 32 + r) * HW];
        float v[16];
        float m = -1e30f;
#pragma unroll
        for (int q = 0; q < 16; ++q) { v[q] = e[tid + q * 256]; m = fmaxf(m, v[q]); }
        float s = 0.f;
#pragma unroll
        for (int q = 0; q < 16; ++q) s += __expf(v[q] - m);
#pragma unroll
        for (int q = 0; q < 16; ++q) {
            float mn = fmaxf(cm[q], v[q]);
            cs[q] = cs[q] * __expf(cm[q] - mn) + __expf(v[q] - mn);
            cm[q] = mn;
        }
#pragma unroll
        for (int o = 16; o; o >>= 1) {
            float m2 = __shfl_xor_sync(0xFFFFFFFFu, m, o);
            float s2 = __shfl_xor_sync(0xFFFFFFFFu, s, o);
            float M = fmaxf(m, m2);
            s = s * __expf(m - M) + s2 * __expf(m2 - M);
            m = M;
        }
        if ((tid & 31) == 0) { sm[tid >> 5] = m; ss[tid >> 5] = s; }
        __syncthreads();
        if (tid == 0) {
            float M = sm[0], S = ss[0];
#pragma unroll
            for (int w = 1; w < 8; ++w) {
                float M2 = fmaxf(M, sm[w]);
                S = S * __expf(M - M2) + ss[w] * __expf(sm[w] - M2);
                M = M2;
            }
            g_rowM[n][rb * 32 + r] = M;
            g_rowSinv[n][rb * 32 + r] = 1.0f / S;
        }
        __syncthreads();
    }
#pragma unroll
    for (int q = 0; q < 16; ++q) {
        g_colPm[n][rb][tid + q * 256] = cm[q];
        g_colPs[n][rb][tid + q * 256] = cs[q];
    }
}

__global__ void colcombine_kernel() {
    const int c = blockIdx.x * 256 + threadIdx.x;
    const int n = blockIdx.y;
    float M = -1e30f, S = 0.f;
    for (int rb = 0; rb < 128; ++rb) {
        float m = g_colPm[n][rb][c], s = g_colPs[n][rb][c];
        float M2 = fmaxf(M, m);
        S = S * __expf(M - M2) + s * __expf(m - M2);
        M = M2;
    }
    g_colM[n][c] = M;
    g_colSinv[n][c] = 1.0f / S;
}

// ---------------- K6: softmax writeout ----------------
__global__ void writeout_kernel(float* __restrict__ out_ab, float* __restrict__ out_ba) {
    const int c0 = blockIdx.x * 64, r0 = blockIdx.y * 64, n = blockIdx.z;
    const int tid = threadIdx.x;
    const int tx = tid & 63, ty = tid >> 6;
    const float* __restrict__ E = g_E[n];
    __half* __restrict__ Hab = g_corr_h[0][n];
    __half* __restrict__ Hba = g_corr_h[1][n];
    float* __restrict__ Oab = out_ab + (size_t)n * HW * HW;
    float* __restrict__ Oba = out_ba + (size_t)n * HW * HW;

    __shared__ float t_ba[64][65];
    __shared__ float rm_s[64], rsi_s[64];
    if (tid < 64)       rm_s[tid]       = g_rowM[n][r0 + tid];
    else if (tid < 128) rsi_s[tid - 64] = g_rowSinv[n][r0 + tid - 64];
    const float cm  = g_colM[n][c0 + tx];
    const float csi = g_colSinv[n][c0 + tx];
    __syncthreads();

#pragma unroll 4
    for (int it = 0; it < 16; ++it) {
        int r_in = it * 4 + ty;
        int R = r0 + r_in, C = c0 + tx;
        float e = E[(size_t)R * HW + C];
        float pr = __expf(e - rm_s[r_in]) * rsi_s[r_in];
        float pc = __expf(e - cm) * csi;
        size_t off = (size_t)R * HW + C;
        Oab[off] = pr;
        Hab[off] = __float2half_rn(pr);
        t_ba[tx][r_in] = pc;
    }
    __syncthreads();
#pragma unroll 4
    for (int it = 0; it < 16; ++it) {
        int c_in = it * 4 + ty;
        float p = t_ba[c_in][tx];
        size_t off = (size_t)(c0 + c_in) * HW + r0 + tx;
        Oba[off] = p;
        Hba[off] = __float2half_rn(p);
    }
}

// ---------------- K7: raw -> fp16 ----------------
__global__ void tohalf_kernel(const float* __restrict__ a_raw, const float* __restrict__ b_raw) {
    const int t = blockIdx.y;
    const float* __restrict__ src = (t == 0 ? a_raw : b_raw);
    __half* __restrict__ dst = &g_raw_h[t][0][0];
    size_t i = ((size_t)blockIdx.x * 256 + threadIdx.x) * 4;
    float4 v = *(const float4*)&src[i];
    __half2* d2 = (__half2*)&dst[i];
    d2[0] = __floats2half2_rn(v.x, v.y);
    d2[1] = __floats2half2_rn(v.z, v.w);
}

// ---------------- K8: warp matmul  C[1088,4096] = raw @ corr ----------------
// 512 thr, 16 warps (4x4), block 128x256, warp 32x64, K-chunk 64, 3 stages, frag-pipelined.
#define G_AST (128 * 72)
#define G_BST (64 * 264)
#define G_NC 64
__global__ __launch_bounds__(512, 1) void wgemm_kernel(float* __restrict__ out) {
    extern __shared__ __align__(16) __half gshm[];
    __half* As = gshm;                        // [3][128][72]
    __half* Bs = gshm + 3 * G_AST;            // [3][64][264]
    const uint32_t su = smaddr(gshm);

    const int z = blockIdx.z;
    const int dir = z >> 1, n = z & 1;
    const __half* __restrict__ A = g_raw_h[dir][n];
    const __half* __restrict__ B = g_corr_h[dir ^ 1][n];
    float* __restrict__ C = out + (size_t)4 * HW * HW
                                + (size_t)dir * 2 * CIN * HW + (size_t)n * CIN * HW;
    const int m0 = blockIdx.y * 128, n0 = blockIdx.x * 256;
    const int tid = threadIdx.x, lane = tid & 31, warp = tid >> 5;
    const int wm = warp & 3, wn = warp >> 2;
    const int r16 = lane & 15, c8 = (lane >> 4) << 3;

    float acc[2][8][4];
#pragma unroll
    for (int i = 0; i < 2; ++i)
#pragma unroll
        for (int j = 0; j < 8; ++j)
#pragma unroll
            for (int k = 0; k < 4; ++k) acc[i][j][k] = 0.f;

    auto loadst = [&](int st, int j) {
        const int k0 = j * 64;
#pragma unroll
        for (int i = 0; i < 6; ++i) {
            int idx = tid + i * 512;
            if (idx < 1024) {
                int row = idx >> 3, cp = (idx & 7) * 8;
                int gr = m0 + row;
                int ok = gr < CIN;
                cpa16u(su + (st * G_AST + row * 72 + cp) * 2,
                       &A[(size_t)(ok ? gr : 0) * HW + k0 + cp], ok ? 16 : 0);
            } else {
                int ix = idx - 1024;
                int row = ix >> 5, cp = (ix & 31) * 8;
                cpa16u(su + (3 * G_AST + st * G_BST + row * 264 + cp) * 2,
                       &B[(size_t)(k0 + row) * HW + n0 + cp], 16);
            }
        }
    };

    auto ldfrag = [&](int st, int ks, uint32_t a[2][4], uint32_t b[4][4]) {
#pragma unroll
        for (int mi = 0; mi < 2; ++mi)
            ldsm4(a[mi], As + st * G_AST + (wm * 32 + mi * 16 + r16) * 72 + ks + c8);
#pragma unroll
        for (int nj = 0; nj < 4; ++nj)
            ldsm4t(b[nj], Bs + st * G_BST + (ks + r16) * 264 + wn * 64 + nj * 16 + c8);
    };
    auto mmag = [&](uint32_t a[2][4], uint32_t b[4][4]) {
#pragma unroll
        for (int mi = 0; mi < 2; ++mi)
#pragma unroll
            for (int nj = 0; nj < 4; ++nj) {
                mma16816(acc[mi][nj * 2],     a[mi], &b[nj][0]);
                mma16816(acc[mi][nj * 2 + 1], a[mi], &b[nj][2]);
            }
    };

    loadst(0, 0); CP_COMMIT();
    loadst(1, 1); CP_COMMIT();

    for (int j = 0; j < G_NC; ++j) {
        const int st = j % 3;
        CP_WAIT(1);
        __syncthreads();
        if (j + 2 < G_NC) loadst((j + 2) % 3, j + 2);
        CP_COMMIT();

        uint32_t a[2][2][4], b[2][4][4];
        ldfrag(st, 0, a[0], b[0]);
        ldfrag(st, 16, a[1], b[1]);
        mmag(a[0], b[0]);
        ldfrag(st, 32, a[0], b[0]);
        mmag(a[1], b[1]);
        ldfrag(st, 48, a[1], b[1]);
        mmag(a[0], b[0]);
        mmag(a[1], b[1]);
        __syncthreads();
    }

#pragma unroll
    for (int mi = 0; mi < 2; ++mi)
#pragma unroll
        for (int nj = 0; nj < 8; ++nj) {
            int row = m0 + wm * 32 + mi * 16 + (lane >> 2);
            int col = n0 + wn * 64 + nj * 8 + (lane & 3) * 2;
            if (row < CIN)
                *(float2*)&C[(size_t)row * HW + col] = make_float2(acc[mi][nj][0], acc[mi][nj][1]);
            if (row + 8 < CIN)
                *(float2*)&C[(size_t)(row + 8) * HW + col] = make_float2(acc[mi][nj][2], acc[mi][nj][3]);
        }
}

// ---------------- launch ----------------
extern "C" void kernel_launch(void* const* d_in, const int* in_sizes, int n_in,
                              void* d_out, int out_size) {
    const float* fa    = (const float*)d_in[0];
    const float* fb    = (const float*)d_in[1];
    const float* a_raw = (const float*)d_in[2];
    const float* b_raw = (const float*)d_in[3];
    const float* Wa    = (const float*)d_in[4];
    const float* ba    = (const float*)d_in[5];
    const float* Wb    = (const float*)d_in[6];
    const float* bb    = (const float*)d_in[7];
    float* out = (float*)d_out;

    const int c_smem = 32 * 256 * 4 + 48 * 32 * 4 + 2 * 2 * 32 * 264 * 2 + 2 * 2 * 48 * 40 * 2; // 121856
    const int e_smem = 3 * (E_AST + E_BST) * 2;          // 115200
    const int g_smem = 3 * (G_AST + G_BST) * 2;          // 156672
    cudaFuncSetAttribute(conv_mma_kernel, cudaFuncAttributeMaxDynamicSharedMemorySize, c_smem);
    cudaFuncSetAttribute(energy_mma_kernel, cudaFuncAttributeMaxDynamicSharedMemorySize, e_smem);
    cudaFuncSetAttribute(wgemm_kernel, cudaFuncAttributeMaxDynamicSharedMemorySize, g_smem);

    conv_mma_kernel<<<dim3(16, 3, 4), 256, c_smem>>>(fa, fb, Wa, ba, Wb, bb);
    inorm_kernel<<<dim3(CMID, 2, 2), 256>>>();
    l2norm_kernel<<<dim3(HW / 256, 2, 2), 256>>>();
    energy_mma_kernel<<<dim3(16, 32, 2), 512, e_smem>>>();
    tohalf_kernel<<<dim3(8704, 2), 256>>>(a_raw, b_raw);
    rowcol_kernel<<<dim3(128, 2), 256>>>();
    colcombine_kernel<<<dim3(HW / 256, 2), 256>>>();
    writeout_kernel<<<dim3(64, 64, 2), 256>>>(out, out + (size_t)2 * HW * HW);
    wgemm_kernel<<<dim3(16, 9, 4), 512, g_smem>>>(out);
}

// round 8
// speedup vs baseline: 1.6937x; 1.0869x over previous
#include <cuda_runtime.h>
#include <cuda_fp16.h>
#include <cstdint>
#include <cstddef>

#define HW 4096
#define CIN 1088
#define CMID 136
#define CPAD 144

// ---------------- scratch (device globals; zero-initialized, no allocs) ----------------
__device__ float  g_feat[2][2][(size_t)CMID * HW];        // [a/b][n][c*HW+p]
__device__ float  g_E[2][(size_t)HW * HW];                // energy (already *100)
__device__ __half g_corr_h[2][2][(size_t)HW * HW];        // fp16 corr, [ab/ba][n], [k][l]
__device__ __half g_raw_h[2][2][(size_t)CIN * HW];        // [a/b][n]
__device__ __half g_fh[2][2][2][(size_t)CPAD * HW];       // [a/b][hi/lo][n], [c][p]
__device__ float  g_rowM[2][HW], g_rowSinv[2][HW];
__device__ float  g_colM[2][HW], g_colSinv[2][HW];
__device__ float  g_colPm[2][128][HW];
__device__ float  g_colPs[2][128][HW];

// ---------------- PTX helpers ----------------
__device__ __forceinline__ uint32_t smaddr(const void* p) {
    return (uint32_t)__cvta_generic_to_shared(p);
}
__device__ __forceinline__ void ldsm4(uint32_t r[4], const void* p) {
    asm volatile("ldmatrix.sync.aligned.m8n8.x4.shared.b16 {%0,%1,%2,%3}, [%4];\n"
                 : "=r"(r[0]), "=r"(r[1]), "=r"(r[2]), "=r"(r[3]) : "r"(smaddr(p)));
}
__device__ __forceinline__ void ldsm4t(uint32_t r[4], const void* p) {
    asm volatile("ldmatrix.sync.aligned.m8n8.x4.trans.shared.b16 {%0,%1,%2,%3}, [%4];\n"
                 : "=r"(r[0]), "=r"(r[1]), "=r"(r[2]), "=r"(r[3]) : "r"(smaddr(p)));
}
__device__ __forceinline__ void mma16816(float* d, const uint32_t* a, const uint32_t* b) {
    asm volatile("mma.sync.aligned.m16n8k16.row.col.f32.f16.f16.f32 "
                 "{%0,%1,%2,%3}, {%4,%5,%6,%7}, {%8,%9}, {%0,%1,%2,%3};\n"
                 : "+f"(d[0]), "+f"(d[1]), "+f"(d[2]), "+f"(d[3])
                 : "r"(a[0]), "r"(a[1]), "r"(a[2]), "r"(a[3]), "r"(b[0]), "r"(b[1]));
}
__device__ __forceinline__ void cpa16u(uint32_t sm, const void* g, int bytes) {
    asm volatile("cp.async.cg.shared.global [%0], [%1], 16, %2;\n"
                 :: "r"(sm), "l"(g), "r"(bytes));
}
#define CP_COMMIT() asm volatile("cp.async.commit_group;\n" ::: "memory")
#define CP_WAIT(n)  asm volatile("cp.async.wait_group %0;\n" :: "n"(n) : "memory")

// ---------------- K1: 1x1 conv via split-fp16 HMMA ----------------
__global__ __launch_bounds__(256, 1) void conv_mma_kernel(
    const float* __restrict__ fa, const float* __restrict__ fb,
    const float* __restrict__ Wa, const float* __restrict__ ba,
    const float* __restrict__ Wb, const float* __restrict__ bb) {
    extern __shared__ __align__(16) char csm[];
    float*  Xf  = (float*)csm;
    float*  Wf  = Xf + 32 * 256;
    __half* Xhl = (__half*)(Wf + 48 * 32);
    __half* Whl = Xhl + 2 * 2 * 32 * 264;

    const int t = blockIdx.z >> 1, n = blockIdx.z & 1;
    const float* __restrict__ X = (t == 0 ? fa : fb) + (size_t)n * CIN * HW;
    const float* __restrict__ W = (t == 0 ? Wa : Wb);
    const float* __restrict__ bias = (t == 0 ? ba : bb);
    const int m0 = blockIdx.y * 48, n0 = blockIdx.x * 256;
    const int tid = threadIdx.x, lane = tid & 31, warp = tid >> 5;
    const int r16 = lane & 15, c8 = (lane >> 4) << 3;

    float acc[3][4][4];
#pragma unroll
    for (int i = 0; i < 3; ++i)
#pragma unroll
        for (int j = 0; j < 4; ++j)
#pragma unroll
            for (int k = 0; k < 4; ++k) acc[i][j][k] = 0.f;

    auto cpX = [&](int kc) {
#pragma unroll
        for (int i = 0; i < 8; ++i) {
            int idx = tid + i * 256;
            int row = idx >> 6, seg = (idx & 63) * 4;
            cpa16u(smaddr(&Xf[row * 256 + seg]), &X[(size_t)(kc + row) * HW + n0 + seg], 16);
        }
#pragma unroll
        for (int i = 0; i < 2; ++i) {
            int idx = tid + i * 256;
            if (idx < 384) {
                int row = idx >> 3, seg = (idx & 7) * 4;
                int o = m0 + row;
                int ok = o < CMID;
                cpa16u(smaddr(&Wf[row * 32 + seg]), &W[(size_t)(ok ? o : 0) * CIN + kc + seg], ok ? 16 : 0);
            }
        }
    };
    auto convert = [&](int s) {
        __half* Xh = Xhl + s * (2 * 32 * 264);
        __half* Xl = Xh + 32 * 264;
#pragma unroll
        for (int i = 0; i < 32; ++i) {
            int idx = tid + i * 256;
            int row = idx >> 8, col = idx & 255;
            float v = Xf[row * 256 + col];
            __half h = __float2half_rn(v);
            Xh[row * 264 + col] = h;
            Xl[row * 264 + col] = __float2half_rn(v - __half2float(h));
        }
        __half* Wh = Whl + s * (2 * 48 * 40);
        __half* Wl = Wh + 48 * 40;
#pragma unroll
        for (int i = 0; i < 6; ++i) {
            int idx = tid + i * 256;
            if (idx < 1536) {
                int row = idx >> 5, col = idx & 31;
                float v = Wf[row * 32 + col];
                __half h = __float2half_rn(v);
                Wh[row * 40 + col] = h;
                Wl[row * 40 + col] = __float2half_rn(v - __half2float(h));
            }
        }
    };

    cpX(0); CP_COMMIT();
    for (int j = 0; j < 34; ++j) {
        const int s = j & 1;
        CP_WAIT(0);
        __syncthreads();
        convert(s);
        __syncthreads();
        if (j + 1 < 34) cpX((j + 1) * 32);
        CP_COMMIT();

        const __half* Xh = Xhl + s * (2 * 32 * 264);
        const __half* Xl = Xh + 32 * 264;
        const __half* Wh = Whl + s * (2 * 48 * 40);
        const __half* Wl = Wh + 48 * 40;
#pragma unroll
        for (int ks = 0; ks < 32; ks += 16) {
            uint32_t ah[3][4], al[3][4], bh[2][4], bl[2][4];
#pragma unroll
            for (int mi = 0; mi < 3; ++mi) {
                ldsm4(ah[mi], &Wh[(mi * 16 + r16) * 40 + ks + c8]);
                ldsm4(al[mi], &Wl[(mi * 16 + r16) * 40 + ks + c8]);
            }
#pragma unroll
            for (int nj = 0; nj < 2; ++nj) {
                ldsm4t(bh[nj], &Xh[(ks + r16) * 264 + warp * 32 + nj * 16 + c8]);
                ldsm4t(bl[nj], &Xl[(ks + r16) * 264 + warp * 32 + nj * 16 + c8]);
            }
#pragma unroll
            for (int mi = 0; mi < 3; ++mi)
#pragma unroll
                for (int nj = 0; nj < 2; ++nj) {
                    mma16816(acc[mi][nj * 2],     ah[mi], &bh[nj][0]);
                    mma16816(acc[mi][nj * 2 + 1], ah[mi], &bh[nj][2]);
                    mma16816(acc[mi][nj * 2],     ah[mi], &bl[nj][0]);
                    mma16816(acc[mi][nj * 2 + 1], ah[mi], &bl[nj][2]);
                    mma16816(acc[mi][nj * 2],     al[mi], &bh[nj][0]);
                    mma16816(acc[mi][nj * 2 + 1], al[mi], &bh[nj][2]);
                }
        }
        __syncthreads();
    }

    float* __restrict__ Y = g_feat[t][n];
#pragma unroll
    for (int mi = 0; mi < 3; ++mi)
#pragma unroll
        for (int g = 0; g < 4; ++g) {
            int r0 = m0 + mi * 16 + (lane >> 2);
            int col = n0 + warp * 32 + (g >> 1) * 16 + (g & 1) * 8 + (lane & 3) * 2;
            if (r0 < CMID) {
                float bv = bias[r0];
                *(float2*)&Y[(size_t)r0 * HW + col] =
                    make_float2(acc[mi][g][0] + bv, acc[mi][g][1] + bv);
            }
            if (r0 + 8 < CMID) {
                float bv = bias[r0 + 8];
                *(float2*)&Y[(size_t)(r0 + 8) * HW + col] =
                    make_float2(acc[mi][g][2] + bv, acc[mi][g][3] + bv);
            }
        }
}

// ---------------- K2: InstanceNorm + LeakyReLU + mean-center ----------------
__global__ void inorm_kernel() {
    const int c = blockIdx.x, n = blockIdx.y, t = blockIdx.z;
    float* __restrict__ Y = &g_feat[t][n][(size_t)c * HW];
    __shared__ float sd[HW];
    __shared__ float r1[256], r2[256];
    const int tid = threadIdx.x;

    float s = 0.f, q = 0.f;
    for (int i = tid; i < HW; i += 256) { float v = Y[i]; sd[i] = v; s += v; q += v * v; }
    r1[tid] = s; r2[tid] = q; __syncthreads();
    for (int st = 128; st > 0; st >>= 1) {
        if (tid < st) { r1[tid] += r1[tid + st]; r2[tid] += r2[tid + st]; }
        __syncthreads();
    }
    const float mean = r1[0] * (1.f / HW);
    const float var  = r2[0] * (1.f / HW) - mean * mean;
    const float inv  = rsqrtf(var + 1e-5f);
    __syncthreads();

    float s2 = 0.f;
    for (int i = tid; i < HW; i += 256) {
        float v = (sd[i] - mean) * inv;
        v = (v >= 0.f) ? v : 0.2f * v;
        sd[i] = v; s2 += v;
    }
    r1[tid] = s2; __syncthreads();
    for (int st = 128; st > 0; st >>= 1) {
        if (tid < st) r1[tid] += r1[tid + st];
        __syncthreads();
    }
    const float mean2 = r1[0] * (1.f / HW);
    for (int i = tid; i < HW; i += 256) Y[i] = sd[i] - mean2;
}

// ---------------- K3: L2-normalize + split hi/lo ----------------
__global__ void l2norm_kernel() {
    const int p = blockIdx.x * 256 + threadIdx.x;
    const int n = blockIdx.y, t = blockIdx.z;
    const float* __restrict__ F = g_feat[t][n];
    float q = 0.f;
    for (int c = 0; c < CMID; ++c) { float v = F[(size_t)c * HW + p]; q += v * v; }
    const float inv = rsqrtf(q);
    __half* __restrict__ hi = g_fh[t][0][n];
    __half* __restrict__ lo = g_fh[t][1][n];
    for (int c = 0; c < CMID; ++c) {
        float v = F[(size_t)c * HW + p] * inv;
        __half h = __float2half_rn(v);
        hi[(size_t)c * HW + p] = h;
        lo[(size_t)c * HW + p] = __float2half_rn(v - __half2float(h));
    }
}

// ---------------- K4: energy via split-fp16 HMMA (single-frag, no spills) ----------------
#define E_AST (48 * 136)
#define E_BST (48 * 264)
__global__ __launch_bounds__(512, 1) void energy_mma_kernel() {
    extern __shared__ __align__(16) __half eshm[];
    __half* As = eshm;                         // [3][48][136]
    __half* Bs = eshm + 3 * E_AST;             // [3][48][264]

    const int n = blockIdx.z;
    const int m0 = blockIdx.y * 128, l0 = blockIdx.x * 256;
    const int tid = threadIdx.x, lane = tid & 31, warp = tid >> 5;
    const int wm = warp & 3, wn = warp >> 2;
    const int r16 = lane & 15, c8 = (lane >> 4) << 3;
    const int arow = (lane & 7) + ((lane >> 4) & 1) * 8;
    const int acol = ((lane >> 3) & 1) * 8;

    const __half* Ap[3] = { g_fh[1][0][n], g_fh[1][0][n], g_fh[1][1][n] };
    const __half* Bp[3] = { g_fh[0][0][n], g_fh[0][1][n], g_fh[0][0][n] };

    float acc[2][8][4];
#pragma unroll
    for (int i = 0; i < 2; ++i)
#pragma unroll
        for (int j = 0; j < 8; ++j)
#pragma unroll
            for (int k = 0; k < 4; ++k) acc[i][j][k] = 0.f;

    const uint32_t su = smaddr(eshm);
    auto loadst = [&](int st, int q) {
        const int pass = q / 3, kc = (q % 3) * 48;
        const __half* __restrict__ A = Ap[pass];
        const __half* __restrict__ B = Bp[pass];
#pragma unroll
        for (int i = 0; i < 5; ++i) {
            int idx = tid + i * 512;
            if (idx < 768) {
                int row = idx >> 4, cp = (idx & 15) * 8;
                cpa16u(su + (st * E_AST + row * 136 + cp) * 2,
                       &A[(size_t)(kc + row) * HW + m0 + cp], 16);
            } else if (idx < 2304) {
                int ix = idx - 768;
                int row = ix >> 5, cp = (ix & 31) * 8;
                cpa16u(su + (3 * E_AST + st * E_BST + row * 264 + cp) * 2,
                       &B[(size_t)(kc + row) * HW + l0 + cp], 16);
            }
        }
    };

    loadst(0, 0); CP_COMMIT();
    loadst(1, 1); CP_COMMIT();
    for (int q = 0; q < 9; ++q) {
        const int st = q % 3;
        CP_WAIT(1);
        __syncthreads();
        if (q + 2 < 9) loadst((q + 2) % 3, q + 2);
        CP_COMMIT();

#pragma unroll
        for (int ks = 0; ks < 48; ks += 16) {
            uint32_t a[2][4], b[4][4];
#pragma unroll
            for (int mi = 0; mi < 2; ++mi)
                ldsm4t(a[mi], As + st * E_AST + (ks + arow) * 136 + wm * 32 + mi * 16 + acol);
#pragma unroll
            for (int nj = 0; nj < 4; ++nj)
                ldsm4t(b[nj], Bs + st * E_BST + (ks + r16) * 264 + wn * 64 + nj * 16 + c8);
#pragma unroll
            for (int mi = 0; mi < 2; ++mi)
#pragma unroll
                for (int nj = 0; nj < 4; ++nj) {
                    mma16816(acc[mi][nj * 2],     a[mi], &b[nj][0]);
                    mma16816(acc[mi][nj * 2 + 1], a[mi], &b[nj][2]);
                }
        }
        __syncthreads();
    }

    float* __restrict__ E = g_E[n];
#pragma unroll
    for (int mi = 0; mi < 2; ++mi)
#pragma unroll
        for (int nj = 0; nj < 8; ++nj) {
            int row = m0 + wm * 32 + mi * 16 + (lane >> 2);
            int col = l0 + wn * 64 + nj * 8 + (lane & 3) * 2;
            *(float2*)&E[(size_t)row * HW + col] =
                make_float2(acc[mi][nj][0] * 100.f, acc[mi][nj][1] * 100.f);
            *(float2*)&E[(size_t)(row + 8) * HW + col] =
                make_float2(acc[mi][nj][2] * 100.f, acc[mi][nj][3] * 100.f);
        }
}

// ---------------- K5: fused row+col stats, float4 loads ----------------
__global__ __launch_bounds__(256, 2) void rowcol_kernel() {
    const int rb = blockIdx.x, n = blockIdx.y;
    const float* __restrict__ E = g_E[n];
    const int tid = threadIdx.x;
    float cm[4][4], cs[4][4];
#pragma unroll
    for (int q = 0; q < 4; ++q)
#pragma unroll
        for (int j = 0; j < 4; ++j) { cm[q][j] = -1e30f; cs[q][j] = 0.f; }
    __shared__ float sm[8], ss[8];

    for (int r = 0; r < 32; ++r) {
        const float* __restrict__ e = &E[(size_t)(rb * 32 + r) * HW];
        float4 v[4];
        float m = -1e30f;
#pragma unroll
        for (int q = 0; q < 4; ++q) {
            v[q] = *(const float4*)&e[tid * 4 + q * 1024];
            m = fmaxf(m, fmaxf(fmaxf(v[q].x, v[q].y), fmaxf(v[q].z, v[q].w)));
        }
        float s = 0.f;
#pragma unroll
        for (int q = 0; q < 4; ++q) {
            s += __expf(v[q].x - m) + __expf(v[q].y - m)
               + __expf(v[q].z - m) + __expf(v[q].w - m);
        }
#pragma unroll
        for (int q = 0; q < 4; ++q) {
            float vv[4] = { v[q].x, v[q].y, v[q].z, v[q].w };
#pragma unroll
            for (int j = 0; j < 4; ++j) {
                float mn = fmaxf(cm[q][j], vv[j]);
                cs[q][j] = cs[q][j] * __expf(cm[q][j] - mn) + __expf(vv[j] - mn);
                cm[q][j] = mn;
            }
        }
#pragma unroll
        for (int o = 16; o; o >>= 1) {
            float m2 = __shfl_xor_sync(0xFFFFFFFFu, m, o);
            float s2 = __shfl_xor_sync(0xFFFFFFFFu, s, o);
            float M = fmaxf(m, m2);
            s = s * __expf(m - M) + s2 * __expf(m2 - M);
            m = M;
        }
        if ((tid & 31) == 0) { sm[tid >> 5] = m; ss[tid >> 5] = s; }
        __syncthreads();
        if (tid == 0) {
            float M = sm[0], S = ss[0];
#pragma unroll
            for (int w = 1; w < 8; ++w) {
                float M2 = fmaxf(M, sm[w]);
                S = S * __expf(M - M2) + ss[w] * __expf(sm[w] - M2);
                M = M2;
            }
            g_rowM[n][rb * 32 + r] = M;
            g_rowSinv[n][rb * 32 + r] = 1.0f / S;
        }
        __syncthreads();
    }
#pragma unroll
    for (int q = 0; q < 4; ++q) {
        *(float4*)&g_colPm[n][rb][tid * 4 + q * 1024] = make_float4(cm[q][0], cm[q][1], cm[q][2], cm[q][3]);
        *(float4*)&g_colPs[n][rb][tid * 4 + q * 1024] = make_float4(cs[q][0], cs[q][1], cs[q][2], cs[q][3]);
    }
}

__global__ void colcombine_kernel() {
    const int c = blockIdx.x * 256 + threadIdx.x;
    const int n = blockIdx.y;
    float M = -1e30f, S = 0.f;
    for (int rb = 0; rb < 128; ++rb) {
        float m = g_colPm[n][rb][c], s = g_colPs[n][rb][c];
        float M2 = fmaxf(M, m);
        S = S * __expf(M - M2) + s * __expf(m - M2);
        M = M2;
    }
    g_colM[n][c] = M;
    g_colSinv[n][c] = 1.0f / S;
}

// ---------------- K6: softmax writeout, vectorized ----------------
// 64x64 tile; 256 thr = (tx 0..15 cols x4, ty 0..15 rows), 4 row-iters.
__global__ void writeout_kernel(float* __restrict__ out_ab, float* __restrict__ out_ba) {
    const int c0 = blockIdx.x * 64, r0 = blockIdx.y * 64, n = blockIdx.z;
    const int tid = threadIdx.x;
    const int tx = tid & 15, ty = tid >> 4;
    const float* __restrict__ E = g_E[n];
    __half* __restrict__ Hab = g_corr_h[0][n];
    __half* __restrict__ Hba = g_corr_h[1][n];
    float* __restrict__ Oab = out_ab + (size_t)n * HW * HW;
    float* __restrict__ Oba = out_ba + (size_t)n * HW * HW;

    __shared__ float t_ba[64][68];
    __shared__ float rm_s[64], rsi_s[64];
    if (tid < 64)       rm_s[tid]       = g_rowM[n][r0 + tid];
    else if (tid < 128) rsi_s[tid - 64] = g_rowSinv[n][r0 + tid - 64];
    const float4 cm4  = *(const float4*)&g_colM[n][c0 + tx * 4];
    const float4 csi4 = *(const float4*)&g_colSinv[n][c0 + tx * 4];
    __syncthreads();

#pragma unroll
    for (int it = 0; it < 4; ++it) {
        int r_in = it * 16 + ty;
        int R = r0 + r_in;
        float4 e = *(const float4*)&E[(size_t)R * HW + c0 + tx * 4];
        float rm = rm_s[r_in], rsi = rsi_s[r_in];
        float4 pr = make_float4(__expf(e.x - rm) * rsi, __expf(e.y - rm) * rsi,
                                __expf(e.z - rm) * rsi, __expf(e.w - rm) * rsi);
        float pc0 = __expf(e.x - cm4.x) * csi4.x;
        float pc1 = __expf(e.y - cm4.y) * csi4.y;
        float pc2 = __expf(e.z - cm4.z) * csi4.z;
        float pc3 = __expf(e.w - cm4.w) * csi4.w;
        size_t off = (size_t)R * HW + c0 + tx * 4;
        *(float4*)&Oab[off] = pr;
        __half2 h0 = __floats2half2_rn(pr.x, pr.y);
        __half2 h1 = __floats2half2_rn(pr.z, pr.w);
        *(uint2*)&Hab[off] = make_uint2(*(uint32_t*)&h0, *(uint32_t*)&h1);
        t_ba[tx * 4 + 0][r_in] = pc0;
        t_ba[tx * 4 + 1][r_in] = pc1;
        t_ba[tx * 4 + 2][r_in] = pc2;
        t_ba[tx * 4 + 3][r_in] = pc3;
    }
    __syncthreads();
#pragma unroll
    for (int it = 0; it < 4; ++it) {
        int c_in = it * 16 + ty;
        float4 p = *(const float4*)&t_ba[c_in][tx * 4];
        size_t off = (size_t)(c0 + c_in) * HW + r0 + tx * 4;
        *(float4*)&Oba[off] = p;
        __half2 h0 = __floats2half2_rn(p.x, p.y);
        __half2 h1 = __floats2half2_rn(p.z, p.w);
        *(uint2*)&Hba[off] = make_uint2(*(uint32_t*)&h0, *(uint32_t*)&h1);
    }
}

// ---------------- K7: raw -> fp16 ----------------
__global__ void tohalf_kernel(const float* __restrict__ a_raw, const float* __restrict__ b_raw) {
    const int t = blockIdx.y;
    const float* __restrict__ src = (t == 0 ? a_raw : b_raw);
    __half* __restrict__ dst = &g_raw_h[t][0][0];
    size_t i = ((size_t)blockIdx.x * 256 + threadIdx.x) * 4;
    float4 v = *(const float4*)&src[i];
    __half2* d2 = (__half2*)&dst[i];
    d2[0] = __floats2half2_rn(v.x, v.y);
    d2[1] = __floats2half2_rn(v.z, v.w);
}

// ---------------- K8: warp matmul (single-frag, no spills) ----------------
#define G_AST (128 * 72)
#define G_BST (64 * 264)
#define G_NC 64
__global__ __launch_bounds__(512, 1) void wgemm_kernel(float* __restrict__ out) {
    extern __shared__ __align__(16) __half gshm[];
    __half* As = gshm;                        // [3][128][72]
    __half* Bs = gshm + 3 * G_AST;            // [3][64][264]
    const uint32_t su = smaddr(gshm);

    const int z = blockIdx.z;
    const int dir = z >> 1, n = z & 1;
    const __half* __restrict__ A = g_raw_h[dir][n];
    const __half* __restrict__ B = g_corr_h[dir ^ 1][n];
    float* __restrict__ C = out + (size_t)4 * HW * HW
                                + (size_t)dir * 2 * CIN * HW + (size_t)n * CIN * HW;
    const int m0 = blockIdx.y * 128, n0 = blockIdx.x * 256;
    const int tid = threadIdx.x, lane = tid & 31, warp = tid >> 5;
    const int wm = warp & 3, wn = warp >> 2;
    const int r16 = lane & 15, c8 = (lane >> 4) << 3;

    float acc[2][8][4];
#pragma unroll
    for (int i = 0; i < 2; ++i)
#pragma unroll
        for (int j = 0; j < 8; ++j)
#pragma unroll
            for (int k = 0; k < 4; ++k) acc[i][j][k] = 0.f;

    auto loadst = [&](int st, int j) {
        const int k0 = j * 64;
#pragma unroll
        for (int i = 0; i < 6; ++i) {
            int idx = tid + i * 512;
            if (idx < 1024) {
                int row = idx >> 3, cp = (idx & 7) * 8;
                int gr = m0 + row;
                int ok = gr < CIN;
                cpa16u(su + (st * G_AST + row * 72 + cp) * 2,
                       &A[(size_t)(ok ? gr : 0) * HW + k0 + cp], ok ? 16 : 0);
            } else {
                int ix = idx - 1024;
                int row = ix >> 5, cp = (ix & 31) * 8;
                cpa16u(su + (3 * G_AST + st * G_BST + row * 264 + cp) * 2,
                       &B[(size_t)(k0 + row) * HW + n0 + cp], 16);
            }
        }
    };

    loadst(0, 0); CP_COMMIT();
    loadst(1, 1); CP_COMMIT();

    for (int j = 0; j < G_NC; ++j) {
        const int st = j % 3;
        CP_WAIT(1);
        __syncthreads();
        if (j + 2 < G_NC) loadst((j + 2) % 3, j + 2);
        CP_COMMIT();

#pragma unroll
        for (int ks = 0; ks < 64; ks += 16) {
            uint32_t a[2][4], b[4][4];
#pragma unroll
            for (int mi = 0; mi < 2; ++mi)
                ldsm4(a[mi], As + st * G_AST + (wm * 32 + mi * 16 + r16) * 72 + ks + c8);
#pragma unroll
            for (int nj = 0; nj < 4; ++nj)
                ldsm4t(b[nj], Bs + st * G_BST + (ks + r16) * 264 + wn * 64 + nj * 16 + c8);
#pragma unroll
            for (int mi = 0; mi < 2; ++mi)
#pragma unroll
                for (int nj = 0; nj < 4; ++nj) {
                    mma16816(acc[mi][nj * 2],     a[mi], &b[nj][0]);
                    mma16816(acc[mi][nj * 2 + 1], a[mi], &b[nj][2]);
                }
        }
        __syncthreads();
    }

#pragma unroll
    for (int mi = 0; mi < 2; ++mi)
#pragma unroll
        for (int nj = 0; nj < 8; ++nj) {
            int row = m0 + wm * 32 + mi * 16 + (lane >> 2);
            int col = n0 + wn * 64 + nj * 8 + (lane & 3) * 2;
            if (row < CIN)
                *(float2*)&C[(size_t)row * HW + col] = make_float2(acc[mi][nj][0], acc[mi][nj][1]);
            if (row + 8 < CIN)
                *(float2*)&C[(size_t)(row + 8) * HW + col] = make_float2(acc[mi][nj][2], acc[mi][nj][3]);
        }
}

// ---------------- launch ----------------
extern "C" void kernel_launch(void* const* d_in, const int* in_sizes, int n_in,
                              void* d_out, int out_size) {
    const float* fa    = (const float*)d_in[0];
    const float* fb    = (const float*)d_in[1];
    const float* a_raw = (const float*)d_in[2];
    const float* b_raw = (const float*)d_in[3];
    const float* Wa    = (const float*)d_in[4];
    const float* ba    = (const float*)d_in[5];
    const float* Wb    = (const float*)d_in[6];
    const float* bb    = (const float*)d_in[7];
    float* out = (float*)d_out;

    const int c_smem = 32 * 256 * 4 + 48 * 32 * 4 + 2 * 2 * 32 * 264 * 2 + 2 * 2 * 48 * 40 * 2; // 121856
    const int e_smem = 3 * (E_AST + E_BST) * 2;          // 115200
    const int g_smem = 3 * (G_AST + G_BST) * 2;          // 156672
    cudaFuncSetAttribute(conv_mma_kernel, cudaFuncAttributeMaxDynamicSharedMemorySize, c_smem);
    cudaFuncSetAttribute(energy_mma_kernel, cudaFuncAttributeMaxDynamicSharedMemorySize, e_smem);
    cudaFuncSetAttribute(wgemm_kernel, cudaFuncAttributeMaxDynamicSharedMemorySize, g_smem);

    conv_mma_kernel<<<dim3(16, 3, 4), 256, c_smem>>>(fa, fb, Wa, ba, Wb, bb);
    inorm_kernel<<<dim3(CMID, 2, 2), 256>>>();
    l2norm_kernel<<<dim3(HW / 256, 2, 2), 256>>>();
    energy_mma_kernel<<<dim3(16, 32, 2), 512, e_smem>>>();
    tohalf_kernel<<<dim3(8704, 2), 256>>>(a_raw, b_raw);
    rowcol_kernel<<<dim3(128, 2), 256>>>();
    colcombine_kernel<<<dim3(HW / 256, 2), 256>>>();
    writeout_kernel<<<dim3(64, 64, 2), 256>>>(out, out + (size_t)2 * HW * HW);
    wgemm_kernel<<<dim3(16, 9, 4), 512, g_smem>>>(out);
}

// round 9
// speedup vs baseline: 1.7563x; 1.0369x over previous
#include <cuda_runtime.h>
#include <cuda_fp16.h>
#include <cstdint>
#include <cstddef>

#define HW 4096
#define CIN 1088
#define CMID 136
#define CPAD 144

// ---------------- scratch (device globals; zero-initialized, no allocs) ----------------
__device__ float  g_feat[2][2][(size_t)CMID * HW];        // [a/b][n][c*HW+p]
__device__ float  g_E[2][(size_t)HW * HW];                // energy (already *100)
__device__ __half g_corr_h[2][2][(size_t)HW * HW];        // fp16 corr, [ab/ba][n], [k][l]
__device__ __half g_raw_h[2][2][(size_t)CIN * HW];        // [a/b][n]
__device__ __half g_fh[2][2][2][(size_t)CPAD * HW];       // [a/b][hi/lo][n], [c][p]
__device__ float  g_rowM[2][HW], g_rowSinv[2][HW];
__device__ float  g_colM[2][HW], g_colSinv[2][HW];
__device__ float  g_rowPm[2][16][HW],  g_rowPs[2][16][HW];   // per-l-block row partials
__device__ float  g_colPm[2][32][HW],  g_colPs[2][32][HW];   // per-m-block col partials

// ---------------- PTX helpers ----------------
__device__ __forceinline__ uint32_t smaddr(const void* p) {
    return (uint32_t)__cvta_generic_to_shared(p);
}
__device__ __forceinline__ void ldsm4(uint32_t r[4], const void* p) {
    asm volatile("ldmatrix.sync.aligned.m8n8.x4.shared.b16 {%0,%1,%2,%3}, [%4];\n"
                 : "=r"(r[0]), "=r"(r[1]), "=r"(r[2]), "=r"(r[3]) : "r"(smaddr(p)));
}
__device__ __forceinline__ void ldsm4t(uint32_t r[4], const void* p) {
    asm volatile("ldmatrix.sync.aligned.m8n8.x4.trans.shared.b16 {%0,%1,%2,%3}, [%4];\n"
                 : "=r"(r[0]), "=r"(r[1]), "=r"(r[2]), "=r"(r[3]) : "r"(smaddr(p)));
}
__device__ __forceinline__ void mma16816(float* d, const uint32_t* a, const uint32_t* b) {
    asm volatile("mma.sync.aligned.m16n8k16.row.col.f32.f16.f16.f32 "
                 "{%0,%1,%2,%3}, {%4,%5,%6,%7}, {%8,%9}, {%0,%1,%2,%3};\n"
                 : "+f"(d[0]), "+f"(d[1]), "+f"(d[2]), "+f"(d[3])
                 : "r"(a[0]), "r"(a[1]), "r"(a[2]), "r"(a[3]), "r"(b[0]), "r"(b[1]));
}
__device__ __forceinline__ void cpa16u(uint32_t sm, const void* g, int bytes) {
    asm volatile("cp.async.cg.shared.global [%0], [%1], 16, %2;\n"
                 :: "r"(sm), "l"(g), "r"(bytes));
}
#define CP_COMMIT() asm volatile("cp.async.commit_group;\n" ::: "memory")
#define CP_WAIT(n)  asm volatile("cp.async.wait_group %0;\n" :: "n"(n) : "memory")

// ---------------- K1: 1x1 conv via split-fp16 HMMA ----------------
__global__ __launch_bounds__(256, 1) void conv_mma_kernel(
    const float* __restrict__ fa, const float* __restrict__ fb,
    const float* __restrict__ Wa, const float* __restrict__ ba,
    const float* __restrict__ Wb, const float* __restrict__ bb) {
    extern __shared__ __align__(16) char csm[];
    float*  Xf  = (float*)csm;
    float*  Wf  = Xf + 32 * 256;
    __half* Xhl = (__half*)(Wf + 48 * 32);
    __half* Whl = Xhl + 2 * 2 * 32 * 264;

    const int t = blockIdx.z >> 1, n = blockIdx.z & 1;
    const float* __restrict__ X = (t == 0 ? fa : fb) + (size_t)n * CIN * HW;
    const float* __restrict__ W = (t == 0 ? Wa : Wb);
    const float* __restrict__ bias = (t == 0 ? ba : bb);
    const int m0 = blockIdx.y * 48, n0 = blockIdx.x * 256;
    const int tid = threadIdx.x, lane = tid & 31, warp = tid >> 5;
    const int r16 = lane & 15, c8 = (lane >> 4) << 3;

    float acc[3][4][4];
#pragma unroll
    for (int i = 0; i < 3; ++i)
#pragma unroll
        for (int j = 0; j < 4; ++j)
#pragma unroll
            for (int k = 0; k < 4; ++k) acc[i][j][k] = 0.f;

    auto cpX = [&](int kc) {
#pragma unroll
        for (int i = 0; i < 8; ++i) {
            int idx = tid + i * 256;
            int row = idx >> 6, seg = (idx & 63) * 4;
            cpa16u(smaddr(&Xf[row * 256 + seg]), &X[(size_t)(kc + row) * HW + n0 + seg], 16);
        }
#pragma unroll
        for (int i = 0; i < 2; ++i) {
            int idx = tid + i * 256;
            if (idx < 384) {
                int row = idx >> 3, seg = (idx & 7) * 4;
                int o = m0 + row;
                int ok = o < CMID;
                cpa16u(smaddr(&Wf[row * 32 + seg]), &W[(size_t)(ok ? o : 0) * CIN + kc + seg], ok ? 16 : 0);
            }
        }
    };
    auto convert = [&](int s) {
        __half* Xh = Xhl + s * (2 * 32 * 264);
        __half* Xl = Xh + 32 * 264;
#pragma unroll
        for (int i = 0; i < 32; ++i) {
            int idx = tid + i * 256;
            int row = idx >> 8, col = idx & 255;
            float v = Xf[row * 256 + col];
            __half h = __float2half_rn(v);
            Xh[row * 264 + col] = h;
            Xl[row * 264 + col] = __float2half_rn(v - __half2float(h));
        }
        __half* Wh = Whl + s * (2 * 48 * 40);
        __half* Wl = Wh + 48 * 40;
#pragma unroll
        for (int i = 0; i < 6; ++i) {
            int idx = tid + i * 256;
            if (idx < 1536) {
                int row = idx >> 5, col = idx & 31;
                float v = Wf[row * 32 + col];
                __half h = __float2half_rn(v);
                Wh[row * 40 + col] = h;
                Wl[row * 40 + col] = __float2half_rn(v - __half2float(h));
            }
        }
    };

    cpX(0); CP_COMMIT();
    for (int j = 0; j < 34; ++j) {
        const int s = j & 1;
        CP_WAIT(0);
        __syncthreads();
        convert(s);
        __syncthreads();
        if (j + 1 < 34) cpX((j + 1) * 32);
        CP_COMMIT();

        const __half* Xh = Xhl + s * (2 * 32 * 264);
        const __half* Xl = Xh + 32 * 264;
        const __half* Wh = Whl + s * (2 * 48 * 40);
        const __half* Wl = Wh + 48 * 40;
#pragma unroll
        for (int ks = 0; ks < 32; ks += 16) {
            uint32_t ah[3][4], al[3][4], bh[2][4], bl[2][4];
#pragma unroll
            for (int mi = 0; mi < 3; ++mi) {
                ldsm4(ah[mi], &Wh[(mi * 16 + r16) * 40 + ks + c8]);
                ldsm4(al[mi], &Wl[(mi * 16 + r16) * 40 + ks + c8]);
            }
#pragma unroll
            for (int nj = 0; nj < 2; ++nj) {
                ldsm4t(bh[nj], &Xh[(ks + r16) * 264 + warp * 32 + nj * 16 + c8]);
                ldsm4t(bl[nj], &Xl[(ks + r16) * 264 + warp * 32 + nj * 16 + c8]);
            }
#pragma unroll
            for (int mi = 0; mi < 3; ++mi)
#pragma unroll
                for (int nj = 0; nj < 2; ++nj) {
                    mma16816(acc[mi][nj * 2],     ah[mi], &bh[nj][0]);
                    mma16816(acc[mi][nj * 2 + 1], ah[mi], &bh[nj][2]);
                    mma16816(acc[mi][nj * 2],     ah[mi], &bl[nj][0]);
                    mma16816(acc[mi][nj * 2 + 1], ah[mi], &bl[nj][2]);
                    mma16816(acc[mi][nj * 2],     al[mi], &bh[nj][0]);
                    mma16816(acc[mi][nj * 2 + 1], al[mi], &bh[nj][2]);
                }
        }
        __syncthreads();
    }

    float* __restrict__ Y = g_feat[t][n];
#pragma unroll
    for (int mi = 0; mi < 3; ++mi)
#pragma unroll
        for (int g = 0; g < 4; ++g) {
            int r0 = m0 + mi * 16 + (lane >> 2);
            int col = n0 + warp * 32 + (g >> 1) * 16 + (g & 1) * 8 + (lane & 3) * 2;
            if (r0 < CMID) {
                float bv = bias[r0];
                *(float2*)&Y[(size_t)r0 * HW + col] =
                    make_float2(acc[mi][g][0] + bv, acc[mi][g][1] + bv);
            }
            if (r0 + 8 < CMID) {
                float bv = bias[r0 + 8];
                *(float2*)&Y[(size_t)(r0 + 8) * HW + col] =
                    make_float2(acc[mi][g][2] + bv, acc[mi][g][3] + bv);
            }
        }
}

// ---------------- K2: InstanceNorm + LeakyReLU + mean-center ----------------
__global__ void inorm_kernel() {
    const int c = blockIdx.x, n = blockIdx.y, t = blockIdx.z;
    float* __restrict__ Y = &g_feat[t][n][(size_t)c * HW];
    __shared__ float sd[HW];
    __shared__ float r1[256], r2[256];
    const int tid = threadIdx.x;

    float s = 0.f, q = 0.f;
    for (int i = tid; i < HW; i += 256) { float v = Y[i]; sd[i] = v; s += v; q += v * v; }
    r1[tid] = s; r2[tid] = q; __syncthreads();
    for (int st = 128; st > 0; st >>= 1) {
        if (tid < st) { r1[tid] += r1[tid + st]; r2[tid] += r2[tid + st]; }
        __syncthreads();
    }
    const float mean = r1[0] * (1.f / HW);
    const float var  = r2[0] * (1.f / HW) - mean * mean;
    const float inv  = rsqrtf(var + 1e-5f);
    __syncthreads();

    float s2 = 0.f;
    for (int i = tid; i < HW; i += 256) {
        float v = (sd[i] - mean) * inv;
        v = (v >= 0.f) ? v : 0.2f * v;
        sd[i] = v; s2 += v;
    }
    r1[tid] = s2; __syncthreads();
    for (int st = 128; st > 0; st >>= 1) {
        if (tid < st) r1[tid] += r1[tid + st];
        __syncthreads();
    }
    const float mean2 = r1[0] * (1.f / HW);
    for (int i = tid; i < HW; i += 256) Y[i] = sd[i] - mean2;
}

// ---------------- K3: L2-normalize + split hi/lo ----------------
__global__ void l2norm_kernel() {
    const int p = blockIdx.x * 256 + threadIdx.x;
    const int n = blockIdx.y, t = blockIdx.z;
    const float* __restrict__ F = g_feat[t][n];
    float q = 0.f;
    for (int c = 0; c < CMID; ++c) { float v = F[(size_t)c * HW + p]; q += v * v; }
    const float inv = rsqrtf(q);
    __half* __restrict__ hi = g_fh[t][0][n];
    __half* __restrict__ lo = g_fh[t][1][n];
    for (int c = 0; c < CMID; ++c) {
        float v = F[(size_t)c * HW + p] * inv;
        __half h = __float2half_rn(v);
        hi[(size_t)c * HW + p] = h;
        lo[(size_t)c * HW + p] = __float2half_rn(v - __half2float(h));
    }
}

// ---------------- K4: energy via split-fp16 HMMA + fused softmax partials ----------------
#define E_AST (48 * 136)
#define E_BST (48 * 264)
__global__ __launch_bounds__(512, 1) void energy_mma_kernel() {
    extern __shared__ __align__(16) __half eshm[];
    __half* As = eshm;                         // [3][48][136]
    __half* Bs = eshm + 3 * E_AST;             // [3][48][264]

    const int n = blockIdx.z;
    const int m0 = blockIdx.y * 128, l0 = blockIdx.x * 256;
    const int tid = threadIdx.x, lane = tid & 31, warp = tid >> 5;
    const int wm = warp & 3, wn = warp >> 2;
    const int r16 = lane & 15, c8 = (lane >> 4) << 3;
    const int arow = (lane & 7) + ((lane >> 4) & 1) * 8;
    const int acol = ((lane >> 3) & 1) * 8;

    const __half* Ap[3] = { g_fh[1][0][n], g_fh[1][0][n], g_fh[1][1][n] };
    const __half* Bp[3] = { g_fh[0][0][n], g_fh[0][1][n], g_fh[0][0][n] };

    float acc[2][8][4];
#pragma unroll
    for (int i = 0; i < 2; ++i)
#pragma unroll
        for (int j = 0; j < 8; ++j)
#pragma unroll
            for (int k = 0; k < 4; ++k) acc[i][j][k] = 0.f;

    const uint32_t su = smaddr(eshm);
    auto loadst = [&](int st, int q) {
        const int pass = q / 3, kc = (q % 3) * 48;
        const __half* __restrict__ A = Ap[pass];
        const __half* __restrict__ B = Bp[pass];
#pragma unroll
        for (int i = 0; i < 5; ++i) {
            int idx = tid + i * 512;
            if (idx < 768) {
                int row = idx >> 4, cp = (idx & 15) * 8;
                cpa16u(su + (st * E_AST + row * 136 + cp) * 2,
                       &A[(size_t)(kc + row) * HW + m0 + cp], 16);
            } else if (idx < 2304) {
                int ix = idx - 768;
                int row = ix >> 5, cp = (ix & 31) * 8;
                cpa16u(su + (3 * E_AST + st * E_BST + row * 264 + cp) * 2,
                       &B[(size_t)(kc + row) * HW + l0 + cp], 16);
            }
        }
    };

    loadst(0, 0); CP_COMMIT();
    loadst(1, 1); CP_COMMIT();
    for (int q = 0; q < 9; ++q) {
        const int st = q % 3;
        CP_WAIT(1);
        __syncthreads();
        if (q + 2 < 9) loadst((q + 2) % 3, q + 2);
        CP_COMMIT();

#pragma unroll
        for (int ks = 0; ks < 48; ks += 16) {
            uint32_t a[2][4], b[4][4];
#pragma unroll
            for (int mi = 0; mi < 2; ++mi)
                ldsm4t(a[mi], As + st * E_AST + (ks + arow) * 136 + wm * 32 + mi * 16 + acol);
#pragma unroll
            for (int nj = 0; nj < 4; ++nj)
                ldsm4t(b[nj], Bs + st * E_BST + (ks + r16) * 264 + wn * 64 + nj * 16 + c8);
#pragma unroll
            for (int mi = 0; mi < 2; ++mi)
#pragma unroll
                for (int nj = 0; nj < 4; ++nj) {
                    mma16816(acc[mi][nj * 2],     a[mi], &b[nj][0]);
                    mma16816(acc[mi][nj * 2 + 1], a[mi], &b[nj][2]);
                }
        }
        __syncthreads();
    }

    // scale to final E values
#pragma unroll
    for (int mi = 0; mi < 2; ++mi)
#pragma unroll
        for (int nj = 0; nj < 8; ++nj)
#pragma unroll
            for (int k = 0; k < 4; ++k) acc[mi][nj][k] *= 100.f;

    // write E
    float* __restrict__ E = g_E[n];
#pragma unroll
    for (int mi = 0; mi < 2; ++mi)
#pragma unroll
        for (int nj = 0; nj < 8; ++nj) {
            int row = m0 + wm * 32 + mi * 16 + (lane >> 2);
            int col = l0 + wn * 64 + nj * 8 + (lane & 3) * 2;
            *(float2*)&E[(size_t)row * HW + col] = make_float2(acc[mi][nj][0], acc[mi][nj][1]);
            *(float2*)&E[(size_t)(row + 8) * HW + col] = make_float2(acc[mi][nj][2], acc[mi][nj][3]);
        }

    // ---- fused softmax partials (reuse stage smem) ----
    float* sM   = (float*)eshm;        // row partials  [4 wn][128]
    float* sS   = sM + 512;            //               [4 wn][128]
    float* cMax = sS + 512;            // col partials  [4 wm][256]
    float* cS   = cMax + 1024;         //               [4 wm][256]

    // row partials (per l-block): max then expsum over this warp's 64 cols, merge 4 wn in smem
#pragma unroll
    for (int mi = 0; mi < 2; ++mi)
#pragma unroll
        for (int h = 0; h < 2; ++h) {
            float m = -1e30f;
#pragma unroll
            for (int nj = 0; nj < 8; ++nj)
                m = fmaxf(m, fmaxf(acc[mi][nj][2 * h], acc[mi][nj][2 * h + 1]));
            m = fmaxf(m, __shfl_xor_sync(0xFFFFFFFFu, m, 1));
            m = fmaxf(m, __shfl_xor_sync(0xFFFFFFFFu, m, 2));
            float s = 0.f;
#pragma unroll
            for (int nj = 0; nj < 8; ++nj)
                s += __expf(acc[mi][nj][2 * h] - m) + __expf(acc[mi][nj][2 * h + 1] - m);
            s += __shfl_xor_sync(0xFFFFFFFFu, s, 1);
            s += __shfl_xor_sync(0xFFFFFFFFu, s, 2);
            if ((lane & 3) == 0) {
                int r = wm * 32 + mi * 16 + (lane >> 2) + 8 * h;
                sM[wn * 128 + r] = m;
                sS[wn * 128 + r] = s;
            }
        }
    // col partials step 1: thread-local + cross-lane max (lanes xor 4,8,16 share cols)
    float m16[8][2];
#pragma unroll
    for (int nj = 0; nj < 8; ++nj)
#pragma unroll
        for (int c = 0; c < 2; ++c) {
            float m = fmaxf(fmaxf(acc[0][nj][c], acc[0][nj][2 + c]),
                            fmaxf(acc[1][nj][c], acc[1][nj][2 + c]));
            m = fmaxf(m, __shfl_xor_sync(0xFFFFFFFFu, m, 4));
            m = fmaxf(m, __shfl_xor_sync(0xFFFFFFFFu, m, 8));
            m = fmaxf(m, __shfl_xor_sync(0xFFFFFFFFu, m, 16));
            m16[nj][c] = m;
        }
    if ((lane >> 2) == 0) {
#pragma unroll
        for (int nj = 0; nj < 8; ++nj)
#pragma unroll
            for (int c = 0; c < 2; ++c)
                cMax[wm * 256 + wn * 64 + nj * 8 + (lane & 3) * 2 + c] = m16[nj][c];
    }
    __syncthreads();

    // row partials: merge 4 wn, write global
    if (tid < 128) {
        float M = sM[tid], S = sS[tid];
#pragma unroll
        for (int w = 1; w < 4; ++w) {
            float m2 = sM[w * 128 + tid], s2 = sS[w * 128 + tid];
            float M2 = fmaxf(M, m2);
            S = S * __expf(M - M2) + s2 * __expf(m2 - M2);
            M = M2;
        }
        g_rowPm[n][blockIdx.x][m0 + tid] = M;
        g_rowPs[n][blockIdx.x][m0 + tid] = S;
    }
    // col block max: merge 4 wm
    if (tid < 256) {
        float M = fmaxf(fmaxf(cMax[tid], cMax[256 + tid]),
                        fmaxf(cMax[512 + tid], cMax[768 + tid]));
        cMax[tid] = M;
    }
    __syncthreads();

    // col expsums vs block max
    float s16[8][2];
#pragma unroll
    for (int nj = 0; nj < 8; ++nj)
#pragma unroll
        for (int c = 0; c < 2; ++c) {
            float bm = cMax[wn * 64 + nj * 8 + (lane & 3) * 2 + c];
            float s = __expf(acc[0][nj][c] - bm) + __expf(acc[0][nj][2 + c] - bm)
                    + __expf(acc[1][nj][c] - bm) + __expf(acc[1][nj][2 + c] - bm);
            s += __shfl_xor_sync(0xFFFFFFFFu, s, 4);
            s += __shfl_xor_sync(0xFFFFFFFFu, s, 8);
            s += __shfl_xor_sync(0xFFFFFFFFu, s, 16);
            s16[nj][c] = s;
        }
    if ((lane >> 2) == 0) {
#pragma unroll
        for (int nj = 0; nj < 8; ++nj)
#pragma unroll
            for (int c = 0; c < 2; ++c)
                cS[wm * 256 + wn * 64 + nj * 8 + (lane & 3) * 2 + c] = s16[nj][c];
    }
    __syncthreads();
    if (tid < 256) {
        float S = cS[tid] + cS[256 + tid] + cS[512 + tid] + cS[768 + tid];
        g_colPm[n][blockIdx.y][l0 + tid] = cMax[tid];
        g_colPs[n][blockIdx.y][l0 + tid] = S;
    }
}

// ---------------- K5: combine partial stats ----------------
__global__ void rowcombine_kernel() {
    const int r = blockIdx.x * 256 + threadIdx.x;
    const int n = blockIdx.y;
    float M = -1e30f, S = 0.f;
#pragma unroll
    for (int b = 0; b < 16; ++b) {
        float m = g_rowPm[n][b][r], s = g_rowPs[n][b][r];
        float M2 = fmaxf(M, m);
        S = S * __expf(M - M2) + s * __expf(m - M2);
        M = M2;
    }
    g_rowM[n][r] = M;
    g_rowSinv[n][r] = 1.0f / S;
}

__global__ void colcombine_kernel() {
    const int c = blockIdx.x * 256 + threadIdx.x;
    const int n = blockIdx.y;
    float M = -1e30f, S = 0.f;
#pragma unroll
    for (int b = 0; b < 32; ++b) {
        float m = g_colPm[n][b][c], s = g_colPs[n][b][c];
        float M2 = fmaxf(M, m);
        S = S * __expf(M - M2) + s * __expf(m - M2);
        M = M2;
    }
    g_colM[n][c] = M;
    g_colSinv[n][c] = 1.0f / S;
}

// ---------------- K6: softmax writeout, vectorized ----------------
__global__ void writeout_kernel(float* __restrict__ out_ab, float* __restrict__ out_ba) {
    const int c0 = blockIdx.x * 64, r0 = blockIdx.y * 64, n = blockIdx.z;
    const int tid = threadIdx.x;
    const int tx = tid & 15, ty = tid >> 4;
    const float* __restrict__ E = g_E[n];
    __half* __restrict__ Hab = g_corr_h[0][n];
    __half* __restrict__ Hba = g_corr_h[1][n];
    float* __restrict__ Oab = out_ab + (size_t)n * HW * HW;
    float* __restrict__ Oba = out_ba + (size_t)n * HW * HW;

    __shared__ float t_ba[64][68];
    __shared__ float rm_s[64], rsi_s[64];
    if (tid < 64)       rm_s[tid]       = g_rowM[n][r0 + tid];
    else if (tid < 128) rsi_s[tid - 64] = g_rowSinv[n][r0 + tid - 64];
    const float4 cm4  = *(const float4*)&g_colM[n][c0 + tx * 4];
    const float4 csi4 = *(const float4*)&g_colSinv[n][c0 + tx * 4];
    __syncthreads();

#pragma unroll
    for (int it = 0; it < 4; ++it) {
        int r_in = it * 16 + ty;
        int R = r0 + r_in;
        float4 e = *(const float4*)&E[(size_t)R * HW + c0 + tx * 4];
        float rm = rm_s[r_in], rsi = rsi_s[r_in];
        float4 pr = make_float4(__expf(e.x - rm) * rsi, __expf(e.y - rm) * rsi,
                                __expf(e.z - rm) * rsi, __expf(e.w - rm) * rsi);
        float pc0 = __expf(e.x - cm4.x) * csi4.x;
        float pc1 = __expf(e.y - cm4.y) * csi4.y;
        float pc2 = __expf(e.z - cm4.z) * csi4.z;
        float pc3 = __expf(e.w - cm4.w) * csi4.w;
        size_t off = (size_t)R * HW + c0 + tx * 4;
        *(float4*)&Oab[off] = pr;
        __half2 h0 = __floats2half2_rn(pr.x, pr.y);
        __half2 h1 = __floats2half2_rn(pr.z, pr.w);
        *(uint2*)&Hab[off] = make_uint2(*(uint32_t*)&h0, *(uint32_t*)&h1);
        t_ba[tx * 4 + 0][r_in] = pc0;
        t_ba[tx * 4 + 1][r_in] = pc1;
        t_ba[tx * 4 + 2][r_in] = pc2;
        t_ba[tx * 4 + 3][r_in] = pc3;
    }
    __syncthreads();
#pragma unroll
    for (int it = 0; it < 4; ++it) {
        int c_in = it * 16 + ty;
        float4 p = *(const float4*)&t_ba[c_in][tx * 4];
        size_t off = (size_t)(c0 + c_in) * HW + r0 + tx * 4;
        *(float4*)&Oba[off] = p;
        __half2 h0 = __floats2half2_rn(p.x, p.y);
        __half2 h1 = __floats2half2_rn(p.z, p.w);
        *(uint2*)&Hba[off] = make_uint2(*(uint32_t*)&h0, *(uint32_t*)&h1);
    }
}

// ---------------- K7: raw -> fp16 ----------------
__global__ void tohalf_kernel(const float* __restrict__ a_raw, const float* __restrict__ b_raw) {
    const int t = blockIdx.y;
    const float* __restrict__ src = (t == 0 ? a_raw : b_raw);
    __half* __restrict__ dst = &g_raw_h[t][0][0];
    size_t i = ((size_t)blockIdx.x * 256 + threadIdx.x) * 4;
    float4 v = *(const float4*)&src[i];
    __half2* d2 = (__half2*)&dst[i];
    d2[0] = __floats2half2_rn(v.x, v.y);
    d2[1] = __floats2half2_rn(v.z, v.w);
}

// ---------------- K8: warp matmul (single-frag, no spills) ----------------
#define G_AST (128 * 72)
#define G_BST (64 * 264)
#define G_NC 64
__global__ __launch_bounds__(512, 1) void wgemm_kernel(float* __restrict__ out) {
    extern __shared__ __align__(16) __half gshm[];
    __half* As = gshm;                        // [3][128][72]
    __half* Bs = gshm + 3 * G_AST;            // [3][64][264]
    const uint32_t su = smaddr(gshm);

    const int z = blockIdx.z;
    const int dir = z >> 1, n = z & 1;
    const __half* __restrict__ A = g_raw_h[dir][n];
    const __half* __restrict__ B = g_corr_h[dir ^ 1][n];
    float* __restrict__ C = out + (size_t)4 * HW * HW
                                + (size_t)dir * 2 * CIN * HW + (size_t)n * CIN * HW;
    const int m0 = blockIdx.y * 128, n0 = blockIdx.x * 256;
    const int tid = threadIdx.x, lane = tid & 31, warp = tid >> 5;
    const int wm = warp & 3, wn = warp >> 2;
    const int r16 = lane & 15, c8 = (lane >> 4) << 3;

    float acc[2][8][4];
#pragma unroll
    for (int i = 0; i < 2; ++i)
#pragma unroll
        for (int j = 0; j < 8; ++j)
#pragma unroll
            for (int k = 0; k < 4; ++k) acc[i][j][k] = 0.f;

    auto loadst = [&](int st, int j) {
        const int k0 = j * 64;
#pragma unroll
        for (int i = 0; i < 6; ++i) {
            int idx = tid + i * 512;
            if (idx < 1024) {
                int row = idx >> 3, cp = (idx & 7) * 8;
                int gr = m0 + row;
                int ok = gr < CIN;
                cpa16u(su + (st * G_AST + row * 72 + cp) * 2,
                       &A[(size_t)(ok ? gr : 0) * HW + k0 + cp], ok ? 16 : 0);
            } else {
                int ix = idx - 1024;
                int row = ix >> 5, cp = (ix & 31) * 8;
                cpa16u(su + (3 * G_AST + st * G_BST + row * 264 + cp) * 2,
                       &B[(size_t)(k0 + row) * HW + n0 + cp], 16);
            }
        }
    };

    loadst(0, 0); CP_COMMIT();
    loadst(1, 1); CP_COMMIT();

    for (int j = 0; j < G_NC; ++j) {
        const int st = j % 3;
        CP_WAIT(1);
        __syncthreads();
        if (j + 2 < G_NC) loadst((j + 2) % 3, j + 2);
        CP_COMMIT();

#pragma unroll
        for (int ks = 0; ks < 64; ks += 16) {
            uint32_t a[2][4], b[4][4];
#pragma unroll
            for (int mi = 0; mi < 2; ++mi)
                ldsm4(a[mi], As + st * G_AST + (wm * 32 + mi * 16 + r16) * 72 + ks + c8);
#pragma unroll
            for (int nj = 0; nj < 4; ++nj)
                ldsm4t(b[nj], Bs + st * G_BST + (ks + r16) * 264 + wn * 64 + nj * 16 + c8);
#pragma unroll
            for (int mi = 0; mi < 2; ++mi)
#pragma unroll
                for (int nj = 0; nj < 4; ++nj) {
                    mma16816(acc[mi][nj * 2],     a[mi], &b[nj][0]);
                    mma16816(acc[mi][nj * 2 + 1], a[mi], &b[nj][2]);
                }
        }
        __syncthreads();
    }

#pragma unroll
    for (int mi = 0; mi < 2; ++mi)
#pragma unroll
        for (int nj = 0; nj < 8; ++nj) {
            int row = m0 + wm * 32 + mi * 16 + (lane >> 2);
            int col = n0 + wn * 64 + nj * 8 + (lane & 3) * 2;
            if (row < CIN)
                *(float2*)&C[(size_t)row * HW + col] = make_float2(acc[mi][nj][0], acc[mi][nj][1]);
            if (row + 8 < CIN)
                *(float2*)&C[(size_t)(row + 8) * HW + col] = make_float2(acc[mi][nj][2], acc[mi][nj][3]);
        }
}

// ---------------- launch ----------------
extern "C" void kernel_launch(void* const* d_in, const int* in_sizes, int n_in,
                              void* d_out, int out_size) {
    const float* fa    = (const float*)d_in[0];
    const float* fb    = (const float*)d_in[1];
    const float* a_raw = (const float*)d_in[2];
    const float* b_raw = (const float*)d_in[3];
    const float* Wa    = (const float*)d_in[4];
    const float* ba    = (const float*)d_in[5];
    const float* Wb    = (const float*)d_in[6];
    const float* bb    = (const float*)d_in[7];
    float* out = (float*)d_out;

    const int c_smem = 32 * 256 * 4 + 48 * 32 * 4 + 2 * 2 * 32 * 264 * 2 + 2 * 2 * 48 * 40 * 2; // 121856
    const int e_smem = 3 * (E_AST + E_BST) * 2;          // 115200
    const int g_smem = 3 * (G_AST + G_BST) * 2;          // 156672
    cudaFuncSetAttribute(conv_mma_kernel, cudaFuncAttributeMaxDynamicSharedMemorySize, c_smem);
    cudaFuncSetAttribute(energy_mma_kernel, cudaFuncAttributeMaxDynamicSharedMemorySize, e_smem);
    cudaFuncSetAttribute(wgemm_kernel, cudaFuncAttributeMaxDynamicSharedMemorySize, g_smem);

    conv_mma_kernel<<<dim3(16, 3, 4), 256, c_smem>>>(fa, fb, Wa, ba, Wb, bb);
    inorm_kernel<<<dim3(CMID, 2, 2), 256>>>();
    l2norm_kernel<<<dim3(HW / 256, 2, 2), 256>>>();
    energy_mma_kernel<<<dim3(16, 32, 2), 512, e_smem>>>();
    tohalf_kernel<<<dim3(8704, 2), 256>>>(a_raw, b_raw);
    rowcombine_kernel<<<dim3(HW / 256, 2), 256>>>();
    colcombine_kernel<<<dim3(HW / 256, 2), 256>>>();
    writeout_kernel<<<dim3(64, 64, 2), 256>>>(out, out + (size_t)2 * HW * HW);
    wgemm_kernel<<<dim3(16, 9, 4), 512, g_smem>>>(out);
}

// round 10
// speedup vs baseline: 1.7840x; 1.0158x over previous
#include <cuda_runtime.h>
#include <cuda_fp16.h>
#include <cstdint>
#include <cstddef>

#define HW 4096
#define CIN 1088
#define CMID 136
#define CPAD 144

// ---------------- scratch (device globals; zero-initialized, no allocs) ----------------
__device__ float  g_feat[2][2][(size_t)CMID * HW];        // [a/b][n][c*HW+p]
__device__ float  g_E[2][(size_t)HW * HW];                // energy (already *100)
__device__ __half g_corr_h[2][2][(size_t)HW * HW];        // fp16 corr, [ab/ba][n], [k][l]
__device__ __half g_raw_h[2][2][(size_t)CIN * HW];        // [a/b][n]
__device__ __half g_fh[2][2][2][(size_t)CPAD * HW];       // [a/b][hi/lo][n], [c][p]
__device__ float  g_rowM[2][HW], g_rowSinv[2][HW];
__device__ float  g_colM[2][HW], g_colSinv[2][HW];
__device__ float  g_rowPm[2][16][HW],  g_rowPs[2][16][HW];   // per-l-block row partials
__device__ float  g_colPm[2][32][HW],  g_colPs[2][32][HW];   // per-m-block col partials

// ---------------- PTX helpers ----------------
__device__ __forceinline__ uint32_t smaddr(const void* p) {
    return (uint32_t)__cvta_generic_to_shared(p);
}
__device__ __forceinline__ void ldsm4(uint32_t r[4], const void* p) {
    asm volatile("ldmatrix.sync.aligned.m8n8.x4.shared.b16 {%0,%1,%2,%3}, [%4];\n"
                 : "=r"(r[0]), "=r"(r[1]), "=r"(r[2]), "=r"(r[3]) : "r"(smaddr(p)));
}
__device__ __forceinline__ void ldsm4t(uint32_t r[4], const void* p) {
    asm volatile("ldmatrix.sync.aligned.m8n8.x4.trans.shared.b16 {%0,%1,%2,%3}, [%4];\n"
                 : "=r"(r[0]), "=r"(r[1]), "=r"(r[2]), "=r"(r[3]) : "r"(smaddr(p)));
}
__device__ __forceinline__ void mma16816(float* d, const uint32_t* a, const uint32_t* b) {
    asm volatile("mma.sync.aligned.m16n8k16.row.col.f32.f16.f16.f32 "
                 "{%0,%1,%2,%3}, {%4,%5,%6,%7}, {%8,%9}, {%0,%1,%2,%3};\n"
                 : "+f"(d[0]), "+f"(d[1]), "+f"(d[2]), "+f"(d[3])
                 : "r"(a[0]), "r"(a[1]), "r"(a[2]), "r"(a[3]), "r"(b[0]), "r"(b[1]));
}
__device__ __forceinline__ void cpa16u(uint32_t sm, const void* g, int bytes) {
    asm volatile("cp.async.cg.shared.global [%0], [%1], 16, %2;\n"
                 :: "r"(sm), "l"(g), "r"(bytes));
}
#define CP_COMMIT() asm volatile("cp.async.commit_group;\n" ::: "memory")
#define CP_WAIT(n)  asm volatile("cp.async.wait_group %0;\n" :: "n"(n) : "memory")

// ---------------- K1: 1x1 conv via split-fp16 HMMA ----------------
__global__ __launch_bounds__(256, 1) void conv_mma_kernel(
    const float* __restrict__ fa, const float* __restrict__ fb,
    const float* __restrict__ Wa, const float* __restrict__ ba,
    const float* __restrict__ Wb, const float* __restrict__ bb) {
    extern __shared__ __align__(16) char csm[];
    float*  Xf  = (float*)csm;
    float*  Wf  = Xf + 32 * 256;
    __half* Xhl = (__half*)(Wf + 48 * 32);
    __half* Whl = Xhl + 2 * 2 * 32 * 264;

    const int t = blockIdx.z >> 1, n = blockIdx.z & 1;
    const float* __restrict__ X = (t == 0 ? fa : fb) + (size_t)n * CIN * HW;
    const float* __restrict__ W = (t == 0 ? Wa : Wb);
    const float* __restrict__ bias = (t == 0 ? ba : bb);
    const int m0 = blockIdx.y * 48, n0 = blockIdx.x * 256;
    const int tid = threadIdx.x, lane = tid & 31, warp = tid >> 5;
    const int r16 = lane & 15, c8 = (lane >> 4) << 3;

    float acc[3][4][4];
#pragma unroll
    for (int i = 0; i < 3; ++i)
#pragma unroll
        for (int j = 0; j < 4; ++j)
#pragma unroll
            for (int k = 0; k < 4; ++k) acc[i][j][k] = 0.f;

    auto cpX = [&](int kc) {
#pragma unroll
        for (int i = 0; i < 8; ++i) {
            int idx = tid + i * 256;
            int row = idx >> 6, seg = (idx & 63) * 4;
            cpa16u(smaddr(&Xf[row * 256 + seg]), &X[(size_t)(kc + row) * HW + n0 + seg], 16);
        }
#pragma unroll
        for (int i = 0; i < 2; ++i) {
            int idx = tid + i * 256;
            if (idx < 384) {
                int row = idx >> 3, seg = (idx & 7) * 4;
                int o = m0 + row;
                int ok = o < CMID;
                cpa16u(smaddr(&Wf[row * 32 + seg]), &W[(size_t)(ok ? o : 0) * CIN + kc + seg], ok ? 16 : 0);
            }
        }
    };
    auto convert = [&](int s) {
        __half* Xh = Xhl + s * (2 * 32 * 264);
        __half* Xl = Xh + 32 * 264;
#pragma unroll
        for (int i = 0; i < 32; ++i) {
            int idx = tid + i * 256;
            int row = idx >> 8, col = idx & 255;
            float v = Xf[row * 256 + col];
            __half h = __float2half_rn(v);
            Xh[row * 264 + col] = h;
            Xl[row * 264 + col] = __float2half_rn(v - __half2float(h));
        }
        __half* Wh = Whl + s * (2 * 48 * 40);
        __half* Wl = Wh + 48 * 40;
#pragma unroll
        for (int i = 0; i < 6; ++i) {
            int idx = tid + i * 256;
            if (idx < 1536) {
                int row = idx >> 5, col = idx & 31;
                float v = Wf[row * 32 + col];
                __half h = __float2half_rn(v);
                Wh[row * 40 + col] = h;
                Wl[row * 40 + col] = __float2half_rn(v - __half2float(h));
            }
        }
    };

    cpX(0); CP_COMMIT();
    for (int j = 0; j < 34; ++j) {
        const int s = j & 1;
        CP_WAIT(0);
        __syncthreads();
        convert(s);
        __syncthreads();
        if (j + 1 < 34) cpX((j + 1) * 32);
        CP_COMMIT();

        const __half* Xh = Xhl + s * (2 * 32 * 264);
        const __half* Xl = Xh + 32 * 264;
        const __half* Wh = Whl + s * (2 * 48 * 40);
        const __half* Wl = Wh + 48 * 40;
#pragma unroll
        for (int ks = 0; ks < 32; ks += 16) {
            uint32_t ah[3][4], al[3][4], bh[2][4], bl[2][4];
#pragma unroll
            for (int mi = 0; mi < 3; ++mi) {
                ldsm4(ah[mi], &Wh[(mi * 16 + r16) * 40 + ks + c8]);
                ldsm4(al[mi], &Wl[(mi * 16 + r16) * 40 + ks + c8]);
            }
#pragma unroll
            for (int nj = 0; nj < 2; ++nj) {
                ldsm4t(bh[nj], &Xh[(ks + r16) * 264 + warp * 32 + nj * 16 + c8]);
                ldsm4t(bl[nj], &Xl[(ks + r16) * 264 + warp * 32 + nj * 16 + c8]);
            }
#pragma unroll
            for (int mi = 0; mi < 3; ++mi)
#pragma unroll
                for (int nj = 0; nj < 2; ++nj) {
                    mma16816(acc[mi][nj * 2],     ah[mi], &bh[nj][0]);
                    mma16816(acc[mi][nj * 2 + 1], ah[mi], &bh[nj][2]);
                    mma16816(acc[mi][nj * 2],     ah[mi], &bl[nj][0]);
                    mma16816(acc[mi][nj * 2 + 1], ah[mi], &bl[nj][2]);
                    mma16816(acc[mi][nj * 2],     al[mi], &bh[nj][0]);
                    mma16816(acc[mi][nj * 2 + 1], al[mi], &bh[nj][2]);
                }
        }
        __syncthreads();
    }

    float* __restrict__ Y = g_feat[t][n];
#pragma unroll
    for (int mi = 0; mi < 3; ++mi)
#pragma unroll
        for (int g = 0; g < 4; ++g) {
            int r0 = m0 + mi * 16 + (lane >> 2);
            int col = n0 + warp * 32 + (g >> 1) * 16 + (g & 1) * 8 + (lane & 3) * 2;
            if (r0 < CMID) {
                float bv = bias[r0];
                *(float2*)&Y[(size_t)r0 * HW + col] =
                    make_float2(acc[mi][g][0] + bv, acc[mi][g][1] + bv);
            }
            if (r0 + 8 < CMID) {
                float bv = bias[r0 + 8];
                *(float2*)&Y[(size_t)(r0 + 8) * HW + col] =
                    make_float2(acc[mi][g][2] + bv, acc[mi][g][3] + bv);
            }
        }
}

// ---------------- K2: InstanceNorm + LeakyReLU + mean-center ----------------
__global__ void inorm_kernel() {
    const int c = blockIdx.x, n = blockIdx.y, t = blockIdx.z;
    float* __restrict__ Y = &g_feat[t][n][(size_t)c * HW];
    __shared__ float sd[HW];
    __shared__ float r1[256], r2[256];
    const int tid = threadIdx.x;

    float s = 0.f, q = 0.f;
    for (int i = tid; i < HW; i += 256) { float v = Y[i]; sd[i] = v; s += v; q += v * v; }
    r1[tid] = s; r2[tid] = q; __syncthreads();
    for (int st = 128; st > 0; st >>= 1) {
        if (tid < st) { r1[tid] += r1[tid + st]; r2[tid] += r2[tid + st]; }
        __syncthreads();
    }
    const float mean = r1[0] * (1.f / HW);
    const float var  = r2[0] * (1.f / HW) - mean * mean;
    const float inv  = rsqrtf(var + 1e-5f);
    __syncthreads();

    float s2 = 0.f;
    for (int i = tid; i < HW; i += 256) {
        float v = (sd[i] - mean) * inv;
        v = (v >= 0.f) ? v : 0.2f * v;
        sd[i] = v; s2 += v;
    }
    r1[tid] = s2; __syncthreads();
    for (int st = 128; st > 0; st >>= 1) {
        if (tid < st) r1[tid] += r1[tid + st];
        __syncthreads();
    }
    const float mean2 = r1[0] * (1.f / HW);
    for (int i = tid; i < HW; i += 256) Y[i] = sd[i] - mean2;
}

// ---------------- K3: L2-normalize + split hi/lo ----------------
__global__ void l2norm_kernel() {
    const int p = blockIdx.x * 256 + threadIdx.x;
    const int n = blockIdx.y, t = blockIdx.z;
    const float* __restrict__ F = g_feat[t][n];
    float q = 0.f;
    for (int c = 0; c < CMID; ++c) { float v = F[(size_t)c * HW + p]; q += v * v; }
    const float inv = rsqrtf(q);
    __half* __restrict__ hi = g_fh[t][0][n];
    __half* __restrict__ lo = g_fh[t][1][n];
    for (int c = 0; c < CMID; ++c) {
        float v = F[(size_t)c * HW + p] * inv;
        __half h = __float2half_rn(v);
        hi[(size_t)c * HW + p] = h;
        lo[(size_t)c * HW + p] = __float2half_rn(v - __half2float(h));
    }
}

// ---------------- K4: energy, merged-pass split-fp16 HMMA + fused softmax partials ----------------
// block 128(m) x 256(l); per k48 chunk load Ah/Al/Bh/Bl once; hh + ah*bl + al*bh.
#define E_A   (48 * 136)             // halves per A tile
#define E_B   (48 * 264)             // halves per B tile
#define E_STG (2 * E_A + 2 * E_B)    // halves per stage (38400)
__global__ __launch_bounds__(512, 1) void energy_mma_kernel() {
    extern __shared__ __align__(16) __half eshm[];

    const int n = blockIdx.z;
    const int m0 = blockIdx.y * 128, l0 = blockIdx.x * 256;
    const int tid = threadIdx.x, lane = tid & 31, warp = tid >> 5;
    const int wm = warp & 3, wn = warp >> 2;
    const int r16 = lane & 15, c8 = (lane >> 4) << 3;
    const int arow = (lane & 7) + ((lane >> 4) & 1) * 8;
    const int acol = ((lane >> 3) & 1) * 8;

    float acc[2][8][4];
#pragma unroll
    for (int i = 0; i < 2; ++i)
#pragma unroll
        for (int j = 0; j < 8; ++j)
#pragma unroll
            for (int k = 0; k < 4; ++k) acc[i][j][k] = 0.f;

    const uint32_t su = smaddr(eshm);
    auto loadst = [&](int st, int q) {
        const int kc = q * 48;
        const uint32_t SB = su + st * E_STG * 2;
#pragma unroll
        for (int i = 0; i < 9; ++i) {
            int idx = tid + i * 512;
            if (idx < 1536) {
                int hl = idx >= 768;
                int ix = idx - hl * 768;
                int row = ix >> 4, cp = (ix & 15) * 8;
                cpa16u(SB + (hl * E_A + row * 136 + cp) * 2,
                       &g_fh[1][hl][n][(size_t)(kc + row) * HW + m0 + cp], 16);
            } else {
                int jx = idx - 1536;
                int hl = jx >= 1536;
                int ix = jx - hl * 1536;
                int row = ix >> 5, cp = (ix & 31) * 8;
                cpa16u(SB + (2 * E_A + hl * E_B + row * 264 + cp) * 2,
                       &g_fh[0][hl][n][(size_t)(kc + row) * HW + l0 + cp], 16);
            }
        }
    };

    auto mmag2 = [&](uint32_t a[2][4], uint32_t b[4][4]) {
#pragma unroll
        for (int mi = 0; mi < 2; ++mi)
#pragma unroll
            for (int nj = 0; nj < 4; ++nj) {
                mma16816(acc[mi][nj * 2],     a[mi], &b[nj][0]);
                mma16816(acc[mi][nj * 2 + 1], a[mi], &b[nj][2]);
            }
    };

    loadst(0, 0); CP_COMMIT();
    loadst(1, 1); CP_COMMIT();
    for (int q = 0; q < 3; ++q) {
        const int st = q & 1;
        if (q == 2) CP_WAIT(0); else CP_WAIT(1);
        __syncthreads();
        const __half* Ah = eshm + st * E_STG;
        const __half* Al = Ah + E_A;
        const __half* Bh = Al + E_A;
        const __half* Bl = Bh + E_B;
#pragma unroll
        for (int ks = 0; ks < 48; ks += 16) {
            uint32_t ah[2][4], bh[4][4];
#pragma unroll
            for (int mi = 0; mi < 2; ++mi)
                ldsm4t(ah[mi], Ah + (ks + arow) * 136 + wm * 32 + mi * 16 + acol);
#pragma unroll
            for (int nj = 0; nj < 4; ++nj)
                ldsm4t(bh[nj], Bh + (ks + r16) * 264 + wn * 64 + nj * 16 + c8);
            mmag2(ah, bh);
            {
                uint32_t bl[4][4];
#pragma unroll
                for (int nj = 0; nj < 4; ++nj)
                    ldsm4t(bl[nj], Bl + (ks + r16) * 264 + wn * 64 + nj * 16 + c8);
                mmag2(ah, bl);
            }
            {
                uint32_t al[2][4];
#pragma unroll
                for (int mi = 0; mi < 2; ++mi)
                    ldsm4t(al[mi], Al + (ks + arow) * 136 + wm * 32 + mi * 16 + acol);
                mmag2(al, bh);
            }
        }
        __syncthreads();
        if (q + 2 < 3) { loadst(st, q + 2); CP_COMMIT(); }
    }

    // scale to final E values
#pragma unroll
    for (int mi = 0; mi < 2; ++mi)
#pragma unroll
        for (int nj = 0; nj < 8; ++nj)
#pragma unroll
            for (int k = 0; k < 4; ++k) acc[mi][nj][k] *= 100.f;

    // write E
    float* __restrict__ E = g_E[n];
#pragma unroll
    for (int mi = 0; mi < 2; ++mi)
#pragma unroll
        for (int nj = 0; nj < 8; ++nj) {
            int row = m0 + wm * 32 + mi * 16 + (lane >> 2);
            int col = l0 + wn * 64 + nj * 8 + (lane & 3) * 2;
            *(float2*)&E[(size_t)row * HW + col] = make_float2(acc[mi][nj][0], acc[mi][nj][1]);
            *(float2*)&E[(size_t)(row + 8) * HW + col] = make_float2(acc[mi][nj][2], acc[mi][nj][3]);
        }

    // ---- fused softmax partials (reuse stage smem) ----
    float* sM   = (float*)eshm;        // row partials  [4 wn][128]
    float* sS   = sM + 512;            //               [4 wn][128]
    float* cMax = sS + 512;            // col partials  [4 wm][256]
    float* cS   = cMax + 1024;         //               [4 wm][256]

#pragma unroll
    for (int mi = 0; mi < 2; ++mi)
#pragma unroll
        for (int h = 0; h < 2; ++h) {
            float m = -1e30f;
#pragma unroll
            for (int nj = 0; nj < 8; ++nj)
                m = fmaxf(m, fmaxf(acc[mi][nj][2 * h], acc[mi][nj][2 * h + 1]));
            m = fmaxf(m, __shfl_xor_sync(0xFFFFFFFFu, m, 1));
            m = fmaxf(m, __shfl_xor_sync(0xFFFFFFFFu, m, 2));
            float s = 0.f;
#pragma unroll
            for (int nj = 0; nj < 8; ++nj)
                s += __expf(acc[mi][nj][2 * h] - m) + __expf(acc[mi][nj][2 * h + 1] - m);
            s += __shfl_xor_sync(0xFFFFFFFFu, s, 1);
            s += __shfl_xor_sync(0xFFFFFFFFu, s, 2);
            if ((lane & 3) == 0) {
                int r = wm * 32 + mi * 16 + (lane >> 2) + 8 * h;
                sM[wn * 128 + r] = m;
                sS[wn * 128 + r] = s;
            }
        }
    float m16[8][2];
#pragma unroll
    for (int nj = 0; nj < 8; ++nj)
#pragma unroll
        for (int c = 0; c < 2; ++c) {
            float m = fmaxf(fmaxf(acc[0][nj][c], acc[0][nj][2 + c]),
                            fmaxf(acc[1][nj][c], acc[1][nj][2 + c]));
            m = fmaxf(m, __shfl_xor_sync(0xFFFFFFFFu, m, 4));
            m = fmaxf(m, __shfl_xor_sync(0xFFFFFFFFu, m, 8));
            m = fmaxf(m, __shfl_xor_sync(0xFFFFFFFFu, m, 16));
            m16[nj][c] = m;
        }
    if ((lane >> 2) == 0) {
#pragma unroll
        for (int nj = 0; nj < 8; ++nj)
#pragma unroll
            for (int c = 0; c < 2; ++c)
                cMax[wm * 256 + wn * 64 + nj * 8 + (lane & 3) * 2 + c] = m16[nj][c];
    }
    __syncthreads();

    if (tid < 128) {
        float M = sM[tid], S = sS[tid];
#pragma unroll
        for (int w = 1; w < 4; ++w) {
            float m2 = sM[w * 128 + tid], s2 = sS[w * 128 + tid];
            float M2 = fmaxf(M, m2);
            S = S * __expf(M - M2) + s2 * __expf(m2 - M2);
            M = M2;
        }
        g_rowPm[n][blockIdx.x][m0 + tid] = M;
        g_rowPs[n][blockIdx.x][m0 + tid] = S;
    }
    if (tid < 256) {
        float M = fmaxf(fmaxf(cMax[tid], cMax[256 + tid]),
                        fmaxf(cMax[512 + tid], cMax[768 + tid]));
        cMax[tid] = M;
    }
    __syncthreads();

    float s16[8][2];
#pragma unroll
    for (int nj = 0; nj < 8; ++nj)
#pragma unroll
        for (int c = 0; c < 2; ++c) {
            float bm = cMax[wn * 64 + nj * 8 + (lane & 3) * 2 + c];
            float s = __expf(acc[0][nj][c] - bm) + __expf(acc[0][nj][2 + c] - bm)
                    + __expf(acc[1][nj][c] - bm) + __expf(acc[1][nj][2 + c] - bm);
            s += __shfl_xor_sync(0xFFFFFFFFu, s, 4);
            s += __shfl_xor_sync(0xFFFFFFFFu, s, 8);
            s += __shfl_xor_sync(0xFFFFFFFFu, s, 16);
            s16[nj][c] = s;
        }
    if ((lane >> 2) == 0) {
#pragma unroll
        for (int nj = 0; nj < 8; ++nj)
#pragma unroll
            for (int c = 0; c < 2; ++c)
                cS[wm * 256 + wn * 64 + nj * 8 + (lane & 3) * 2 + c] = s16[nj][c];
    }
    __syncthreads();
    if (tid < 256) {
        float S = cS[tid] + cS[256 + tid] + cS[512 + tid] + cS[768 + tid];
        g_colPm[n][blockIdx.y][l0 + tid] = cMax[tid];
        g_colPs[n][blockIdx.y][l0 + tid] = S;
    }
}

// ---------------- K5: combine partial stats (row z=0, col z=1) ----------------
__global__ void combine_kernel() {
    const int i = blockIdx.x * 256 + threadIdx.x;
    const int n = blockIdx.y;
    float M = -1e30f, S = 0.f;
    if (blockIdx.z == 0) {
#pragma unroll
        for (int b = 0; b < 16; ++b) {
            float m = g_rowPm[n][b][i], s = g_rowPs[n][b][i];
            float M2 = fmaxf(M, m);
            S = S * __expf(M - M2) + s * __expf(m - M2);
            M = M2;
        }
        g_rowM[n][i] = M;
        g_rowSinv[n][i] = 1.0f / S;
    } else {
#pragma unroll
        for (int b = 0; b < 32; ++b) {
            float m = g_colPm[n][b][i], s = g_colPs[n][b][i];
            float M2 = fmaxf(M, m);
            S = S * __expf(M - M2) + s * __expf(m - M2);
            M = M2;
        }
        g_colM[n][i] = M;
        g_colSinv[n][i] = 1.0f / S;
    }
}

// ---------------- K6: softmax writeout, vectorized ----------------
__global__ void writeout_kernel(float* __restrict__ out_ab, float* __restrict__ out_ba) {
    const int c0 = blockIdx.x * 64, r0 = blockIdx.y * 64, n = blockIdx.z;
    const int tid = threadIdx.x;
    const int tx = tid & 15, ty = tid >> 4;
    const float* __restrict__ E = g_E[n];
    __half* __restrict__ Hab = g_corr_h[0][n];
    __half* __restrict__ Hba = g_corr_h[1][n];
    float* __restrict__ Oab = out_ab + (size_t)n * HW * HW;
    float* __restrict__ Oba = out_ba + (size_t)n * HW * HW;

    __shared__ float t_ba[64][68];
    __shared__ float rm_s[64], rsi_s[64];
    if (tid < 64)       rm_s[tid]       = g_rowM[n][r0 + tid];
    else if (tid < 128) rsi_s[tid - 64] = g_rowSinv[n][r0 + tid - 64];
    const float4 cm4  = *(const float4*)&g_colM[n][c0 + tx * 4];
    const float4 csi4 = *(const float4*)&g_colSinv[n][c0 + tx * 4];
    __syncthreads();

#pragma unroll
    for (int it = 0; it < 4; ++it) {
        int r_in = it * 16 + ty;
        int R = r0 + r_in;
        float4 e = *(const float4*)&E[(size_t)R * HW + c0 + tx * 4];
        float rm = rm_s[r_in], rsi = rsi_s[r_in];
        float4 pr = make_float4(__expf(e.x - rm) * rsi, __expf(e.y - rm) * rsi,
                                __expf(e.z - rm) * rsi, __expf(e.w - rm) * rsi);
        float pc0 = __expf(e.x - cm4.x) * csi4.x;
        float pc1 = __expf(e.y - cm4.y) * csi4.y;
        float pc2 = __expf(e.z - cm4.z) * csi4.z;
        float pc3 = __expf(e.w - cm4.w) * csi4.w;
        size_t off = (size_t)R * HW + c0 + tx * 4;
        *(float4*)&Oab[off] = pr;
        __half2 h0 = __floats2half2_rn(pr.x, pr.y);
        __half2 h1 = __floats2half2_rn(pr.z, pr.w);
        *(uint2*)&Hab[off] = make_uint2(*(uint32_t*)&h0, *(uint32_t*)&h1);
        t_ba[tx * 4 + 0][r_in] = pc0;
        t_ba[tx * 4 + 1][r_in] = pc1;
        t_ba[tx * 4 + 2][r_in] = pc2;
        t_ba[tx * 4 + 3][r_in] = pc3;
    }
    __syncthreads();
#pragma unroll
    for (int it = 0; it < 4; ++it) {
        int c_in = it * 16 + ty;
        float4 p = *(const float4*)&t_ba[c_in][tx * 4];
        size_t off = (size_t)(c0 + c_in) * HW + r0 + tx * 4;
        *(float4*)&Oba[off] = p;
        __half2 h0 = __floats2half2_rn(p.x, p.y);
        __half2 h1 = __floats2half2_rn(p.z, p.w);
        *(uint2*)&Hba[off] = make_uint2(*(uint32_t*)&h0, *(uint32_t*)&h1);
    }
}

// ---------------- K7: raw -> fp16 ----------------
__global__ void tohalf_kernel(const float* __restrict__ a_raw, const float* __restrict__ b_raw) {
    const int t = blockIdx.y;
    const float* __restrict__ src = (t == 0 ? a_raw : b_raw);
    __half* __restrict__ dst = &g_raw_h[t][0][0];
    size_t i = ((size_t)blockIdx.x * 256 + threadIdx.x) * 4;
    float4 v = *(const float4*)&src[i];
    __half2* d2 = (__half2*)&dst[i];
    d2[0] = __floats2half2_rn(v.x, v.y);
    d2[1] = __floats2half2_rn(v.z, v.w);
}

// ---------------- K8: warp matmul (single-frag, no spills) ----------------
#define G_AST (128 * 72)
#define G_BST (64 * 264)
#define G_NC 64
__global__ __launch_bounds__(512, 1) void wgemm_kernel(float* __restrict__ out) {
    extern __shared__ __align__(16) __half gshm[];
    __half* As = gshm;                        // [3][128][72]
    __half* Bs = gshm + 3 * G_AST;            // [3][64][264]
    const uint32_t su = smaddr(gshm);

    const int z = blockIdx.z;
    const int dir = z >> 1, n = z & 1;
    const __half* __restrict__ A = g_raw_h[dir][n];
    const __half* __restrict__ B = g_corr_h[dir ^ 1][n];
    float* __restrict__ C = out + (size_t)4 * HW * HW
                                + (size_t)dir * 2 * CIN * HW + (size_t)n * CIN * HW;
    const int m0 = blockIdx.y * 128, n0 = blockIdx.x * 256;
    const int tid = threadIdx.x, lane = tid & 31, warp = tid >> 5;
    const int wm = warp & 3, wn = warp >> 2;
    const int r16 = lane & 15, c8 = (lane >> 4) << 3;

    float acc[2][8][4];
#pragma unroll
    for (int i = 0; i < 2; ++i)
#pragma unroll
        for (int j = 0; j < 8; ++j)
#pragma unroll
            for (int k = 0; k < 4; ++k) acc[i][j][k] = 0.f;

    auto loadst = [&](int st, int j) {
        const int k0 = j * 64;
#pragma unroll
        for (int i = 0; i < 6; ++i) {
            int idx = tid + i * 512;
            if (idx < 1024) {
                int row = idx >> 3, cp = (idx & 7) * 8;
                int gr = m0 + row;
                int ok = gr < CIN;
                cpa16u(su + (st * G_AST + row * 72 + cp) * 2,
                       &A[(size_t)(ok ? gr : 0) * HW + k0 + cp], ok ? 16 : 0);
            } else {
                int ix = idx - 1024;
                int row = ix >> 5, cp = (ix & 31) * 8;
                cpa16u(su + (3 * G_AST + st * G_BST + row * 264 + cp) * 2,
                       &B[(size_t)(k0 + row) * HW + n0 + cp], 16);
            }
        }
    };

    loadst(0, 0); CP_COMMIT();
    loadst(1, 1); CP_COMMIT();

    for (int j = 0; j < G_NC; ++j) {
        const int st = j % 3;
        CP_WAIT(1);
        __syncthreads();
        if (j + 2 < G_NC) loadst((j + 2) % 3, j + 2);
        CP_COMMIT();

#pragma unroll
        for (int ks = 0; ks < 64; ks += 16) {
            uint32_t a[2][4], b[4][4];
#pragma unroll
            for (int mi = 0; mi < 2; ++mi)
                ldsm4(a[mi], As + st * G_AST + (wm * 32 + mi * 16 + r16) * 72 + ks + c8);
#pragma unroll
            for (int nj = 0; nj < 4; ++nj)
                ldsm4t(b[nj], Bs + st * G_BST + (ks + r16) * 264 + wn * 64 + nj * 16 + c8);
#pragma unroll
            for (int mi = 0; mi < 2; ++mi)
#pragma unroll
                for (int nj = 0; nj < 4; ++nj) {
                    mma16816(acc[mi][nj * 2],     a[mi], &b[nj][0]);
                    mma16816(acc[mi][nj * 2 + 1], a[mi], &b[nj][2]);
                }
        }
        __syncthreads();
    }

#pragma unroll
    for (int mi = 0; mi < 2; ++mi)
#pragma unroll
        for (int nj = 0; nj < 8; ++nj) {
            int row = m0 + wm * 32 + mi * 16 + (lane >> 2);
            int col = n0 + wn * 64 + nj * 8 + (lane & 3) * 2;
            if (row < CIN)
                *(float2*)&C[(size_t)row * HW + col] = make_float2(acc[mi][nj][0], acc[mi][nj][1]);
            if (row + 8 < CIN)
                *(float2*)&C[(size_t)(row + 8) * HW + col] = make_float2(acc[mi][nj][2], acc[mi][nj][3]);
        }
}

// ---------------- launch ----------------
extern "C" void kernel_launch(void* const* d_in, const int* in_sizes, int n_in,
                              void* d_out, int out_size) {
    const float* fa    = (const float*)d_in[0];
    const float* fb    = (const float*)d_in[1];
    const float* a_raw = (const float*)d_in[2];
    const float* b_raw = (const float*)d_in[3];
    const float* Wa    = (const float*)d_in[4];
    const float* ba    = (const float*)d_in[5];
    const float* Wb    = (const float*)d_in[6];
    const float* bb    = (const float*)d_in[7];
    float* out = (float*)d_out;

    const int c_smem = 32 * 256 * 4 + 48 * 32 * 4 + 2 * 2 * 32 * 264 * 2 + 2 * 2 * 48 * 40 * 2; // 121856
    const int e_smem = 2 * E_STG * 2;                    // 153600
    const int g_smem = 3 * (G_AST + G_BST) * 2;          // 156672
    cudaFuncSetAttribute(conv_mma_kernel, cudaFuncAttributeMaxDynamicSharedMemorySize, c_smem);
    cudaFuncSetAttribute(energy_mma_kernel, cudaFuncAttributeMaxDynamicSharedMemorySize, e_smem);
    cudaFuncSetAttribute(wgemm_kernel, cudaFuncAttributeMaxDynamicSharedMemorySize, g_smem);

    // side stream: tohalf is independent of the conv->energy chain
    cudaStream_t s2;
    cudaStreamCreate(&s2);
    cudaEvent_t ef, ej;
    cudaEventCreateWithFlags(&ef, cudaEventDisableTiming);
    cudaEventCreateWithFlags(&ej, cudaEventDisableTiming);

    cudaEventRecord(ef, 0);
    cudaStreamWaitEvent(s2, ef, 0);
    tohalf_kernel<<<dim3(8704, 2), 256, 0, s2>>>(a_raw, b_raw);
    cudaEventRecord(ej, s2);

    conv_mma_kernel<<<dim3(16, 3, 4), 256, c_smem>>>(fa, fb, Wa, ba, Wb, bb);
    inorm_kernel<<<dim3(CMID, 2, 2), 256>>>();
    l2norm_kernel<<<dim3(HW / 256, 2, 2), 256>>>();
    energy_mma_kernel<<<dim3(16, 32, 2), 512, e_smem>>>();
    combine_kernel<<<dim3(HW / 256, 2, 2), 256>>>();
    writeout_kernel<<<dim3(64, 64, 2), 256>>>(out, out + (size_t)2 * HW * HW);
    cudaStreamWaitEvent(0, ej, 0);
    wgemm_kernel<<<dim3(16, 9, 4), 512, g_smem>>>(out);
}

// round 11
// speedup vs baseline: 1.8362x; 1.0292x over previous
#include <cuda_runtime.h>
#include <cuda_fp16.h>
#include <cstdint>
#include <cstddef>

#define HW 4096
#define CIN 1088
#define CMID 136
#define CPAD 144

// ---------------- scratch (device globals; zero-initialized, no allocs) ----------------
__device__ float  g_feat[2][2][(size_t)CMID * HW];        // [a/b][n][c*HW+p]
__device__ float  g_E[2][(size_t)HW * HW];                // energy (already *100)
__device__ __half g_corr_h[2][2][(size_t)HW * HW];        // fp16 corr, [ab/ba][n], [k][l]
__device__ __half g_raw_h[2][2][(size_t)CIN * HW];        // [a/b][n]
__device__ __half g_fh[2][2][2][(size_t)CPAD * HW];       // [a/b][hi/lo][n], [c][p]
__device__ float  g_rowM[2][HW], g_rowSinv[2][HW];
__device__ float  g_colM[2][HW], g_colSinv[2][HW];
__device__ float  g_rowPm[2][16][HW],  g_rowPs[2][16][HW];   // per-l-block row partials
__device__ float  g_colPm[2][32][HW],  g_colPs[2][32][HW];   // per-m-block col partials

// ---------------- PTX helpers ----------------
__device__ __forceinline__ uint32_t smaddr(const void* p) {
    return (uint32_t)__cvta_generic_to_shared(p);
}
__device__ __forceinline__ void ldsm4(uint32_t r[4], const void* p) {
    asm volatile("ldmatrix.sync.aligned.m8n8.x4.shared.b16 {%0,%1,%2,%3}, [%4];\n"
                 : "=r"(r[0]), "=r"(r[1]), "=r"(r[2]), "=r"(r[3]) : "r"(smaddr(p)));
}
__device__ __forceinline__ void ldsm4t(uint32_t r[4], const void* p) {
    asm volatile("ldmatrix.sync.aligned.m8n8.x4.trans.shared.b16 {%0,%1,%2,%3}, [%4];\n"
                 : "=r"(r[0]), "=r"(r[1]), "=r"(r[2]), "=r"(r[3]) : "r"(smaddr(p)));
}
__device__ __forceinline__ void mma16816(float* d, const uint32_t* a, const uint32_t* b) {
    asm volatile("mma.sync.aligned.m16n8k16.row.col.f32.f16.f16.f32 "
                 "{%0,%1,%2,%3}, {%4,%5,%6,%7}, {%8,%9}, {%0,%1,%2,%3};\n"
                 : "+f"(d[0]), "+f"(d[1]), "+f"(d[2]), "+f"(d[3])
                 : "r"(a[0]), "r"(a[1]), "r"(a[2]), "r"(a[3]), "r"(b[0]), "r"(b[1]));
}
__device__ __forceinline__ void cpa16u(uint32_t sm, const void* g, int bytes) {
    asm volatile("cp.async.cg.shared.global [%0], [%1], 16, %2;\n"
                 :: "r"(sm), "l"(g), "r"(bytes));
}
#define CP_COMMIT() asm volatile("cp.async.commit_group;\n" ::: "memory")
#define CP_WAIT(n)  asm volatile("cp.async.wait_group %0;\n" :: "n"(n) : "memory")

// ---------------- K1: 1x1 conv via split-fp16 HMMA ----------------
__global__ __launch_bounds__(256, 1) void conv_mma_kernel(
    const float* __restrict__ fa, const float* __restrict__ fb,
    const float* __restrict__ Wa, const float* __restrict__ ba,
    const float* __restrict__ Wb, const float* __restrict__ bb) {
    extern __shared__ __align__(16) char csm[];
    float*  Xf  = (float*)csm;
    float*  Wf  = Xf + 32 * 256;
    __half* Xhl = (__half*)(Wf + 48 * 32);
    __half* Whl = Xhl + 2 * 2 * 32 * 264;

    const int t = blockIdx.z >> 1, n = blockIdx.z & 1;
    const float* __restrict__ X = (t == 0 ? fa : fb) + (size_t)n * CIN * HW;
    const float* __restrict__ W = (t == 0 ? Wa : Wb);
    const float* __restrict__ bias = (t == 0 ? ba : bb);
    const int m0 = blockIdx.y * 48, n0 = blockIdx.x * 256;
    const int tid = threadIdx.x, lane = tid & 31, warp = tid >> 5;
    const int r16 = lane & 15, c8 = (lane >> 4) << 3;

    float acc[3][4][4];
#pragma unroll
    for (int i = 0; i < 3; ++i)
#pragma unroll
        for (int j = 0; j < 4; ++j)
#pragma unroll
            for (int k = 0; k < 4; ++k) acc[i][j][k] = 0.f;

    auto cpX = [&](int kc) {
#pragma unroll
        for (int i = 0; i < 8; ++i) {
            int idx = tid + i * 256;
            int row = idx >> 6, seg = (idx & 63) * 4;
            cpa16u(smaddr(&Xf[row * 256 + seg]), &X[(size_t)(kc + row) * HW + n0 + seg], 16);
        }
#pragma unroll
        for (int i = 0; i < 2; ++i) {
            int idx = tid + i * 256;
            if (idx < 384) {
                int row = idx >> 3, seg = (idx & 7) * 4;
                int o = m0 + row;
                int ok = o < CMID;
                cpa16u(smaddr(&Wf[row * 32 + seg]), &W[(size_t)(ok ? o : 0) * CIN + kc + seg], ok ? 16 : 0);
            }
        }
    };
    auto convert = [&](int s) {
        __half* Xh = Xhl + s * (2 * 32 * 264);
        __half* Xl = Xh + 32 * 264;
#pragma unroll
        for (int i = 0; i < 32; ++i) {
            int idx = tid + i * 256;
            int row = idx >> 8, col = idx & 255;
            float v = Xf[row * 256 + col];
            __half h = __float2half_rn(v);
            Xh[row * 264 + col] = h;
            Xl[row * 264 + col] = __float2half_rn(v - __half2float(h));
        }
        __half* Wh = Whl + s * (2 * 48 * 40);
        __half* Wl = Wh + 48 * 40;
#pragma unroll
        for (int i = 0; i < 6; ++i) {
            int idx = tid + i * 256;
            if (idx < 1536) {
                int row = idx >> 5, col = idx & 31;
                float v = Wf[row * 32 + col];
                __half h = __float2half_rn(v);
                Wh[row * 40 + col] = h;
                Wl[row * 40 + col] = __float2half_rn(v - __half2float(h));
            }
        }
    };

    cpX(0); CP_COMMIT();
    for (int j = 0; j < 34; ++j) {
        const int s = j & 1;
        CP_WAIT(0);
        __syncthreads();
        convert(s);
        __syncthreads();
        if (j + 1 < 34) cpX((j + 1) * 32);
        CP_COMMIT();

        const __half* Xh = Xhl + s * (2 * 32 * 264);
        const __half* Xl = Xh + 32 * 264;
        const __half* Wh = Whl + s * (2 * 48 * 40);
        const __half* Wl = Wh + 48 * 40;
#pragma unroll
        for (int ks = 0; ks < 32; ks += 16) {
            uint32_t ah[3][4], al[3][4], bh[2][4], bl[2][4];
#pragma unroll
            for (int mi = 0; mi < 3; ++mi) {
                ldsm4(ah[mi], &Wh[(mi * 16 + r16) * 40 + ks + c8]);
                ldsm4(al[mi], &Wl[(mi * 16 + r16) * 40 + ks + c8]);
            }
#pragma unroll
            for (int nj = 0; nj < 2; ++nj) {
                ldsm4t(bh[nj], &Xh[(ks + r16) * 264 + warp * 32 + nj * 16 + c8]);
                ldsm4t(bl[nj], &Xl[(ks + r16) * 264 + warp * 32 + nj * 16 + c8]);
            }
#pragma unroll
            for (int mi = 0; mi < 3; ++mi)
#pragma unroll
                for (int nj = 0; nj < 2; ++nj) {
                    mma16816(acc[mi][nj * 2],     ah[mi], &bh[nj][0]);
                    mma16816(acc[mi][nj * 2 + 1], ah[mi], &bh[nj][2]);
                    mma16816(acc[mi][nj * 2],     ah[mi], &bl[nj][0]);
                    mma16816(acc[mi][nj * 2 + 1], ah[mi], &bl[nj][2]);
                    mma16816(acc[mi][nj * 2],     al[mi], &bh[nj][0]);
                    mma16816(acc[mi][nj * 2 + 1], al[mi], &bh[nj][2]);
                }
        }
        __syncthreads();
    }

    float* __restrict__ Y = g_feat[t][n];
#pragma unroll
    for (int mi = 0; mi < 3; ++mi)
#pragma unroll
        for (int g = 0; g < 4; ++g) {
            int r0 = m0 + mi * 16 + (lane >> 2);
            int col = n0 + warp * 32 + (g >> 1) * 16 + (g & 1) * 8 + (lane & 3) * 2;
            if (r0 < CMID) {
                float bv = bias[r0];
                *(float2*)&Y[(size_t)r0 * HW + col] =
                    make_float2(acc[mi][g][0] + bv, acc[mi][g][1] + bv);
            }
            if (r0 + 8 < CMID) {
                float bv = bias[r0 + 8];
                *(float2*)&Y[(size_t)(r0 + 8) * HW + col] =
                    make_float2(acc[mi][g][2] + bv, acc[mi][g][3] + bv);
            }
        }
}

// ---------------- K2: InstanceNorm + LeakyReLU + mean-center ----------------
__global__ void inorm_kernel() {
    const int c = blockIdx.x, n = blockIdx.y, t = blockIdx.z;
    float* __restrict__ Y = &g_feat[t][n][(size_t)c * HW];
    __shared__ float sd[HW];
    __shared__ float r1[256], r2[256];
    const int tid = threadIdx.x;

    float s = 0.f, q = 0.f;
    for (int i = tid; i < HW; i += 256) { float v = Y[i]; sd[i] = v; s += v; q += v * v; }
    r1[tid] = s; r2[tid] = q; __syncthreads();
    for (int st = 128; st > 0; st >>= 1) {
        if (tid < st) { r1[tid] += r1[tid + st]; r2[tid] += r2[tid + st]; }
        __syncthreads();
    }
    const float mean = r1[0] * (1.f / HW);
    const float var  = r2[0] * (1.f / HW) - mean * mean;
    const float inv  = rsqrtf(var + 1e-5f);
    __syncthreads();

    float s2 = 0.f;
    for (int i = tid; i < HW; i += 256) {
        float v = (sd[i] - mean) * inv;
        v = (v >= 0.f) ? v : 0.2f * v;
        sd[i] = v; s2 += v;
    }
    r1[tid] = s2; __syncthreads();
    for (int st = 128; st > 0; st >>= 1) {
        if (tid < st) r1[tid] += r1[tid + st];
        __syncthreads();
    }
    const float mean2 = r1[0] * (1.f / HW);
    for (int i = tid; i < HW; i += 256) Y[i] = sd[i] - mean2;
}

// ---------------- K3: L2-normalize + split hi/lo (4 channel-groups per block) ----------------
__global__ void l2norm_kernel() {
    const int tid = threadIdx.x;
    const int px = tid & 63, cg = tid >> 6;                 // 64 positions x 4 groups
    const int p = blockIdx.x * 64 + px;
    const int n = blockIdx.y, t = blockIdx.z;
    const float* __restrict__ F = g_feat[t][n];
    __shared__ float red[4][64];

    const int cbeg = cg * 34, cend = cbeg + 34;             // 136 = 4*34
    float q = 0.f;
    for (int c = cbeg; c < cend; ++c) { float v = F[(size_t)c * HW + p]; q += v * v; }
    red[cg][px] = q;
    __syncthreads();
    const float inv = rsqrtf(red[0][px] + red[1][px] + red[2][px] + red[3][px]);

    __half* __restrict__ hi = g_fh[t][0][n];
    __half* __restrict__ lo = g_fh[t][1][n];
    for (int c = cbeg; c < cend; ++c) {
        float v = F[(size_t)c * HW + p] * inv;
        __half h = __float2half_rn(v);
        hi[(size_t)c * HW + p] = h;
        lo[(size_t)c * HW + p] = __float2half_rn(v - __half2float(h));
    }
}

// ---------------- K4: energy, merged-pass split-fp16 HMMA + fused softmax partials ----------------
#define E_A   (48 * 136)             // halves per A tile
#define E_B   (48 * 264)             // halves per B tile
#define E_STG (2 * E_A + 2 * E_B)    // halves per stage (38400)
__global__ __launch_bounds__(512, 1) void energy_mma_kernel() {
    extern __shared__ __align__(16) __half eshm[];

    const int n = blockIdx.z;
    const int m0 = blockIdx.y * 128, l0 = blockIdx.x * 256;
    const int tid = threadIdx.x, lane = tid & 31, warp = tid >> 5;
    const int wm = warp & 3, wn = warp >> 2;
    const int r16 = lane & 15, c8 = (lane >> 4) << 3;
    const int arow = (lane & 7) + ((lane >> 4) & 1) * 8;
    const int acol = ((lane >> 3) & 1) * 8;

    float acc[2][8][4];
#pragma unroll
    for (int i = 0; i < 2; ++i)
#pragma unroll
        for (int j = 0; j < 8; ++j)
#pragma unroll
            for (int k = 0; k < 4; ++k) acc[i][j][k] = 0.f;

    const uint32_t su = smaddr(eshm);
    auto loadst = [&](int st, int q) {
        const int kc = q * 48;
        const uint32_t SB = su + st * E_STG * 2;
#pragma unroll
        for (int i = 0; i < 9; ++i) {
            int idx = tid + i * 512;
            if (idx < 1536) {
                int hl = idx >= 768;
                int ix = idx - hl * 768;
                int row = ix >> 4, cp = (ix & 15) * 8;
                cpa16u(SB + (hl * E_A + row * 136 + cp) * 2,
                       &g_fh[1][hl][n][(size_t)(kc + row) * HW + m0 + cp], 16);
            } else {
                int jx = idx - 1536;
                int hl = jx >= 1536;
                int ix = jx - hl * 1536;
                int row = ix >> 5, cp = (ix & 31) * 8;
                cpa16u(SB + (2 * E_A + hl * E_B + row * 264 + cp) * 2,
                       &g_fh[0][hl][n][(size_t)(kc + row) * HW + l0 + cp], 16);
            }
        }
    };

    auto mmag2 = [&](uint32_t a[2][4], uint32_t b[4][4]) {
#pragma unroll
        for (int mi = 0; mi < 2; ++mi)
#pragma unroll
            for (int nj = 0; nj < 4; ++nj) {
                mma16816(acc[mi][nj * 2],     a[mi], &b[nj][0]);
                mma16816(acc[mi][nj * 2 + 1], a[mi], &b[nj][2]);
            }
    };

    loadst(0, 0); CP_COMMIT();
    loadst(1, 1); CP_COMMIT();
    for (int q = 0; q < 3; ++q) {
        const int st = q & 1;
        if (q == 2) CP_WAIT(0); else CP_WAIT(1);
        __syncthreads();
        const __half* Ah = eshm + st * E_STG;
        const __half* Al = Ah + E_A;
        const __half* Bh = Al + E_A;
        const __half* Bl = Bh + E_B;
#pragma unroll
        for (int ks = 0; ks < 48; ks += 16) {
            uint32_t ah[2][4], bh[4][4];
#pragma unroll
            for (int mi = 0; mi < 2; ++mi)
                ldsm4t(ah[mi], Ah + (ks + arow) * 136 + wm * 32 + mi * 16 + acol);
#pragma unroll
            for (int nj = 0; nj < 4; ++nj)
                ldsm4t(bh[nj], Bh + (ks + r16) * 264 + wn * 64 + nj * 16 + c8);
            mmag2(ah, bh);
            {
                uint32_t bl[4][4];
#pragma unroll
                for (int nj = 0; nj < 4; ++nj)
                    ldsm4t(bl[nj], Bl + (ks + r16) * 264 + wn * 64 + nj * 16 + c8);
                mmag2(ah, bl);
            }
            {
                uint32_t al[2][4];
#pragma unroll
                for (int mi = 0; mi < 2; ++mi)
                    ldsm4t(al[mi], Al + (ks + arow) * 136 + wm * 32 + mi * 16 + acol);
                mmag2(al, bh);
            }
        }
        __syncthreads();
        if (q + 2 < 3) { loadst(st, q + 2); CP_COMMIT(); }
    }

#pragma unroll
    for (int mi = 0; mi < 2; ++mi)
#pragma unroll
        for (int nj = 0; nj < 8; ++nj)
#pragma unroll
            for (int k = 0; k < 4; ++k) acc[mi][nj][k] *= 100.f;

    float* __restrict__ E = g_E[n];
#pragma unroll
    for (int mi = 0; mi < 2; ++mi)
#pragma unroll
        for (int nj = 0; nj < 8; ++nj) {
            int row = m0 + wm * 32 + mi * 16 + (lane >> 2);
            int col = l0 + wn * 64 + nj * 8 + (lane & 3) * 2;
            *(float2*)&E[(size_t)row * HW + col] = make_float2(acc[mi][nj][0], acc[mi][nj][1]);
            *(float2*)&E[(size_t)(row + 8) * HW + col] = make_float2(acc[mi][nj][2], acc[mi][nj][3]);
        }

    // ---- fused softmax partials (reuse stage smem) ----
    float* sM   = (float*)eshm;
    float* sS   = sM + 512;
    float* cMax = sS + 512;
    float* cS   = cMax + 1024;

#pragma unroll
    for (int mi = 0; mi < 2; ++mi)
#pragma unroll
        for (int h = 0; h < 2; ++h) {
            float m = -1e30f;
#pragma unroll
            for (int nj = 0; nj < 8; ++nj)
                m = fmaxf(m, fmaxf(acc[mi][nj][2 * h], acc[mi][nj][2 * h + 1]));
            m = fmaxf(m, __shfl_xor_sync(0xFFFFFFFFu, m, 1));
            m = fmaxf(m, __shfl_xor_sync(0xFFFFFFFFu, m, 2));
            float s = 0.f;
#pragma unroll
            for (int nj = 0; nj < 8; ++nj)
                s += __expf(acc[mi][nj][2 * h] - m) + __expf(acc[mi][nj][2 * h + 1] - m);
            s += __shfl_xor_sync(0xFFFFFFFFu, s, 1);
            s += __shfl_xor_sync(0xFFFFFFFFu, s, 2);
            if ((lane & 3) == 0) {
                int r = wm * 32 + mi * 16 + (lane >> 2) + 8 * h;
                sM[wn * 128 + r] = m;
                sS[wn * 128 + r] = s;
            }
        }
    float m16[8][2];
#pragma unroll
    for (int nj = 0; nj < 8; ++nj)
#pragma unroll
        for (int c = 0; c < 2; ++c) {
            float m = fmaxf(fmaxf(acc[0][nj][c], acc[0][nj][2 + c]),
                            fmaxf(acc[1][nj][c], acc[1][nj][2 + c]));
            m = fmaxf(m, __shfl_xor_sync(0xFFFFFFFFu, m, 4));
            m = fmaxf(m, __shfl_xor_sync(0xFFFFFFFFu, m, 8));
            m = fmaxf(m, __shfl_xor_sync(0xFFFFFFFFu, m, 16));
            m16[nj][c] = m;
        }
    if ((lane >> 2) == 0) {
#pragma unroll
        for (int nj = 0; nj < 8; ++nj)
#pragma unroll
            for (int c = 0; c < 2; ++c)
                cMax[wm * 256 + wn * 64 + nj * 8 + (lane & 3) * 2 + c] = m16[nj][c];
    }
    __syncthreads();

    if (tid < 128) {
        float M = sM[tid], S = sS[tid];
#pragma unroll
        for (int w = 1; w < 4; ++w) {
            float m2 = sM[w * 128 + tid], s2 = sS[w * 128 + tid];
            float M2 = fmaxf(M, m2);
            S = S * __expf(M - M2) + s2 * __expf(m2 - M2);
            M = M2;
        }
        g_rowPm[n][blockIdx.x][m0 + tid] = M;
        g_rowPs[n][blockIdx.x][m0 + tid] = S;
    }
    if (tid < 256) {
        float M = fmaxf(fmaxf(cMax[tid], cMax[256 + tid]),
                        fmaxf(cMax[512 + tid], cMax[768 + tid]));
        cMax[tid] = M;
    }
    __syncthreads();

    float s16[8][2];
#pragma unroll
    for (int nj = 0; nj < 8; ++nj)
#pragma unroll
        for (int c = 0; c < 2; ++c) {
            float bm = cMax[wn * 64 + nj * 8 + (lane & 3) * 2 + c];
            float s = __expf(acc[0][nj][c] - bm) + __expf(acc[0][nj][2 + c] - bm)
                    + __expf(acc[1][nj][c] - bm) + __expf(acc[1][nj][2 + c] - bm);
            s += __shfl_xor_sync(0xFFFFFFFFu, s, 4);
            s += __shfl_xor_sync(0xFFFFFFFFu, s, 8);
            s += __shfl_xor_sync(0xFFFFFFFFu, s, 16);
            s16[nj][c] = s;
        }
    if ((lane >> 2) == 0) {
#pragma unroll
        for (int nj = 0; nj < 8; ++nj)
#pragma unroll
            for (int c = 0; c < 2; ++c)
                cS[wm * 256 + wn * 64 + nj * 8 + (lane & 3) * 2 + c] = s16[nj][c];
    }
    __syncthreads();
    if (tid < 256) {
        float S = cS[tid] + cS[256 + tid] + cS[512 + tid] + cS[768 + tid];
        g_colPm[n][blockIdx.y][l0 + tid] = cMax[tid];
        g_colPs[n][blockIdx.y][l0 + tid] = S;
    }
}

// ---------------- K5: combine partial stats (row z=0, col z=1) ----------------
__global__ void combine_kernel() {
    const int i = blockIdx.x * 256 + threadIdx.x;
    const int n = blockIdx.y;
    float M = -1e30f, S = 0.f;
    if (blockIdx.z == 0) {
#pragma unroll
        for (int b = 0; b < 16; ++b) {
            float m = g_rowPm[n][b][i], s = g_rowPs[n][b][i];
            float M2 = fmaxf(M, m);
            S = S * __expf(M - M2) + s * __expf(m - M2);
            M = M2;
        }
        g_rowM[n][i] = M;
        g_rowSinv[n][i] = 1.0f / S;
    } else {
#pragma unroll
        for (int b = 0; b < 32; ++b) {
            float m = g_colPm[n][b][i], s = g_colPs[n][b][i];
            float M2 = fmaxf(M, m);
            S = S * __expf(M - M2) + s * __expf(m - M2);
            M = M2;
        }
        g_colM[n][i] = M;
        g_colSinv[n][i] = 1.0f / S;
    }
}

// ---------------- K6: softmax writeout, vectorized ----------------
__global__ void writeout_kernel(float* __restrict__ out_ab, float* __restrict__ out_ba) {
    const int c0 = blockIdx.x * 64, r0 = blockIdx.y * 64, n = blockIdx.z;
    const int tid = threadIdx.x;
    const int tx = tid & 15, ty = tid >> 4;
    const float* __restrict__ E = g_E[n];
    __half* __restrict__ Hab = g_corr_h[0][n];
    __half* __restrict__ Hba = g_corr_h[1][n];
    float* __restrict__ Oab = out_ab + (size_t)n * HW * HW;
    float* __restrict__ Oba = out_ba + (size_t)n * HW * HW;

    __shared__ float t_ba[64][68];
    __shared__ float rm_s[64], rsi_s[64];
    if (tid < 64)       rm_s[tid]       = g_rowM[n][r0 + tid];
    else if (tid < 128) rsi_s[tid - 64] = g_rowSinv[n][r0 + tid - 64];
    const float4 cm4  = *(const float4*)&g_colM[n][c0 + tx * 4];
    const float4 csi4 = *(const float4*)&g_colSinv[n][c0 + tx * 4];
    __syncthreads();

#pragma unroll
    for (int it = 0; it < 4; ++it) {
        int r_in = it * 16 + ty;
        int R = r0 + r_in;
        float4 e = *(const float4*)&E[(size_t)R * HW + c0 + tx * 4];
        float rm = rm_s[r_in], rsi = rsi_s[r_in];
        float4 pr = make_float4(__expf(e.x - rm) * rsi, __expf(e.y - rm) * rsi,
                                __expf(e.z - rm) * rsi, __expf(e.w - rm) * rsi);
        float pc0 = __expf(e.x - cm4.x) * csi4.x;
        float pc1 = __expf(e.y - cm4.y) * csi4.y;
        float pc2 = __expf(e.z - cm4.z) * csi4.z;
        float pc3 = __expf(e.w - cm4.w) * csi4.w;
        size_t off = (size_t)R * HW + c0 + tx * 4;
        *(float4*)&Oab[off] = pr;
        __half2 h0 = __floats2half2_rn(pr.x, pr.y);
        __half2 h1 = __floats2half2_rn(pr.z, pr.w);
        *(uint2*)&Hab[off] = make_uint2(*(uint32_t*)&h0, *(uint32_t*)&h1);
        t_ba[tx * 4 + 0][r_in] = pc0;
        t_ba[tx * 4 + 1][r_in] = pc1;
        t_ba[tx * 4 + 2][r_in] = pc2;
        t_ba[tx * 4 + 3][r_in] = pc3;
    }
    __syncthreads();
#pragma unroll
    for (int it = 0; it < 4; ++it) {
        int c_in = it * 16 + ty;
        float4 p = *(const float4*)&t_ba[c_in][tx * 4];
        size_t off = (size_t)(c0 + c_in) * HW + r0 + tx * 4;
        *(float4*)&Oba[off] = p;
        __half2 h0 = __floats2half2_rn(p.x, p.y);
        __half2 h1 = __floats2half2_rn(p.z, p.w);
        *(uint2*)&Hba[off] = make_uint2(*(uint32_t*)&h0, *(uint32_t*)&h1);
    }
}

// ---------------- K7: raw -> fp16 ----------------
__global__ void tohalf_kernel(const float* __restrict__ a_raw, const float* __restrict__ b_raw) {
    const int t = blockIdx.y;
    const float* __restrict__ src = (t == 0 ? a_raw : b_raw);
    __half* __restrict__ dst = &g_raw_h[t][0][0];
    size_t i = ((size_t)blockIdx.x * 256 + threadIdx.x) * 4;
    float4 v = *(const float4*)&src[i];
    __half2* d2 = (__half2*)&dst[i];
    d2[0] = __floats2half2_rn(v.x, v.y);
    d2[1] = __floats2half2_rn(v.z, v.w);
}

// ---------------- K8: warp matmul, 128x128 tile, 256 thr, 2 CTAs/SM ----------------
#define G2_AST (128 * 72)
#define G2_BST (64 * 136)
#define G2_NC 64
__global__ __launch_bounds__(256, 2) void wgemm_kernel(float* __restrict__ out) {
    extern __shared__ __align__(16) __half gshm[];
    __half* As = gshm;                        // [2][128][72]
    __half* Bs = gshm + 2 * G2_AST;           // [2][64][136]
    const uint32_t su = smaddr(gshm);

    const int z = blockIdx.z;
    const int dir = z >> 1, n = z & 1;
    const __half* __restrict__ A = g_raw_h[dir][n];
    const __half* __restrict__ B = g_corr_h[dir ^ 1][n];
    float* __restrict__ C = out + (size_t)4 * HW * HW
                                + (size_t)dir * 2 * CIN * HW + (size_t)n * CIN * HW;
    const int m0 = blockIdx.y * 128, n0 = blockIdx.x * 128;
    const int tid = threadIdx.x, lane = tid & 31, warp = tid >> 5;
    const int wm = warp & 3, wn = warp >> 2;
    const int r16 = lane & 15, c8 = (lane >> 4) << 3;

    float acc[2][8][4];
#pragma unroll
    for (int i = 0; i < 2; ++i)
#pragma unroll
        for (int j = 0; j < 8; ++j)
#pragma unroll
            for (int k = 0; k < 4; ++k) acc[i][j][k] = 0.f;

    auto loadst = [&](int st, int j) {
        const int k0 = j * 64;
#pragma unroll
        for (int i = 0; i < 8; ++i) {
            int idx = tid + i * 256;
            if (idx < 1024) {
                int row = idx >> 3, cp = (idx & 7) * 8;
                int gr = m0 + row;
                int ok = gr < CIN;
                cpa16u(su + (st * G2_AST + row * 72 + cp) * 2,
                       &A[(size_t)(ok ? gr : 0) * HW + k0 + cp], ok ? 16 : 0);
            } else {
                int ix = idx - 1024;
                int row = ix >> 4, cp = (ix & 15) * 8;
                cpa16u(su + (2 * G2_AST + st * G2_BST + row * 136 + cp) * 2,
                       &B[(size_t)(k0 + row) * HW + n0 + cp], 16);
            }
        }
    };

    loadst(0, 0); CP_COMMIT();

    for (int j = 0; j < G2_NC; ++j) {
        const int st = j & 1;
        CP_WAIT(0);
        __syncthreads();
        if (j + 1 < G2_NC) { loadst(st ^ 1, j + 1); CP_COMMIT(); }

#pragma unroll
        for (int ks = 0; ks < 64; ks += 16) {
            uint32_t a[2][4], b[4][4];
#pragma unroll
            for (int mi = 0; mi < 2; ++mi)
                ldsm4(a[mi], As + st * G2_AST + (wm * 32 + mi * 16 + r16) * 72 + ks + c8);
#pragma unroll
            for (int nj = 0; nj < 4; ++nj)
                ldsm4t(b[nj], Bs + st * G2_BST + (ks + r16) * 136 + wn * 64 + nj * 16 + c8);
#pragma unroll
            for (int mi = 0; mi < 2; ++mi)
#pragma unroll
                for (int nj = 0; nj < 4; ++nj) {
                    mma16816(acc[mi][nj * 2],     a[mi], &b[nj][0]);
                    mma16816(acc[mi][nj * 2 + 1], a[mi], &b[nj][2]);
                }
        }
        __syncthreads();
    }

#pragma unroll
    for (int mi = 0; mi < 2; ++mi)
#pragma unroll
        for (int nj = 0; nj < 8; ++nj) {
            int row = m0 + wm * 32 + mi * 16 + (lane >> 2);
            int col = n0 + wn * 64 + nj * 8 + (lane & 3) * 2;
            if (row < CIN)
                *(float2*)&C[(size_t)row * HW + col] = make_float2(acc[mi][nj][0], acc[mi][nj][1]);
            if (row + 8 < CIN)
                *(float2*)&C[(size_t)(row + 8) * HW + col] = make_float2(acc[mi][nj][2], acc[mi][nj][3]);
        }
}

// ---------------- launch ----------------
extern "C" void kernel_launch(void* const* d_in, const int* in_sizes, int n_in,
                              void* d_out, int out_size) {
    const float* fa    = (const float*)d_in[0];
    const float* fb    = (const float*)d_in[1];
    const float* a_raw = (const float*)d_in[2];
    const float* b_raw = (const float*)d_in[3];
    const float* Wa    = (const float*)d_in[4];
    const float* ba    = (const float*)d_in[5];
    const float* Wb    = (const float*)d_in[6];
    const float* bb    = (const float*)d_in[7];
    float* out = (float*)d_out;

    const int c_smem = 32 * 256 * 4 + 48 * 32 * 4 + 2 * 2 * 32 * 264 * 2 + 2 * 2 * 48 * 40 * 2; // 121856
    const int e_smem = 2 * E_STG * 2;                    // 153600
    const int g_smem = 2 * (G2_AST + G2_BST) * 2;        // 71680
    cudaFuncSetAttribute(conv_mma_kernel, cudaFuncAttributeMaxDynamicSharedMemorySize, c_smem);
    cudaFuncSetAttribute(energy_mma_kernel, cudaFuncAttributeMaxDynamicSharedMemorySize, e_smem);
    cudaFuncSetAttribute(wgemm_kernel, cudaFuncAttributeMaxDynamicSharedMemorySize, g_smem);

    // side stream: tohalf is independent of the conv->energy chain
    cudaStream_t s2;
    cudaStreamCreate(&s2);
    cudaEvent_t ef, ej;
    cudaEventCreateWithFlags(&ef, cudaEventDisableTiming);
    cudaEventCreateWithFlags(&ej, cudaEventDisableTiming);

    cudaEventRecord(ef, 0);
    cudaStreamWaitEvent(s2, ef, 0);
    tohalf_kernel<<<dim3(8704, 2), 256, 0, s2>>>(a_raw, b_raw);
    cudaEventRecord(ej, s2);

    conv_mma_kernel<<<dim3(16, 3, 4), 256, c_smem>>>(fa, fb, Wa, ba, Wb, bb);
    inorm_kernel<<<dim3(CMID, 2, 2), 256>>>();
    l2norm_kernel<<<dim3(HW / 64, 2, 2), 256>>>();
    energy_mma_kernel<<<dim3(16, 32, 2), 512, e_smem>>>();
    combine_kernel<<<dim3(HW / 256, 2, 2), 256>>>();
    writeout_kernel<<<dim3(64, 64, 2), 256>>>(out, out + (size_t)2 * HW * HW);
    cudaStreamWaitEvent(0, ej, 0);
    wgemm_kernel<<<dim3(32, 9, 4), 256, g_smem>>>(out);
}

// round 12
// speedup vs baseline: 1.9456x; 1.0596x over previous
#include <cuda_runtime.h>
#include <cuda_fp16.h>
#include <cstdint>
#include <cstddef>

#define HW 4096
#define CIN 1088
#define CMID 136
#define CPAD 144

// ---------------- scratch (device globals; zero-initialized, no allocs) ----------------
__device__ float  g_feat[2][2][(size_t)CMID * HW];        // [a/b][n][c*HW+p]
__device__ float  g_E[2][(size_t)HW * HW];                // energy (already *100)
__device__ __half g_corr_h[2][2][(size_t)HW * HW];        // fp16 corr, [ab/ba][n], [k][l]
__device__ __half g_raw_h[2][2][(size_t)CIN * HW];        // [a/b][n]
__device__ __half g_fh[2][2][2][(size_t)CPAD * HW];       // [a/b][hi/lo][n], [c][p]
__device__ float  g_rowM[2][HW], g_rowSinv[2][HW];
__device__ float  g_colM[2][HW], g_colSinv[2][HW];
__device__ float  g_rowPm[2][16][HW],  g_rowPs[2][16][HW];   // per-l-block row partials
__device__ float  g_colPm[2][32][HW],  g_colPs[2][32][HW];   // per-m-block col partials

// ---------------- PTX helpers ----------------
__device__ __forceinline__ uint32_t smaddr(const void* p) {
    return (uint32_t)__cvta_generic_to_shared(p);
}
__device__ __forceinline__ void ldsm4(uint32_t r[4], const void* p) {
    asm volatile("ldmatrix.sync.aligned.m8n8.x4.shared.b16 {%0,%1,%2,%3}, [%4];\n"
                 : "=r"(r[0]), "=r"(r[1]), "=r"(r[2]), "=r"(r[3]) : "r"(smaddr(p)));
}
__device__ __forceinline__ void ldsm4t(uint32_t r[4], const void* p) {
    asm volatile("ldmatrix.sync.aligned.m8n8.x4.trans.shared.b16 {%0,%1,%2,%3}, [%4];\n"
                 : "=r"(r[0]), "=r"(r[1]), "=r"(r[2]), "=r"(r[3]) : "r"(smaddr(p)));
}
__device__ __forceinline__ void mma16816(float* d, const uint32_t* a, const uint32_t* b) {
    asm volatile("mma.sync.aligned.m16n8k16.row.col.f32.f16.f16.f32 "
                 "{%0,%1,%2,%3}, {%4,%5,%6,%7}, {%8,%9}, {%0,%1,%2,%3};\n"
                 : "+f"(d[0]), "+f"(d[1]), "+f"(d[2]), "+f"(d[3])
                 : "r"(a[0]), "r"(a[1]), "r"(a[2]), "r"(a[3]), "r"(b[0]), "r"(b[1]));
}
__device__ __forceinline__ void cpa16u(uint32_t sm, const void* g, int bytes) {
    asm volatile("cp.async.cg.shared.global [%0], [%1], 16, %2;\n"
                 :: "r"(sm), "l"(g), "r"(bytes));
}
#define CP_COMMIT() asm volatile("cp.async.commit_group;\n" ::: "memory")
#define CP_WAIT(n)  asm volatile("cp.async.wait_group %0;\n" :: "n"(n) : "memory")

// ---------------- K1: 1x1 conv via split-fp16 HMMA (single fp16 buffer, 2 CTAs/SM) ----------------
__global__ __launch_bounds__(256, 2) void conv_mma_kernel(
    const float* __restrict__ fa, const float* __restrict__ fb,
    const float* __restrict__ Wa, const float* __restrict__ ba,
    const float* __restrict__ Wb, const float* __restrict__ bb) {
    extern __shared__ __align__(16) char csm[];
    float*  Xf  = (float*)csm;                      // [32][256]
    float*  Wf  = Xf + 32 * 256;                    // [48][32]
    __half* Xhl = (__half*)(Wf + 48 * 32);          // [2 hl][32][264]  (single stage)
    __half* Whl = Xhl + 2 * 32 * 264;               // [2 hl][48][40]

    const int t = blockIdx.z >> 1, n = blockIdx.z & 1;
    const float* __restrict__ X = (t == 0 ? fa : fb) + (size_t)n * CIN * HW;
    const float* __restrict__ W = (t == 0 ? Wa : Wb);
    const float* __restrict__ bias = (t == 0 ? ba : bb);
    const int m0 = blockIdx.y * 48, n0 = blockIdx.x * 256;
    const int tid = threadIdx.x, lane = tid & 31, warp = tid >> 5;
    const int r16 = lane & 15, c8 = (lane >> 4) << 3;

    float acc[3][4][4];
#pragma unroll
    for (int i = 0; i < 3; ++i)
#pragma unroll
        for (int j = 0; j < 4; ++j)
#pragma unroll
            for (int k = 0; k < 4; ++k) acc[i][j][k] = 0.f;

    auto cpX = [&](int kc) {
#pragma unroll
        for (int i = 0; i < 8; ++i) {
            int idx = tid + i * 256;
            int row = idx >> 6, seg = (idx & 63) * 4;
            cpa16u(smaddr(&Xf[row * 256 + seg]), &X[(size_t)(kc + row) * HW + n0 + seg], 16);
        }
#pragma unroll
        for (int i = 0; i < 2; ++i) {
            int idx = tid + i * 256;
            if (idx < 384) {
                int row = idx >> 3, seg = (idx & 7) * 4;
                int o = m0 + row;
                int ok = o < CMID;
                cpa16u(smaddr(&Wf[row * 32 + seg]), &W[(size_t)(ok ? o : 0) * CIN + kc + seg], ok ? 16 : 0);
            }
        }
    };
    auto convert = [&]() {
        __half* Xh = Xhl;
        __half* Xl = Xh + 32 * 264;
#pragma unroll
        for (int i = 0; i < 32; ++i) {
            int idx = tid + i * 256;
            int row = idx >> 8, col = idx & 255;
            float v = Xf[row * 256 + col];
            __half h = __float2half_rn(v);
            Xh[row * 264 + col] = h;
            Xl[row * 264 + col] = __float2half_rn(v - __half2float(h));
        }
        __half* Wh = Whl;
        __half* Wl = Wh + 48 * 40;
#pragma unroll
        for (int i = 0; i < 6; ++i) {
            int idx = tid + i * 256;
            if (idx < 1536) {
                int row = idx >> 5, col = idx & 31;
                float v = Wf[row * 32 + col];
                __half h = __float2half_rn(v);
                Wh[row * 40 + col] = h;
                Wl[row * 40 + col] = __float2half_rn(v - __half2float(h));
            }
        }
    };

    cpX(0); CP_COMMIT();
    for (int j = 0; j < 34; ++j) {
        CP_WAIT(0);
        __syncthreads();
        convert();
        __syncthreads();
        if (j + 1 < 34) cpX((j + 1) * 32);
        CP_COMMIT();

        const __half* Xh = Xhl;
        const __half* Xl = Xh + 32 * 264;
        const __half* Wh = Whl;
        const __half* Wl = Wh + 48 * 40;
#pragma unroll
        for (int ks = 0; ks < 32; ks += 16) {
            uint32_t ah[3][4], al[3][4], bh[2][4], bl[2][4];
#pragma unroll
            for (int mi = 0; mi < 3; ++mi) {
                ldsm4(ah[mi], &Wh[(mi * 16 + r16) * 40 + ks + c8]);
                ldsm4(al[mi], &Wl[(mi * 16 + r16) * 40 + ks + c8]);
            }
#pragma unroll
            for (int nj = 0; nj < 2; ++nj) {
                ldsm4t(bh[nj], &Xh[(ks + r16) * 264 + warp * 32 + nj * 16 + c8]);
                ldsm4t(bl[nj], &Xl[(ks + r16) * 264 + warp * 32 + nj * 16 + c8]);
            }
#pragma unroll
            for (int mi = 0; mi < 3; ++mi)
#pragma unroll
                for (int nj = 0; nj < 2; ++nj) {
                    mma16816(acc[mi][nj * 2],     ah[mi], &bh[nj][0]);
                    mma16816(acc[mi][nj * 2 + 1], ah[mi], &bh[nj][2]);
                    mma16816(acc[mi][nj * 2],     ah[mi], &bl[nj][0]);
                    mma16816(acc[mi][nj * 2 + 1], ah[mi], &bl[nj][2]);
                    mma16816(acc[mi][nj * 2],     al[mi], &bh[nj][0]);
                    mma16816(acc[mi][nj * 2 + 1], al[mi], &bh[nj][2]);
                }
        }
        __syncthreads();
    }

    float* __restrict__ Y = g_feat[t][n];
#pragma unroll
    for (int mi = 0; mi < 3; ++mi)
#pragma unroll
        for (int g = 0; g < 4; ++g) {
            int r0 = m0 + mi * 16 + (lane >> 2);
            int col = n0 + warp * 32 + (g >> 1) * 16 + (g & 1) * 8 + (lane & 3) * 2;
            if (r0 < CMID) {
                float bv = bias[r0];
                *(float2*)&Y[(size_t)r0 * HW + col] =
                    make_float2(acc[mi][g][0] + bv, acc[mi][g][1] + bv);
            }
            if (r0 + 8 < CMID) {
                float bv = bias[r0 + 8];
                *(float2*)&Y[(size_t)(r0 + 8) * HW + col] =
                    make_float2(acc[mi][g][2] + bv, acc[mi][g][3] + bv);
            }
        }
}

// ---------------- K2: InstanceNorm + LeakyReLU + mean-center ----------------
__global__ void inorm_kernel() {
    const int c = blockIdx.x, n = blockIdx.y, t = blockIdx.z;
    float* __restrict__ Y = &g_feat[t][n][(size_t)c * HW];
    __shared__ float sd[HW];
    __shared__ float r1[256], r2[256];
    const int tid = threadIdx.x;

    float s = 0.f, q = 0.f;
    for (int i = tid; i < HW; i += 256) { float v = Y[i]; sd[i] = v; s += v; q += v * v; }
    r1[tid] = s; r2[tid] = q; __syncthreads();
    for (int st = 128; st > 0; st >>= 1) {
        if (tid < st) { r1[tid] += r1[tid + st]; r2[tid] += r2[tid + st]; }
        __syncthreads();
    }
    const float mean = r1[0] * (1.f / HW);
    const float var  = r2[0] * (1.f / HW) - mean * mean;
    const float inv  = rsqrtf(var + 1e-5f);
    __syncthreads();

    float s2 = 0.f;
    for (int i = tid; i < HW; i += 256) {
        float v = (sd[i] - mean) * inv;
        v = (v >= 0.f) ? v : 0.2f * v;
        sd[i] = v; s2 += v;
    }
    r1[tid] = s2; __syncthreads();
    for (int st = 128; st > 0; st >>= 1) {
        if (tid < st) r1[tid] += r1[tid + st];
        __syncthreads();
    }
    const float mean2 = r1[0] * (1.f / HW);
    for (int i = tid; i < HW; i += 256) Y[i] = sd[i] - mean2;
}

// ---------------- K3: L2-normalize + split hi/lo (4 channel-groups per block) ----------------
__global__ void l2norm_kernel() {
    const int tid = threadIdx.x;
    const int px = tid & 63, cg = tid >> 6;
    const int p = blockIdx.x * 64 + px;
    const int n = blockIdx.y, t = blockIdx.z;
    const float* __restrict__ F = g_feat[t][n];
    __shared__ float red[4][64];

    const int cbeg = cg * 34, cend = cbeg + 34;
    float q = 0.f;
    for (int c = cbeg; c < cend; ++c) { float v = F[(size_t)c * HW + p]; q += v * v; }
    red[cg][px] = q;
    __syncthreads();
    const float inv = rsqrtf(red[0][px] + red[1][px] + red[2][px] + red[3][px]);

    __half* __restrict__ hi = g_fh[t][0][n];
    __half* __restrict__ lo = g_fh[t][1][n];
    for (int c = cbeg; c < cend; ++c) {
        float v = F[(size_t)c * HW + p] * inv;
        __half h = __float2half_rn(v);
        hi[(size_t)c * HW + p] = h;
        lo[(size_t)c * HW + p] = __float2half_rn(v - __half2float(h));
    }
}

// ---------------- K4: energy, merged-pass split-fp16 HMMA + fused softmax partials ----------------
#define E_A   (48 * 136)
#define E_B   (48 * 264)
#define E_STG (2 * E_A + 2 * E_B)
__global__ __launch_bounds__(512, 1) void energy_mma_kernel() {
    extern __shared__ __align__(16) __half eshm[];

    const int n = blockIdx.z;
    const int m0 = blockIdx.y * 128, l0 = blockIdx.x * 256;
    const int tid = threadIdx.x, lane = tid & 31, warp = tid >> 5;
    const int wm = warp & 3, wn = warp >> 2;
    const int r16 = lane & 15, c8 = (lane >> 4) << 3;
    const int arow = (lane & 7) + ((lane >> 4) & 1) * 8;
    const int acol = ((lane >> 3) & 1) * 8;

    float acc[2][8][4];
#pragma unroll
    for (int i = 0; i < 2; ++i)
#pragma unroll
        for (int j = 0; j < 8; ++j)
#pragma unroll
            for (int k = 0; k < 4; ++k) acc[i][j][k] = 0.f;

    const uint32_t su = smaddr(eshm);
    auto loadst = [&](int st, int q) {
        const int kc = q * 48;
        const uint32_t SB = su + st * E_STG * 2;
#pragma unroll
        for (int i = 0; i < 9; ++i) {
            int idx = tid + i * 512;
            if (idx < 1536) {
                int hl = idx >= 768;
                int ix = idx - hl * 768;
                int row = ix >> 4, cp = (ix & 15) * 8;
                cpa16u(SB + (hl * E_A + row * 136 + cp) * 2,
                       &g_fh[1][hl][n][(size_t)(kc + row) * HW + m0 + cp], 16);
            } else {
                int jx = idx - 1536;
                int hl = jx >= 1536;
                int ix = jx - hl * 1536;
                int row = ix >> 5, cp = (ix & 31) * 8;
                cpa16u(SB + (2 * E_A + hl * E_B + row * 264 + cp) * 2,
                       &g_fh[0][hl][n][(size_t)(kc + row) * HW + l0 + cp], 16);
            }
        }
    };

    auto mmag2 = [&](uint32_t a[2][4], uint32_t b[4][4]) {
#pragma unroll
        for (int mi = 0; mi < 2; ++mi)
#pragma unroll
            for (int nj = 0; nj < 4; ++nj) {
                mma16816(acc[mi][nj * 2],     a[mi], &b[nj][0]);
                mma16816(acc[mi][nj * 2 + 1], a[mi], &b[nj][2]);
            }
    };

    loadst(0, 0); CP_COMMIT();
    loadst(1, 1); CP_COMMIT();
    for (int q = 0; q < 3; ++q) {
        const int st = q & 1;
        if (q == 2) CP_WAIT(0); else CP_WAIT(1);
        __syncthreads();
        const __half* Ah = eshm + st * E_STG;
        const __half* Al = Ah + E_A;
        const __half* Bh = Al + E_A;
        const __half* Bl = Bh + E_B;
#pragma unroll
        for (int ks = 0; ks < 48; ks += 16) {
            uint32_t ah[2][4], bh[4][4];
#pragma unroll
            for (int mi = 0; mi < 2; ++mi)
                ldsm4t(ah[mi], Ah + (ks + arow) * 136 + wm * 32 + mi * 16 + acol);
#pragma unroll
            for (int nj = 0; nj < 4; ++nj)
                ldsm4t(bh[nj], Bh + (ks + r16) * 264 + wn * 64 + nj * 16 + c8);
            mmag2(ah, bh);
            {
                uint32_t bl[4][4];
#pragma unroll
                for (int nj = 0; nj < 4; ++nj)
                    ldsm4t(bl[nj], Bl + (ks + r16) * 264 + wn * 64 + nj * 16 + c8);
                mmag2(ah, bl);
            }
            {
                uint32_t al[2][4];
#pragma unroll
                for (int mi = 0; mi < 2; ++mi)
                    ldsm4t(al[mi], Al + (ks + arow) * 136 + wm * 32 + mi * 16 + acol);
                mmag2(al, bh);
            }
        }
        __syncthreads();
        if (q + 2 < 3) { loadst(st, q + 2); CP_COMMIT(); }
    }

#pragma unroll
    for (int mi = 0; mi < 2; ++mi)
#pragma unroll
        for (int nj = 0; nj < 8; ++nj)
#pragma unroll
            for (int k = 0; k < 4; ++k) acc[mi][nj][k] *= 100.f;

    float* __restrict__ E = g_E[n];
#pragma unroll
    for (int mi = 0; mi < 2; ++mi)
#pragma unroll
        for (int nj = 0; nj < 8; ++nj) {
            int row = m0 + wm * 32 + mi * 16 + (lane >> 2);
            int col = l0 + wn * 64 + nj * 8 + (lane & 3) * 2;
            *(float2*)&E[(size_t)row * HW + col] = make_float2(acc[mi][nj][0], acc[mi][nj][1]);
            *(float2*)&E[(size_t)(row + 8) * HW + col] = make_float2(acc[mi][nj][2], acc[mi][nj][3]);
        }

    // ---- fused softmax partials (reuse stage smem) ----
    float* sM   = (float*)eshm;
    float* sS   = sM + 512;
    float* cMax = sS + 512;
    float* cS   = cMax + 1024;

#pragma unroll
    for (int mi = 0; mi < 2; ++mi)
#pragma unroll
        for (int h = 0; h < 2; ++h) {
            float m = -1e30f;
#pragma unroll
            for (int nj = 0; nj < 8; ++nj)
                m = fmaxf(m, fmaxf(acc[mi][nj][2 * h], acc[mi][nj][2 * h + 1]));
            m = fmaxf(m, __shfl_xor_sync(0xFFFFFFFFu, m, 1));
            m = fmaxf(m, __shfl_xor_sync(0xFFFFFFFFu, m, 2));
            float s = 0.f;
#pragma unroll
            for (int nj = 0; nj < 8; ++nj)
                s += __expf(acc[mi][nj][2 * h] - m) + __expf(acc[mi][nj][2 * h + 1] - m);
            s += __shfl_xor_sync(0xFFFFFFFFu, s, 1);
            s += __shfl_xor_sync(0xFFFFFFFFu, s, 2);
            if ((lane & 3) == 0) {
                int r = wm * 32 + mi * 16 + (lane >> 2) + 8 * h;
                sM[wn * 128 + r] = m;
                sS[wn * 128 + r] = s;
            }
        }
    float m16[8][2];
#pragma unroll
    for (int nj = 0; nj < 8; ++nj)
#pragma unroll
        for (int c = 0; c < 2; ++c) {
            float m = fmaxf(fmaxf(acc[0][nj][c], acc[0][nj][2 + c]),
                            fmaxf(acc[1][nj][c], acc[1][nj][2 + c]));
            m = fmaxf(m, __shfl_xor_sync(0xFFFFFFFFu, m, 4));
            m = fmaxf(m, __shfl_xor_sync(0xFFFFFFFFu, m, 8));
            m = fmaxf(m, __shfl_xor_sync(0xFFFFFFFFu, m, 16));
            m16[nj][c] = m;
        }
    if ((lane >> 2) == 0) {
#pragma unroll
        for (int nj = 0; nj < 8; ++nj)
#pragma unroll
            for (int c = 0; c < 2; ++c)
                cMax[wm * 256 + wn * 64 + nj * 8 + (lane & 3) * 2 + c] = m16[nj][c];
    }
    __syncthreads();

    if (tid < 128) {
        float M = sM[tid], S = sS[tid];
#pragma unroll
        for (int w = 1; w < 4; ++w) {
            float m2 = sM[w * 128 + tid], s2 = sS[w * 128 + tid];
            float M2 = fmaxf(M, m2);
            S = S * __expf(M - M2) + s2 * __expf(m2 - M2);
            M = M2;
        }
        g_rowPm[n][blockIdx.x][m0 + tid] = M;
        g_rowPs[n][blockIdx.x][m0 + tid] = S;
    }
    if (tid < 256) {
        float M = fmaxf(fmaxf(cMax[tid], cMax[256 + tid]),
                        fmaxf(cMax[512 + tid], cMax[768 + tid]));
        cMax[tid] = M;
    }
    __syncthreads();

    float s16[8][2];
#pragma unroll
    for (int nj = 0; nj < 8; ++nj)
#pragma unroll
        for (int c = 0; c < 2; ++c) {
            float bm = cMax[wn * 64 + nj * 8 + (lane & 3) * 2 + c];
            float s = __expf(acc[0][nj][c] - bm) + __expf(acc[0][nj][2 + c] - bm)
                    + __expf(acc[1][nj][c] - bm) + __expf(acc[1][nj][2 + c] - bm);
            s += __shfl_xor_sync(0xFFFFFFFFu, s, 4);
            s += __shfl_xor_sync(0xFFFFFFFFu, s, 8);
            s += __shfl_xor_sync(0xFFFFFFFFu, s, 16);
            s16[nj][c] = s;
        }
    if ((lane >> 2) == 0) {
#pragma unroll
        for (int nj = 0; nj < 8; ++nj)
#pragma unroll
            for (int c = 0; c < 2; ++c)
                cS[wm * 256 + wn * 64 + nj * 8 + (lane & 3) * 2 + c] = s16[nj][c];
    }
    __syncthreads();
    if (tid < 256) {
        float S = cS[tid] + cS[256 + tid] + cS[512 + tid] + cS[768 + tid];
        g_colPm[n][blockIdx.y][l0 + tid] = cMax[tid];
        g_colPs[n][blockIdx.y][l0 + tid] = S;
    }
}

// ---------------- K5: combine partial stats (row z=0, col z=1) ----------------
__global__ void combine_kernel() {
    const int i = blockIdx.x * 256 + threadIdx.x;
    const int n = blockIdx.y;
    float M = -1e30f, S = 0.f;
    if (blockIdx.z == 0) {
#pragma unroll
        for (int b = 0; b < 16; ++b) {
            float m = g_rowPm[n][b][i], s = g_rowPs[n][b][i];
            float M2 = fmaxf(M, m);
            S = S * __expf(M - M2) + s * __expf(m - M2);
            M = M2;
        }
        g_rowM[n][i] = M;
        g_rowSinv[n][i] = 1.0f / S;
    } else {
#pragma unroll
        for (int b = 0; b < 32; ++b) {
            float m = g_colPm[n][b][i], s = g_colPs[n][b][i];
            float M2 = fmaxf(M, m);
            S = S * __expf(M - M2) + s * __expf(m - M2);
            M = M2;
        }
        g_colM[n][i] = M;
        g_colSinv[n][i] = 1.0f / S;
    }
}

// ---------------- K6: softmax writeout, vectorized ----------------
__global__ void writeout_kernel(float* __restrict__ out_ab, float* __restrict__ out_ba) {
    const int c0 = blockIdx.x * 64, r0 = blockIdx.y * 64, n = blockIdx.z;
    const int tid = threadIdx.x;
    const int tx = tid & 15, ty = tid >> 4;
    const float* __restrict__ E = g_E[n];
    __half* __restrict__ Hab = g_corr_h[0][n];
    __half* __restrict__ Hba = g_corr_h[1][n];
    float* __restrict__ Oab = out_ab + (size_t)n * HW * HW;
    float* __restrict__ Oba = out_ba + (size_t)n * HW * HW;

    __shared__ float t_ba[64][68];
    __shared__ float rm_s[64], rsi_s[64];
    if (tid < 64)       rm_s[tid]       = g_rowM[n][r0 + tid];
    else if (tid < 128) rsi_s[tid - 64] = g_rowSinv[n][r0 + tid - 64];
    const float4 cm4  = *(const float4*)&g_colM[n][c0 + tx * 4];
    const float4 csi4 = *(const float4*)&g_colSinv[n][c0 + tx * 4];
    __syncthreads();

#pragma unroll
    for (int it = 0; it < 4; ++it) {
        int r_in = it * 16 + ty;
        int R = r0 + r_in;
        float4 e = *(const float4*)&E[(size_t)R * HW + c0 + tx * 4];
        float rm = rm_s[r_in], rsi = rsi_s[r_in];
        float4 pr = make_float4(__expf(e.x - rm) * rsi, __expf(e.y - rm) * rsi,
                                __expf(e.z - rm) * rsi, __expf(e.w - rm) * rsi);
        float pc0 = __expf(e.x - cm4.x) * csi4.x;
        float pc1 = __expf(e.y - cm4.y) * csi4.y;
        float pc2 = __expf(e.z - cm4.z) * csi4.z;
        float pc3 = __expf(e.w - cm4.w) * csi4.w;
        size_t off = (size_t)R * HW + c0 + tx * 4;
        *(float4*)&Oab[off] = pr;
        __half2 h0 = __floats2half2_rn(pr.x, pr.y);
        __half2 h1 = __floats2half2_rn(pr.z, pr.w);
        *(uint2*)&Hab[off] = make_uint2(*(uint32_t*)&h0, *(uint32_t*)&h1);
        t_ba[tx * 4 + 0][r_in] = pc0;
        t_ba[tx * 4 + 1][r_in] = pc1;
        t_ba[tx * 4 + 2][r_in] = pc2;
        t_ba[tx * 4 + 3][r_in] = pc3;
    }
    __syncthreads();
#pragma unroll
    for (int it = 0; it < 4; ++it) {
        int c_in = it * 16 + ty;
        float4 p = *(const float4*)&t_ba[c_in][tx * 4];
        size_t off = (size_t)(c0 + c_in) * HW + r0 + tx * 4;
        *(float4*)&Oba[off] = p;
        __half2 h0 = __floats2half2_rn(p.x, p.y);
        __half2 h1 = __floats2half2_rn(p.z, p.w);
        *(uint2*)&Hba[off] = make_uint2(*(uint32_t*)&h0, *(uint32_t*)&h1);
    }
}

// ---------------- K7: raw -> fp16 ----------------
__global__ void tohalf_kernel(const float* __restrict__ a_raw, const float* __restrict__ b_raw) {
    const int t = blockIdx.y;
    const float* __restrict__ src = (t == 0 ? a_raw : b_raw);
    __half* __restrict__ dst = &g_raw_h[t][0][0];
    size_t i = ((size_t)blockIdx.x * 256 + threadIdx.x) * 4;
    float4 v = *(const float4*)&src[i];
    __half2* d2 = (__half2*)&dst[i];
    d2[0] = __floats2half2_rn(v.x, v.y);
    d2[1] = __floats2half2_rn(v.z, v.w);
}

// ---------------- K8: warp matmul, 128x128 tile, 256 thr, 2 CTAs/SM ----------------
#define G2_AST (128 * 72)
#define G2_BST (64 * 136)
#define G2_NC 64
__global__ __launch_bounds__(256, 2) void wgemm_kernel(float* __restrict__ out) {
    extern __shared__ __align__(16) __half gshm[];
    __half* As = gshm;                        // [2][128][72]
    __half* Bs = gshm + 2 * G2_AST;           // [2][64][136]
    const uint32_t su = smaddr(gshm);

    const int z = blockIdx.z;
    const int dir = z >> 1, n = z & 1;
    const __half* __restrict__ A = g_raw_h[dir][n];
    const __half* __restrict__ B = g_corr_h[dir ^ 1][n];
    float* __restrict__ C = out + (size_t)4 * HW * HW
                                + (size_t)dir * 2 * CIN * HW + (size_t)n * CIN * HW;
    const int m0 = blockIdx.y * 128, n0 = blockIdx.x * 128;
    const int tid = threadIdx.x, lane = tid & 31, warp = tid >> 5;
    const int wm = warp & 3, wn = warp >> 2;
    const int r16 = lane & 15, c8 = (lane >> 4) << 3;

    float acc[2][8][4];
#pragma unroll
    for (int i = 0; i < 2; ++i)
#pragma unroll
        for (int j = 0; j < 8; ++j)
#pragma unroll
            for (int k = 0; k < 4; ++k) acc[i][j][k] = 0.f;

    auto loadst = [&](int st, int j) {
        const int k0 = j * 64;
#pragma unroll
        for (int i = 0; i < 8; ++i) {
            int idx = tid + i * 256;
            if (idx < 1024) {
                int row = idx >> 3, cp = (idx & 7) * 8;
                int gr = m0 + row;
                int ok = gr < CIN;
                cpa16u(su + (st * G2_AST + row * 72 + cp) * 2,
                       &A[(size_t)(ok ? gr : 0) * HW + k0 + cp], ok ? 16 : 0);
            } else {
                int ix = idx - 1024;
                int row = ix >> 4, cp = (ix & 15) * 8;
                cpa16u(su + (2 * G2_AST + st * G2_BST + row * 136 + cp) * 2,
                       &B[(size_t)(k0 + row) * HW + n0 + cp], 16);
            }
        }
    };

    loadst(0, 0); CP_COMMIT();

    for (int j = 0; j < G2_NC; ++j) {
        const int st = j & 1;
        CP_WAIT(0);
        __syncthreads();
        if (j + 1 < G2_NC) { loadst(st ^ 1, j + 1); CP_COMMIT(); }

#pragma unroll
        for (int ks = 0; ks < 64; ks += 16) {
            uint32_t a[2][4], b[4][4];
#pragma unroll
            for (int mi = 0; mi < 2; ++mi)
                ldsm4(a[mi], As + st * G2_AST + (wm * 32 + mi * 16 + r16) * 72 + ks + c8);
#pragma unroll
            for (int nj = 0; nj < 4; ++nj)
                ldsm4t(b[nj], Bs + st * G2_BST + (ks + r16) * 136 + wn * 64 + nj * 16 + c8);
#pragma unroll
            for (int mi = 0; mi < 2; ++mi)
#pragma unroll
                for (int nj = 0; nj < 4; ++nj) {
                    mma16816(acc[mi][nj * 2],     a[mi], &b[nj][0]);
                    mma16816(acc[mi][nj * 2 + 1], a[mi], &b[nj][2]);
                }
        }
        __syncthreads();
    }

#pragma unroll
    for (int mi = 0; mi < 2; ++mi)
#pragma unroll
        for (int nj = 0; nj < 8; ++nj) {
            int row = m0 + wm * 32 + mi * 16 + (lane >> 2);
            int col = n0 + wn * 64 + nj * 8 + (lane & 3) * 2;
            if (row < CIN)
                *(float2*)&C[(size_t)row * HW + col] = make_float2(acc[mi][nj][0], acc[mi][nj][1]);
            if (row + 8 < CIN)
                *(float2*)&C[(size_t)(row + 8) * HW + col] = make_float2(acc[mi][nj][2], acc[mi][nj][3]);
        }
}

// ---------------- launch ----------------
extern "C" void kernel_launch(void* const* d_in, const int* in_sizes, int n_in,
                              void* d_out, int out_size) {
    const float* fa    = (const float*)d_in[0];
    const float* fb    = (const float*)d_in[1];
    const float* a_raw = (const float*)d_in[2];
    const float* b_raw = (const float*)d_in[3];
    const float* Wa    = (const float*)d_in[4];
    const float* ba    = (const float*)d_in[5];
    const float* Wb    = (const float*)d_in[6];
    const float* bb    = (const float*)d_in[7];
    float* out = (float*)d_out;

    const int c_smem = 32 * 256 * 4 + 48 * 32 * 4 + 2 * 32 * 264 * 2 + 2 * 48 * 40 * 2; // 80384
    const int e_smem = 2 * E_STG * 2;                    // 153600
    const int g_smem = 2 * (G2_AST + G2_BST) * 2;        // 71680
    cudaFuncSetAttribute(conv_mma_kernel, cudaFuncAttributeMaxDynamicSharedMemorySize, c_smem);
    cudaFuncSetAttribute(energy_mma_kernel, cudaFuncAttributeMaxDynamicSharedMemorySize, e_smem);
    cudaFuncSetAttribute(wgemm_kernel, cudaFuncAttributeMaxDynamicSharedMemorySize, g_smem);

    // side stream: tohalf is independent of the conv->energy chain
    cudaStream_t s2;
    cudaStreamCreate(&s2);
    cudaEvent_t ef, ej;
    cudaEventCreateWithFlags(&ef, cudaEventDisableTiming);
    cudaEventCreateWithFlags(&ej, cudaEventDisableTiming);

    cudaEventRecord(ef, 0);
    cudaStreamWaitEvent(s2, ef, 0);
    tohalf_kernel<<<dim3(8704, 2), 256, 0, s2>>>(a_raw, b_raw);
    cudaEventRecord(ej, s2);

    conv_mma_kernel<<<dim3(16, 3, 4), 256, c_smem>>>(fa, fb, Wa, ba, Wb, bb);
    inorm_kernel<<<dim3(CMID, 2, 2), 256>>>();
    l2norm_kernel<<<dim3(HW / 64, 2, 2), 256>>>();
    energy_mma_kernel<<<dim3(16, 32, 2), 512, e_smem>>>();
    combine_kernel<<<dim3(HW / 256, 2, 2), 256>>>();
    writeout_kernel<<<dim3(64, 64, 2), 256>>>(out, out + (size_t)2 * HW * HW);
    cudaStreamWaitEvent(0, ej, 0);
    wgemm_kernel<<<dim3(32, 9, 4), 256, g_smem>>>(out);
}

// round 13
// speedup vs baseline: 2.0016x; 1.0288x over previous
#include <cuda_runtime.h>
#include <cuda_fp16.h>
#include <cstdint>
#include <cstddef>

#define HW 4096
#define CIN 1088
#define CMID 136
#define CPAD 144

// ---------------- scratch (device globals; zero-initialized, no allocs) ----------------
__device__ float  g_feat[2][2][(size_t)CMID * HW];        // [a/b][n][c*HW+p]
__device__ float  g_E[2][(size_t)HW * HW];                // energy (already *100)
__device__ __half g_corr_h[2][2][(size_t)HW * HW];        // fp16 corr, [ab/ba][n], [k][l]
__device__ __half g_raw_h[2][2][(size_t)CIN * HW];        // [a/b][n]
__device__ __half g_fh[2][2][2][(size_t)CPAD * HW];       // [a/b][hi/lo][n], [c][p]
__device__ float  g_rowM[2][HW], g_rowSinv[2][HW];
__device__ float  g_colM[2][HW], g_colSinv[2][HW];
__device__ float  g_rowPm[2][32][HW],  g_rowPs[2][32][HW];   // per-l-block row partials
__device__ float  g_colPm[2][32][HW],  g_colPs[2][32][HW];   // per-m-block col partials

// ---------------- PTX helpers ----------------
__device__ __forceinline__ uint32_t smaddr(const void* p) {
    return (uint32_t)__cvta_generic_to_shared(p);
}
__device__ __forceinline__ void ldsm4(uint32_t r[4], const void* p) {
    asm volatile("ldmatrix.sync.aligned.m8n8.x4.shared.b16 {%0,%1,%2,%3}, [%4];\n"
                 : "=r"(r[0]), "=r"(r[1]), "=r"(r[2]), "=r"(r[3]) : "r"(smaddr(p)));
}
__device__ __forceinline__ void ldsm4t(uint32_t r[4], const void* p) {
    asm volatile("ldmatrix.sync.aligned.m8n8.x4.trans.shared.b16 {%0,%1,%2,%3}, [%4];\n"
                 : "=r"(r[0]), "=r"(r[1]), "=r"(r[2]), "=r"(r[3]) : "r"(smaddr(p)));
}
__device__ __forceinline__ void mma16816(float* d, const uint32_t* a, const uint32_t* b) {
    asm volatile("mma.sync.aligned.m16n8k16.row.col.f32.f16.f16.f32 "
                 "{%0,%1,%2,%3}, {%4,%5,%6,%7}, {%8,%9}, {%0,%1,%2,%3};\n"
                 : "+f"(d[0]), "+f"(d[1]), "+f"(d[2]), "+f"(d[3])
                 : "r"(a[0]), "r"(a[1]), "r"(a[2]), "r"(a[3]), "r"(b[0]), "r"(b[1]));
}
__device__ __forceinline__ void cpa16u(uint32_t sm, const void* g, int bytes) {
    asm volatile("cp.async.cg.shared.global [%0], [%1], 16, %2;\n"
                 :: "r"(sm), "l"(g), "r"(bytes));
}
#define CP_COMMIT() asm volatile("cp.async.commit_group;\n" ::: "memory")
#define CP_WAIT(n)  asm volatile("cp.async.wait_group %0;\n" :: "n"(n) : "memory")

// ---------------- K1: 1x1 conv via split-fp16 HMMA (single fp16 buffer, 2 CTAs/SM) ----------------
__global__ __launch_bounds__(256, 2) void conv_mma_kernel(
    const float* __restrict__ fa, const float* __restrict__ fb,
    const float* __restrict__ Wa, const float* __restrict__ ba,
    const float* __restrict__ Wb, const float* __restrict__ bb) {
    extern __shared__ __align__(16) char csm[];
    float*  Xf  = (float*)csm;                      // [32][256]
    float*  Wf  = Xf + 32 * 256;                    // [48][32]
    __half* Xhl = (__half*)(Wf + 48 * 32);          // [2 hl][32][264]
    __half* Whl = Xhl + 2 * 32 * 264;               // [2 hl][48][40]

    const int t = blockIdx.z >> 1, n = blockIdx.z & 1;
    const float* __restrict__ X = (t == 0 ? fa : fb) + (size_t)n * CIN * HW;
    const float* __restrict__ W = (t == 0 ? Wa : Wb);
    const float* __restrict__ bias = (t == 0 ? ba : bb);
    const int m0 = blockIdx.y * 48, n0 = blockIdx.x * 256;
    const int tid = threadIdx.x, lane = tid & 31, warp = tid >> 5;
    const int r16 = lane & 15, c8 = (lane >> 4) << 3;

    float acc[3][4][4];
#pragma unroll
    for (int i = 0; i < 3; ++i)
#pragma unroll
        for (int j = 0; j < 4; ++j)
#pragma unroll
            for (int k = 0; k < 4; ++k) acc[i][j][k] = 0.f;

    auto cpX = [&](int kc) {
#pragma unroll
        for (int i = 0; i < 8; ++i) {
            int idx = tid + i * 256;
            int row = idx >> 6, seg = (idx & 63) * 4;
            cpa16u(smaddr(&Xf[row * 256 + seg]), &X[(size_t)(kc + row) * HW + n0 + seg], 16);
        }
#pragma unroll
        for (int i = 0; i < 2; ++i) {
            int idx = tid + i * 256;
            if (idx < 384) {
                int row = idx >> 3, seg = (idx & 7) * 4;
                int o = m0 + row;
                int ok = o < CMID;
                cpa16u(smaddr(&Wf[row * 32 + seg]), &W[(size_t)(ok ? o : 0) * CIN + kc + seg], ok ? 16 : 0);
            }
        }
    };
    auto convert = [&]() {
        __half* Xh = Xhl;
        __half* Xl = Xh + 32 * 264;
#pragma unroll
        for (int i = 0; i < 32; ++i) {
            int idx = tid + i * 256;
            int row = idx >> 8, col = idx & 255;
            float v = Xf[row * 256 + col];
            __half h = __float2half_rn(v);
            Xh[row * 264 + col] = h;
            Xl[row * 264 + col] = __float2half_rn(v - __half2float(h));
        }
        __half* Wh = Whl;
        __half* Wl = Wh + 48 * 40;
#pragma unroll
        for (int i = 0; i < 6; ++i) {
            int idx = tid + i * 256;
            if (idx < 1536) {
                int row = idx >> 5, col = idx & 31;
                float v = Wf[row * 32 + col];
                __half h = __float2half_rn(v);
                Wh[row * 40 + col] = h;
                Wl[row * 40 + col] = __float2half_rn(v - __half2float(h));
            }
        }
    };

    cpX(0); CP_COMMIT();
    for (int j = 0; j < 34; ++j) {
        CP_WAIT(0);
        __syncthreads();
        convert();
        __syncthreads();
        if (j + 1 < 34) cpX((j + 1) * 32);
        CP_COMMIT();

        const __half* Xh = Xhl;
        const __half* Xl = Xh + 32 * 264;
        const __half* Wh = Whl;
        const __half* Wl = Wh + 48 * 40;
#pragma unroll
        for (int ks = 0; ks < 32; ks += 16) {
            uint32_t ah[3][4], al[3][4], bh[2][4], bl[2][4];
#pragma unroll
            for (int mi = 0; mi < 3; ++mi) {
                ldsm4(ah[mi], &Wh[(mi * 16 + r16) * 40 + ks + c8]);
                ldsm4(al[mi], &Wl[(mi * 16 + r16) * 40 + ks + c8]);
            }
#pragma unroll
            for (int nj = 0; nj < 2; ++nj) {
                ldsm4t(bh[nj], &Xh[(ks + r16) * 264 + warp * 32 + nj * 16 + c8]);
                ldsm4t(bl[nj], &Xl[(ks + r16) * 264 + warp * 32 + nj * 16 + c8]);
            }
#pragma unroll
            for (int mi = 0; mi < 3; ++mi)
#pragma unroll
                for (int nj = 0; nj < 2; ++nj) {
                    mma16816(acc[mi][nj * 2],     ah[mi], &bh[nj][0]);
                    mma16816(acc[mi][nj * 2 + 1], ah[mi], &bh[nj][2]);
                    mma16816(acc[mi][nj * 2],     ah[mi], &bl[nj][0]);
                    mma16816(acc[mi][nj * 2 + 1], ah[mi], &bl[nj][2]);
                    mma16816(acc[mi][nj * 2],     al[mi], &bh[nj][0]);
                    mma16816(acc[mi][nj * 2 + 1], al[mi], &bh[nj][2]);
                }
        }
        __syncthreads();
    }

    float* __restrict__ Y = g_feat[t][n];
#pragma unroll
    for (int mi = 0; mi < 3; ++mi)
#pragma unroll
        for (int g = 0; g < 4; ++g) {
            int r0 = m0 + mi * 16 + (lane >> 2);
            int col = n0 + warp * 32 + (g >> 1) * 16 + (g & 1) * 8 + (lane & 3) * 2;
            if (r0 < CMID) {
                float bv = bias[r0];
                *(float2*)&Y[(size_t)r0 * HW + col] =
                    make_float2(acc[mi][g][0] + bv, acc[mi][g][1] + bv);
            }
            if (r0 + 8 < CMID) {
                float bv = bias[r0 + 8];
                *(float2*)&Y[(size_t)(r0 + 8) * HW + col] =
                    make_float2(acc[mi][g][2] + bv, acc[mi][g][3] + bv);
            }
        }
}

// ---------------- K2: InstanceNorm + LeakyReLU + mean-center ----------------
__global__ void inorm_kernel() {
    const int c = blockIdx.x, n = blockIdx.y, t = blockIdx.z;
    float* __restrict__ Y = &g_feat[t][n][(size_t)c * HW];
    __shared__ float sd[HW];
    __shared__ float r1[256], r2[256];
    const int tid = threadIdx.x;

    float s = 0.f, q = 0.f;
    for (int i = tid; i < HW; i += 256) { float v = Y[i]; sd[i] = v; s += v; q += v * v; }
    r1[tid] = s; r2[tid] = q; __syncthreads();
    for (int st = 128; st > 0; st >>= 1) {
        if (tid < st) { r1[tid] += r1[tid + st]; r2[tid] += r2[tid + st]; }
        __syncthreads();
    }
    const float mean = r1[0] * (1.f / HW);
    const float var  = r2[0] * (1.f / HW) - mean * mean;
    const float inv  = rsqrtf(var + 1e-5f);
    __syncthreads();

    float s2 = 0.f;
    for (int i = tid; i < HW; i += 256) {
        float v = (sd[i] - mean) * inv;
        v = (v >= 0.f) ? v : 0.2f * v;
        sd[i] = v; s2 += v;
    }
    r1[tid] = s2; __syncthreads();
    for (int st = 128; st > 0; st >>= 1) {
        if (tid < st) r1[tid] += r1[tid + st];
        __syncthreads();
    }
    const float mean2 = r1[0] * (1.f / HW);
    for (int i = tid; i < HW; i += 256) Y[i] = sd[i] - mean2;
}

// ---------------- K3: L2-normalize + split hi/lo (4 channel-groups per block) ----------------
__global__ void l2norm_kernel() {
    const int tid = threadIdx.x;
    const int px = tid & 63, cg = tid >> 6;
    const int p = blockIdx.x * 64 + px;
    const int n = blockIdx.y, t = blockIdx.z;
    const float* __restrict__ F = g_feat[t][n];
    __shared__ float red[4][64];

    const int cbeg = cg * 34, cend = cbeg + 34;
    float q = 0.f;
    for (int c = cbeg; c < cend; ++c) { float v = F[(size_t)c * HW + p]; q += v * v; }
    red[cg][px] = q;
    __syncthreads();
    const float inv = rsqrtf(red[0][px] + red[1][px] + red[2][px] + red[3][px]);

    __half* __restrict__ hi = g_fh[t][0][n];
    __half* __restrict__ lo = g_fh[t][1][n];
    for (int c = cbeg; c < cend; ++c) {
        float v = F[(size_t)c * HW + p] * inv;
        __half h = __float2half_rn(v);
        hi[(size_t)c * HW + p] = h;
        lo[(size_t)c * HW + p] = __float2half_rn(v - __half2float(h));
    }
}

// ---------------- K4: energy, 128x128 tile, 256 thr, 2 CTAs/SM ----------------
// merged-pass split-fp16: per k48 chunk load Ah/Al/Bh/Bl once; hh + ah*bl + al*bh.
#define E2_T   (48 * 136)            // halves per tile
#define E2_STG (4 * E2_T)            // Ah, Al, Bh, Bl per stage (26112 halves)
__global__ __launch_bounds__(256, 2) void energy_mma_kernel() {
    extern __shared__ __align__(16) __half eshm[];

    const int n = blockIdx.z;
    const int m0 = blockIdx.y * 128, l0 = blockIdx.x * 128;
    const int tid = threadIdx.x, lane = tid & 31, warp = tid >> 5;
    const int wm = warp & 3, wn = warp >> 2;          // 4 x 2
    const int r16 = lane & 15, c8 = (lane >> 4) << 3;
    const int arow = (lane & 7) + ((lane >> 4) & 1) * 8;
    const int acol = ((lane >> 3) & 1) * 8;

    float acc[2][8][4];
#pragma unroll
    for (int i = 0; i < 2; ++i)
#pragma unroll
        for (int j = 0; j < 8; ++j)
#pragma unroll
            for (int k = 0; k < 4; ++k) acc[i][j][k] = 0.f;

    const uint32_t su = smaddr(eshm);
    auto loadst = [&](int st, int q) {
        const int kc = q * 48;
        const uint32_t SB = su + st * E2_STG * 2;
#pragma unroll
        for (int i = 0; i < 12; ++i) {
            int idx = tid + i * 256;
            int tile = idx / 768, ix = idx % 768;     // 0=Ah 1=Al 2=Bh 3=Bl
            int row = ix >> 4, cp = (ix & 15) * 8;
            const __half* src = (tile < 2)
                ? &g_fh[1][tile][n][(size_t)(kc + row) * HW + m0 + cp]
                : &g_fh[0][tile - 2][n][(size_t)(kc + row) * HW + l0 + cp];
            cpa16u(SB + (tile * E2_T + row * 136 + cp) * 2, src, 16);
        }
    };

    auto mmag2 = [&](uint32_t a[2][4], uint32_t b[4][4]) {
#pragma unroll
        for (int mi = 0; mi < 2; ++mi)
#pragma unroll
            for (int nj = 0; nj < 4; ++nj) {
                mma16816(acc[mi][nj * 2],     a[mi], &b[nj][0]);
                mma16816(acc[mi][nj * 2 + 1], a[mi], &b[nj][2]);
            }
    };

    loadst(0, 0); CP_COMMIT();
    loadst(1, 1); CP_COMMIT();
    for (int q = 0; q < 3; ++q) {
        const int st = q & 1;
        if (q == 2) CP_WAIT(0); else CP_WAIT(1);
        __syncthreads();
        const __half* Ah = eshm + st * E2_STG;
        const __half* Al = Ah + E2_T;
        const __half* Bh = Al + E2_T;
        const __half* Bl = Bh + E2_T;
#pragma unroll
        for (int ks = 0; ks < 48; ks += 16) {
            uint32_t ah[2][4], bh[4][4];
#pragma unroll
            for (int mi = 0; mi < 2; ++mi)
                ldsm4t(ah[mi], Ah + (ks + arow) * 136 + wm * 32 + mi * 16 + acol);
#pragma unroll
            for (int nj = 0; nj < 4; ++nj)
                ldsm4t(bh[nj], Bh + (ks + r16) * 136 + wn * 64 + nj * 16 + c8);
            mmag2(ah, bh);
            {
                uint32_t bl[4][4];
#pragma unroll
                for (int nj = 0; nj < 4; ++nj)
                    ldsm4t(bl[nj], Bl + (ks + r16) * 136 + wn * 64 + nj * 16 + c8);
                mmag2(ah, bl);
            }
            {
                uint32_t al[2][4];
#pragma unroll
                for (int mi = 0; mi < 2; ++mi)
                    ldsm4t(al[mi], Al + (ks + arow) * 136 + wm * 32 + mi * 16 + acol);
                mmag2(al, bh);
            }
        }
        __syncthreads();
        if (q + 2 < 3) { loadst(st, q + 2); CP_COMMIT(); }
    }

#pragma unroll
    for (int mi = 0; mi < 2; ++mi)
#pragma unroll
        for (int nj = 0; nj < 8; ++nj)
#pragma unroll
            for (int k = 0; k < 4; ++k) acc[mi][nj][k] *= 100.f;

    float* __restrict__ E = g_E[n];
#pragma unroll
    for (int mi = 0; mi < 2; ++mi)
#pragma unroll
        for (int nj = 0; nj < 8; ++nj) {
            int row = m0 + wm * 32 + mi * 16 + (lane >> 2);
            int col = l0 + wn * 64 + nj * 8 + (lane & 3) * 2;
            *(float2*)&E[(size_t)row * HW + col] = make_float2(acc[mi][nj][0], acc[mi][nj][1]);
            *(float2*)&E[(size_t)(row + 8) * HW + col] = make_float2(acc[mi][nj][2], acc[mi][nj][3]);
        }

    // ---- fused softmax partials (reuse stage smem) ----
    float* sM   = (float*)eshm;        // row partials  [2 wn][128]
    float* sS   = sM + 256;
    float* cMax = sS + 256;            // col partials  [4 wm][128]
    float* cS   = cMax + 512;

    // row partials: per warp max/expsum over its 64 cols, merge 2 wn
#pragma unroll
    for (int mi = 0; mi < 2; ++mi)
#pragma unroll
        for (int h = 0; h < 2; ++h) {
            float m = -1e30f;
#pragma unroll
            for (int nj = 0; nj < 8; ++nj)
                m = fmaxf(m, fmaxf(acc[mi][nj][2 * h], acc[mi][nj][2 * h + 1]));
            m = fmaxf(m, __shfl_xor_sync(0xFFFFFFFFu, m, 1));
            m = fmaxf(m, __shfl_xor_sync(0xFFFFFFFFu, m, 2));
            float s = 0.f;
#pragma unroll
            for (int nj = 0; nj < 8; ++nj)
                s += __expf(acc[mi][nj][2 * h] - m) + __expf(acc[mi][nj][2 * h + 1] - m);
            s += __shfl_xor_sync(0xFFFFFFFFu, s, 1);
            s += __shfl_xor_sync(0xFFFFFFFFu, s, 2);
            if ((lane & 3) == 0) {
                int r = wm * 32 + mi * 16 + (lane >> 2) + 8 * h;
                sM[wn * 128 + r] = m;
                sS[wn * 128 + r] = s;
            }
        }
    // col partials step 1: thread-local + cross-lane max
    float m16[8][2];
#pragma unroll
    for (int nj = 0; nj < 8; ++nj)
#pragma unroll
        for (int c = 0; c < 2; ++c) {
            float m = fmaxf(fmaxf(acc[0][nj][c], acc[0][nj][2 + c]),
                            fmaxf(acc[1][nj][c], acc[1][nj][2 + c]));
            m = fmaxf(m, __shfl_xor_sync(0xFFFFFFFFu, m, 4));
            m = fmaxf(m, __shfl_xor_sync(0xFFFFFFFFu, m, 8));
            m = fmaxf(m, __shfl_xor_sync(0xFFFFFFFFu, m, 16));
            m16[nj][c] = m;
        }
    if ((lane >> 2) == 0) {
#pragma unroll
        for (int nj = 0; nj < 8; ++nj)
#pragma unroll
            for (int c = 0; c < 2; ++c)
                cMax[wm * 128 + wn * 64 + nj * 8 + (lane & 3) * 2 + c] = m16[nj][c];
    }
    __syncthreads();

    if (tid < 128) {
        float M = sM[tid], S = sS[tid];
        float m2 = sM[128 + tid], s2 = sS[128 + tid];
        float M2 = fmaxf(M, m2);
        S = S * __expf(M - M2) + s2 * __expf(m2 - M2);
        M = M2;
        g_rowPm[n][blockIdx.x][m0 + tid] = M;
        g_rowPs[n][blockIdx.x][m0 + tid] = S;
        // merge 4 wm for col block max
        float C = fmaxf(fmaxf(cMax[tid], cMax[128 + tid]),
                        fmaxf(cMax[256 + tid], cMax[384 + tid]));
        cMax[tid] = C;
    }
    __syncthreads();

    // col expsums vs block max
    float s16[8][2];
#pragma unroll
    for (int nj = 0; nj < 8; ++nj)
#pragma unroll
        for (int c = 0; c < 2; ++c) {
            float bm = cMax[wn * 64 + nj * 8 + (lane & 3) * 2 + c];
            float s = __expf(acc[0][nj][c] - bm) + __expf(acc[0][nj][2 + c] - bm)
                    + __expf(acc[1][nj][c] - bm) + __expf(acc[1][nj][2 + c] - bm);
            s += __shfl_xor_sync(0xFFFFFFFFu, s, 4);
            s += __shfl_xor_sync(0xFFFFFFFFu, s, 8);
            s += __shfl_xor_sync(0xFFFFFFFFu, s, 16);
            s16[nj][c] = s;
        }
    if ((lane >> 2) == 0) {
#pragma unroll
        for (int nj = 0; nj < 8; ++nj)
#pragma unroll
            for (int c = 0; c < 2; ++c)
                cS[wm * 128 + wn * 64 + nj * 8 + (lane & 3) * 2 + c] = s16[nj][c];
    }
    __syncthreads();
    if (tid < 128) {
        float S = cS[tid] + cS[128 + tid] + cS[256 + tid] + cS[384 + tid];
        g_colPm[n][blockIdx.y][l0 + tid] = cMax[tid];
        g_colPs[n][blockIdx.y][l0 + tid] = S;
    }
}

// ---------------- K5: combine partial stats (row z=0, col z=1) ----------------
__global__ void combine_kernel() {
    const int i = blockIdx.x * 256 + threadIdx.x;
    const int n = blockIdx.y;
    float M = -1e30f, S = 0.f;
    if (blockIdx.z == 0) {
#pragma unroll
        for (int b = 0; b < 32; ++b) {
            float m = g_rowPm[n][b][i], s = g_rowPs[n][b][i];
            float M2 = fmaxf(M, m);
            S = S * __expf(M - M2) + s * __expf(m - M2);
            M = M2;
        }
        g_rowM[n][i] = M;
        g_rowSinv[n][i] = 1.0f / S;
    } else {
#pragma unroll
        for (int b = 0; b < 32; ++b) {
            float m = g_colPm[n][b][i], s = g_colPs[n][b][i];
            float M2 = fmaxf(M, m);
            S = S * __expf(M - M2) + s * __expf(m - M2);
            M = M2;
        }
        g_colM[n][i] = M;
        g_colSinv[n][i] = 1.0f / S;
    }
}

// ---------------- K6: softmax writeout, vectorized ----------------
__global__ void writeout_kernel(float* __restrict__ out_ab, float* __restrict__ out_ba) {
    const int c0 = blockIdx.x * 64, r0 = blockIdx.y * 64, n = blockIdx.z;
    const int tid = threadIdx.x;
    const int tx = tid & 15, ty = tid >> 4;
    const float* __restrict__ E = g_E[n];
    __half* __restrict__ Hab = g_corr_h[0][n];
    __half* __restrict__ Hba = g_corr_h[1][n];
    float* __restrict__ Oab = out_ab + (size_t)n * HW * HW;
    float* __restrict__ Oba = out_ba + (size_t)n * HW * HW;

    __shared__ float t_ba[64][68];
    __shared__ float rm_s[64], rsi_s[64];
    if (tid < 64)       rm_s[tid]       = g_rowM[n][r0 + tid];
    else if (tid < 128) rsi_s[tid - 64] = g_rowSinv[n][r0 + tid - 64];
    const float4 cm4  = *(const float4*)&g_colM[n][c0 + tx * 4];
    const float4 csi4 = *(const float4*)&g_colSinv[n][c0 + tx * 4];
    __syncthreads();

#pragma unroll
    for (int it = 0; it < 4; ++it) {
        int r_in = it * 16 + ty;
        int R = r0 + r_in;
        float4 e = *(const float4*)&E[(size_t)R * HW + c0 + tx * 4];
        float rm = rm_s[r_in], rsi = rsi_s[r_in];
        float4 pr = make_float4(__expf(e.x - rm) * rsi, __expf(e.y - rm) * rsi,
                                __expf(e.z - rm) * rsi, __expf(e.w - rm) * rsi);
        float pc0 = __expf(e.x - cm4.x) * csi4.x;
        float pc1 = __expf(e.y - cm4.y) * csi4.y;
        float pc2 = __expf(e.z - cm4.z) * csi4.z;
        float pc3 = __expf(e.w - cm4.w) * csi4.w;
        size_t off = (size_t)R * HW + c0 + tx * 4;
        *(float4*)&Oab[off] = pr;
        __half2 h0 = __floats2half2_rn(pr.x, pr.y);
        __half2 h1 = __floats2half2_rn(pr.z, pr.w);
        *(uint2*)&Hab[off] = make_uint2(*(uint32_t*)&h0, *(uint32_t*)&h1);
        t_ba[tx * 4 + 0][r_in] = pc0;
        t_ba[tx * 4 + 1][r_in] = pc1;
        t_ba[tx * 4 + 2][r_in] = pc2;
        t_ba[tx * 4 + 3][r_in] = pc3;
    }
    __syncthreads();
#pragma unroll
    for (int it = 0; it < 4; ++it) {
        int c_in = it * 16 + ty;
        float4 p = *(const float4*)&t_ba[c_in][tx * 4];
        size_t off = (size_t)(c0 + c_in) * HW + r0 + tx * 4;
        *(float4*)&Oba[off] = p;
        __half2 h0 = __floats2half2_rn(p.x, p.y);
        __half2 h1 = __floats2half2_rn(p.z, p.w);
        *(uint2*)&Hba[off] = make_uint2(*(uint32_t*)&h0, *(uint32_t*)&h1);
    }
}

// ---------------- K7: raw -> fp16 ----------------
__global__ void tohalf_kernel(const float* __restrict__ a_raw, const float* __restrict__ b_raw) {
    const int t = blockIdx.y;
    const float* __restrict__ src = (t == 0 ? a_raw : b_raw);
    __half* __restrict__ dst = &g_raw_h[t][0][0];
    size_t i = ((size_t)blockIdx.x * 256 + threadIdx.x) * 4;
    float4 v = *(const float4*)&src[i];
    __half2* d2 = (__half2*)&dst[i];
    d2[0] = __floats2half2_rn(v.x, v.y);
    d2[1] = __floats2half2_rn(v.z, v.w);
}

// ---------------- K8: warp matmul, 128x128 tile, 256 thr, 2 CTAs/SM, 3-stage ----------------
#define G2_AST (128 * 72)
#define G2_BST (64 * 136)
#define G2_NC 64
__global__ __launch_bounds__(256, 2) void wgemm_kernel(float* __restrict__ out) {
    extern __shared__ __align__(16) __half gshm[];
    __half* As = gshm;                        // [3][128][72]
    __half* Bs = gshm + 3 * G2_AST;           // [3][64][136]
    const uint32_t su = smaddr(gshm);

    const int z = blockIdx.z;
    const int dir = z >> 1, n = z & 1;
    const __half* __restrict__ A = g_raw_h[dir][n];
    const __half* __restrict__ B = g_corr_h[dir ^ 1][n];
    float* __restrict__ C = out + (size_t)4 * HW * HW
                                + (size_t)dir * 2 * CIN * HW + (size_t)n * CIN * HW;
    const int m0 = blockIdx.y * 128, n0 = blockIdx.x * 128;
    const int tid = threadIdx.x, lane = tid & 31, warp = tid >> 5;
    const int wm = warp & 3, wn = warp >> 2;
    const int r16 = lane & 15, c8 = (lane >> 4) << 3;

    float acc[2][8][4];
#pragma unroll
    for (int i = 0; i < 2; ++i)
#pragma unroll
        for (int j = 0; j < 8; ++j)
#pragma unroll
            for (int k = 0; k < 4; ++k) acc[i][j][k] = 0.f;

    auto loadst = [&](int st, int j) {
        const int k0 = j * 64;
#pragma unroll
        for (int i = 0; i < 8; ++i) {
            int idx = tid + i * 256;
            if (idx < 1024) {
                int row = idx >> 3, cp = (idx & 7) * 8;
                int gr = m0 + row;
                int ok = gr < CIN;
                cpa16u(su + (st * G2_AST + row * 72 + cp) * 2,
                       &A[(size_t)(ok ? gr : 0) * HW + k0 + cp], ok ? 16 : 0);
            } else {
                int ix = idx - 1024;
                int row = ix >> 4, cp = (ix & 15) * 8;
                cpa16u(su + (3 * G2_AST + st * G2_BST + row * 136 + cp) * 2,
                       &B[(size_t)(k0 + row) * HW + n0 + cp], 16);
            }
        }
    };

    loadst(0, 0); CP_COMMIT();
    loadst(1, 1); CP_COMMIT();

    for (int j = 0; j < G2_NC; ++j) {
        const int st = j % 3;
        if (j + 1 < G2_NC) CP_WAIT(1); else CP_WAIT(0);
        __syncthreads();
        if (j + 2 < G2_NC) { loadst((j + 2) % 3, j + 2); CP_COMMIT(); }

#pragma unroll
        for (int ks = 0; ks < 64; ks += 16) {
            uint32_t a[2][4], b[4][4];
#pragma unroll
            for (int mi = 0; mi < 2; ++mi)
                ldsm4(a[mi], As + st * G2_AST + (wm * 32 + mi * 16 + r16) * 72 + ks + c8);
#pragma unroll
            for (int nj = 0; nj < 4; ++nj)
                ldsm4t(b[nj], Bs + st * G2_BST + (ks + r16) * 136 + wn * 64 + nj * 16 + c8);
#pragma unroll
            for (int mi = 0; mi < 2; ++mi)
#pragma unroll
                for (int nj = 0; nj < 4; ++nj) {
                    mma16816(acc[mi][nj * 2],     a[mi], &b[nj][0]);
                    mma16816(acc[mi][nj * 2 + 1], a[mi], &b[nj][2]);
                }
        }
        __syncthreads();
    }

#pragma unroll
    for (int mi = 0; mi < 2; ++mi)
#pragma unroll
        for (int nj = 0; nj < 8; ++nj) {
            int row = m0 + wm * 32 + mi * 16 + (lane >> 2);
            int col = n0 + wn * 64 + nj * 8 + (lane & 3) * 2;
            if (row < CIN)
                *(float2*)&C[(size_t)row * HW + col] = make_float2(acc[mi][nj][0], acc[mi][nj][1]);
            if (row + 8 < CIN)
                *(float2*)&C[(size_t)(row + 8) * HW + col] = make_float2(acc[mi][nj][2], acc[mi][nj][3]);
        }
}

// ---------------- launch ----------------
extern "C" void kernel_launch(void* const* d_in, const int* in_sizes, int n_in,
                              void* d_out, int out_size) {
    const float* fa    = (const float*)d_in[0];
    const float* fb    = (const float*)d_in[1];
    const float* a_raw = (const float*)d_in[2];
    const float* b_raw = (const float*)d_in[3];
    const float* Wa    = (const float*)d_in[4];
    const float* ba    = (const float*)d_in[5];
    const float* Wb    = (const float*)d_in[6];
    const float* bb    = (const float*)d_in[7];
    float* out = (float*)d_out;

    const int c_smem = 32 * 256 * 4 + 48 * 32 * 4 + 2 * 32 * 264 * 2 + 2 * 48 * 40 * 2; // 80384
    const int e_smem = 2 * E2_STG * 2;                   // 104448
    const int g_smem = 3 * (G2_AST + G2_BST) * 2;        // 107520
    cudaFuncSetAttribute(conv_mma_kernel, cudaFuncAttributeMaxDynamicSharedMemorySize, c_smem);
    cudaFuncSetAttribute(energy_mma_kernel, cudaFuncAttributeMaxDynamicSharedMemorySize, e_smem);
    cudaFuncSetAttribute(wgemm_kernel, cudaFuncAttributeMaxDynamicSharedMemorySize, g_smem);

    // side stream: tohalf is independent of the conv->energy chain
    cudaStream_t s2;
    cudaStreamCreate(&s2);
    cudaEvent_t ef, ej;
    cudaEventCreateWithFlags(&ef, cudaEventDisableTiming);
    cudaEventCreateWithFlags(&ej, cudaEventDisableTiming);

    cudaEventRecord(ef, 0);
    cudaStreamWaitEvent(s2, ef, 0);
    tohalf_kernel<<<dim3(8704, 2), 256, 0, s2>>>(a_raw, b_raw);
    cudaEventRecord(ej, s2);

    conv_mma_kernel<<<dim3(16, 3, 4), 256, c_smem>>>(fa, fb, Wa, ba, Wb, bb);
    inorm_kernel<<<dim3(CMID, 2, 2), 256>>>();
    l2norm_kernel<<<dim3(HW / 64, 2, 2), 256>>>();
    energy_mma_kernel<<<dim3(32, 32, 2), 256, e_smem>>>();
    combine_kernel<<<dim3(HW / 256, 2, 2), 256>>>();
    writeout_kernel<<<dim3(64, 64, 2), 256>>>(out, out + (size_t)2 * HW * HW);
    cudaStreamWaitEvent(0, ej, 0);
    wgemm_kernel<<<dim3(32, 9, 4), 256, g_smem>>>(out);
}

// round 15
// speedup vs baseline: 2.0192x; 1.0088x over previous
#include <cuda_runtime.h>
#include <cuda_fp16.h>
#include <cstdint>
#include <cstddef>

#define HW 4096
#define CIN 1088
#define CMID 136
#define CPAD 144

// ---------------- scratch (device globals; zero-initialized, no allocs) ----------------
__device__ float  g_feat[2][2][(size_t)CMID * HW];        // [a/b][n][c*HW+p]
__device__ float  g_E[2][(size_t)HW * HW];                // energy (already *100)
__device__ __half g_corr_h[2][2][(size_t)HW * HW];        // fp16 corr, [ab/ba][n], [k][l]
__device__ __half g_raw_h[2][2][(size_t)CIN * HW];        // [a/b][n]
__device__ __half g_fh[2][2][2][(size_t)CPAD * HW];       // [a/b][hi/lo][n], [c][p]
__device__ float  g_rowM[2][HW], g_rowSinv[2][HW];
__device__ float  g_colM[2][HW], g_colSinv[2][HW];
__device__ float  g_rowPm[2][32][HW],  g_rowPs[2][32][HW];
__device__ float  g_colPm[2][32][HW],  g_colPs[2][32][HW];

// ---------------- PTX helpers ----------------
__device__ __forceinline__ uint32_t smaddr(const void* p) {
    return (uint32_t)__cvta_generic_to_shared(p);
}
__device__ __forceinline__ void ldsm4(uint32_t r[4], const void* p) {
    asm volatile("ldmatrix.sync.aligned.m8n8.x4.shared.b16 {%0,%1,%2,%3}, [%4];\n"
                 : "=r"(r[0]), "=r"(r[1]), "=r"(r[2]), "=r"(r[3]) : "r"(smaddr(p)));
}
__device__ __forceinline__ void ldsm4t(uint32_t r[4], const void* p) {
    asm volatile("ldmatrix.sync.aligned.m8n8.x4.trans.shared.b16 {%0,%1,%2,%3}, [%4];\n"
                 : "=r"(r[0]), "=r"(r[1]), "=r"(r[2]), "=r"(r[3]) : "r"(smaddr(p)));
}
__device__ __forceinline__ void mma16816(float* d, const uint32_t* a, const uint32_t* b) {
    asm volatile("mma.sync.aligned.m16n8k16.row.col.f32.f16.f16.f32 "
                 "{%0,%1,%2,%3}, {%4,%5,%6,%7}, {%8,%9}, {%0,%1,%2,%3};\n"
                 : "+f"(d[0]), "+f"(d[1]), "+f"(d[2]), "+f"(d[3])
                 : "r"(a[0]), "r"(a[1]), "r"(a[2]), "r"(a[3]), "r"(b[0]), "r"(b[1]));
}
__device__ __forceinline__ void cpa16u(uint32_t sm, const void* g, int bytes) {
    asm volatile("cp.async.cg.shared.global [%0], [%1], 16, %2;\n"
                 :: "r"(sm), "l"(g), "r"(bytes));
}
#define CP_COMMIT() asm volatile("cp.async.commit_group;\n" ::: "memory")
#define CP_WAIT(n)  asm volatile("cp.async.wait_group %0;\n" :: "n"(n) : "memory")

// ---------------- K1: 1x1 conv via split-fp16 HMMA (single fp16 buffer, 2 CTAs/SM) ----------------
__global__ __launch_bounds__(256, 2) void conv_mma_kernel(
    const float* __restrict__ fa, const float* __restrict__ fb,
    const float* __restrict__ Wa, const float* __restrict__ ba,
    const float* __restrict__ Wb, const float* __restrict__ bb) {
    extern __shared__ __align__(16) char csm[];
    float*  Xf  = (float*)csm;
    float*  Wf  = Xf + 32 * 256;
    __half* Xhl = (__half*)(Wf + 48 * 32);
    __half* Whl = Xhl + 2 * 32 * 264;

    const int t = blockIdx.z >> 1, n = blockIdx.z & 1;
    const float* __restrict__ X = (t == 0 ? fa : fb) + (size_t)n * CIN * HW;
    const float* __restrict__ W = (t == 0 ? Wa : Wb);
    const float* __restrict__ bias = (t == 0 ? ba : bb);
    const int m0 = blockIdx.y * 48, n0 = blockIdx.x * 256;
    const int tid = threadIdx.x, lane = tid & 31, warp = tid >> 5;
    const int r16 = lane & 15, c8 = (lane >> 4) << 3;

    float acc[3][4][4];
#pragma unroll
    for (int i = 0; i < 3; ++i)
#pragma unroll
        for (int j = 0; j < 4; ++j)
#pragma unroll
            for (int k = 0; k < 4; ++k) acc[i][j][k] = 0.f;

    auto cpX = [&](int kc) {
#pragma unroll
        for (int i = 0; i < 8; ++i) {
            int idx = tid + i * 256;
            int row = idx >> 6, seg = (idx & 63) * 4;
            cpa16u(smaddr(&Xf[row * 256 + seg]), &X[(size_t)(kc + row) * HW + n0 + seg], 16);
        }
#pragma unroll
        for (int i = 0; i < 2; ++i) {
            int idx = tid + i * 256;
            if (idx < 384) {
                int row = idx >> 3, seg = (idx & 7) * 4;
                int o = m0 + row;
                int ok = o < CMID;
                cpa16u(smaddr(&Wf[row * 32 + seg]), &W[(size_t)(ok ? o : 0) * CIN + kc + seg], ok ? 16 : 0);
            }
        }
    };
    auto convert = [&]() {
        __half* Xh = Xhl;
        __half* Xl = Xh + 32 * 264;
#pragma unroll
        for (int i = 0; i < 32; ++i) {
            int idx = tid + i * 256;
            int row = idx >> 8, col = idx & 255;
            float v = Xf[row * 256 + col];
            __half h = __float2half_rn(v);
            Xh[row * 264 + col] = h;
            Xl[row * 264 + col] = __float2half_rn(v - __half2float(h));
        }
        __half* Wh = Whl;
        __half* Wl = Wh + 48 * 40;
#pragma unroll
        for (int i = 0; i < 6; ++i) {
            int idx = tid + i * 256;
            if (idx < 1536) {
                int row = idx >> 5, col = idx & 31;
                float v = Wf[row * 32 + col];
                __half h = __float2half_rn(v);
                Wh[row * 40 + col] = h;
                Wl[row * 40 + col] = __float2half_rn(v - __half2float(h));
            }
        }
    };

    cpX(0); CP_COMMIT();
    for (int j = 0; j < 34; ++j) {
        CP_WAIT(0);
        __syncthreads();
        convert();
        __syncthreads();
        if (j + 1 < 34) cpX((j + 1) * 32);
        CP_COMMIT();

        const __half* Xh = Xhl;
        const __half* Xl = Xh + 32 * 264;
        const __half* Wh = Whl;
        const __half* Wl = Wh + 48 * 40;
#pragma unroll
        for (int ks = 0; ks < 32; ks += 16) {
            uint32_t ah[3][4], al[3][4], bh[2][4], bl[2][4];
#pragma unroll
            for (int mi = 0; mi < 3; ++mi) {
                ldsm4(ah[mi], &Wh[(mi * 16 + r16) * 40 + ks + c8]);
                ldsm4(al[mi], &Wl[(mi * 16 + r16) * 40 + ks + c8]);
            }
#pragma unroll
            for (int nj = 0; nj < 2; ++nj) {
                ldsm4t(bh[nj], &Xh[(ks + r16) * 264 + warp * 32 + nj * 16 + c8]);
                ldsm4t(bl[nj], &Xl[(ks + r16) * 264 + warp * 32 + nj * 16 + c8]);
            }
#pragma unroll
            for (int mi = 0; mi < 3; ++mi)
#pragma unroll
                for (int nj = 0; nj < 2; ++nj) {
                    mma16816(acc[mi][nj * 2],     ah[mi], &bh[nj][0]);
                    mma16816(acc[mi][nj * 2 + 1], ah[mi], &bh[nj][2]);
                    mma16816(acc[mi][nj * 2],     ah[mi], &bl[nj][0]);
                    mma16816(acc[mi][nj * 2 + 1], ah[mi], &bl[nj][2]);
                    mma16816(acc[mi][nj * 2],     al[mi], &bh[nj][0]);
                    mma16816(acc[mi][nj * 2 + 1], al[mi], &bh[nj][2]);
                }
        }
        __syncthreads();
    }

    float* __restrict__ Y = g_feat[t][n];
#pragma unroll
    for (int mi = 0; mi < 3; ++mi)
#pragma unroll
        for (int g = 0; g < 4; ++g) {
            int r0 = m0 + mi * 16 + (lane >> 2);
            int col = n0 + warp * 32 + (g >> 1) * 16 + (g & 1) * 8 + (lane & 3) * 2;
            if (r0 < CMID) {
                float bv = bias[r0];
                *(float2*)&Y[(size_t)r0 * HW + col] =
                    make_float2(acc[mi][g][0] + bv, acc[mi][g][1] + bv);
            }
            if (r0 + 8 < CMID) {
                float bv = bias[r0 + 8];
                *(float2*)&Y[(size_t)(r0 + 8) * HW + col] =
                    make_float2(acc[mi][g][2] + bv, acc[mi][g][3] + bv);
            }
        }
}

// ---------------- K2: InstanceNorm + LeakyReLU + mean-center ----------------
__global__ void inorm_kernel() {
    const int c = blockIdx.x, n = blockIdx.y, t = blockIdx.z;
    float* __restrict__ Y = &g_feat[t][n][(size_t)c * HW];
    __shared__ float sd[HW];
    __shared__ float r1[256], r2[256];
    const int tid = threadIdx.x;

    float s = 0.f, q = 0.f;
    for (int i = tid; i < HW; i += 256) { float v = Y[i]; sd[i] = v; s += v; q += v * v; }
    r1[tid] = s; r2[tid] = q; __syncthreads();
    for (int st = 128; st > 0; st >>= 1) {
        if (tid < st) { r1[tid] += r1[tid + st]; r2[tid] += r2[tid + st]; }
        __syncthreads();
    }
    const float mean = r1[0] * (1.f / HW);
    const float var  = r2[0] * (1.f / HW) - mean * mean;
    const float inv  = rsqrtf(var + 1e-5f);
    __syncthreads();

    float s2 = 0.f;
    for (int i = tid; i < HW; i += 256) {
        float v = (sd[i] - mean) * inv;
        v = (v >= 0.f) ? v : 0.2f * v;
        sd[i] = v; s2 += v;
    }
    r1[tid] = s2; __syncthreads();
    for (int st = 128; st > 0; st >>= 1) {
        if (tid < st) r1[tid] += r1[tid + st];
        __syncthreads();
    }
    const float mean2 = r1[0] * (1.f / HW);
    for (int i = tid; i < HW; i += 256) Y[i] = sd[i] - mean2;
}

// ---------------- K3: L2-normalize + split hi/lo (4 channel-groups per block) ----------------
__global__ void l2norm_kernel() {
    const int tid = threadIdx.x;
    const int px = tid & 63, cg = tid >> 6;
    const int p = blockIdx.x * 64 + px;
    const int n = blockIdx.y, t = blockIdx.z;
    const float* __restrict__ F = g_feat[t][n];
    __shared__ float red[4][64];

    const int cbeg = cg * 34, cend = cbeg + 34;
    float q = 0.f;
    for (int c = cbeg; c < cend; ++c) { float v = F[(size_t)c * HW + p]; q += v * v; }
    red[cg][px] = q;
    __syncthreads();
    const float inv = rsqrtf(red[0][px] + red[1][px] + red[2][px] + red[3][px]);

    __half* __restrict__ hi = g_fh[t][0][n];
    __half* __restrict__ lo = g_fh[t][1][n];
    for (int c = cbeg; c < cend; ++c) {
        float v = F[(size_t)c * HW + p] * inv;
        __half h = __float2half_rn(v);
        hi[(size_t)c * HW + p] = h;
        lo[(size_t)c * HW + p] = __float2half_rn(v - __half2float(h));
    }
}

// ---------------- K4: energy, 128x128 tile, 256 thr, 2 CTAs/SM (per-n) ----------------
#define E2_T   (48 * 136)
#define E2_STG (4 * E2_T)
__global__ __launch_bounds__(256, 2) void energy_mma_kernel(int n) {
    extern __shared__ __align__(16) __half eshm[];

    const int m0 = blockIdx.y * 128, l0 = blockIdx.x * 128;
    const int tid = threadIdx.x, lane = tid & 31, warp = tid >> 5;
    const int wm = warp & 3, wn = warp >> 2;
    const int r16 = lane & 15, c8 = (lane >> 4) << 3;
    const int arow = (lane & 7) + ((lane >> 4) & 1) * 8;
    const int acol = ((lane >> 3) & 1) * 8;

    float acc[2][8][4];
#pragma unroll
    for (int i = 0; i < 2; ++i)
#pragma unroll
        for (int j = 0; j < 8; ++j)
#pragma unroll
            for (int k = 0; k < 4; ++k) acc[i][j][k] = 0.f;

    const uint32_t su = smaddr(eshm);
    auto loadst = [&](int st, int q) {
        const int kc = q * 48;
        const uint32_t SB = su + st * E2_STG * 2;
#pragma unroll
        for (int i = 0; i < 12; ++i) {
            int idx = tid + i * 256;
            int tile = idx / 768, ix = idx % 768;
            int row = ix >> 4, cp = (ix & 15) * 8;
            const __half* src = (tile < 2)
                ? &g_fh[1][tile][n][(size_t)(kc + row) * HW + m0 + cp]
                : &g_fh[0][tile - 2][n][(size_t)(kc + row) * HW + l0 + cp];
            cpa16u(SB + (tile * E2_T + row * 136 + cp) * 2, src, 16);
        }
    };

    auto mmag2 = [&](uint32_t a[2][4], uint32_t b[4][4]) {
#pragma unroll
        for (int mi = 0; mi < 2; ++mi)
#pragma unroll
            for (int nj = 0; nj < 4; ++nj) {
                mma16816(acc[mi][nj * 2],     a[mi], &b[nj][0]);
                mma16816(acc[mi][nj * 2 + 1], a[mi], &b[nj][2]);
            }
    };

    loadst(0, 0); CP_COMMIT();
    loadst(1, 1); CP_COMMIT();
    for (int q = 0; q < 3; ++q) {
        const int st = q & 1;
        if (q == 2) CP_WAIT(0); else CP_WAIT(1);
        __syncthreads();
        const __half* Ah = eshm + st * E2_STG;
        const __half* Al = Ah + E2_T;
        const __half* Bh = Al + E2_T;
        const __half* Bl = Bh + E2_T;
#pragma unroll
        for (int ks = 0; ks < 48; ks += 16) {
            uint32_t ah[2][4], bh[4][4];
#pragma unroll
            for (int mi = 0; mi < 2; ++mi)
                ldsm4t(ah[mi], Ah + (ks + arow) * 136 + wm * 32 + mi * 16 + acol);
#pragma unroll
            for (int nj = 0; nj < 4; ++nj)
                ldsm4t(bh[nj], Bh + (ks + r16) * 136 + wn * 64 + nj * 16 + c8);
            mmag2(ah, bh);
            {
                uint32_t bl[4][4];
#pragma unroll
                for (int nj = 0; nj < 4; ++nj)
                    ldsm4t(bl[nj], Bl + (ks + r16) * 136 + wn * 64 + nj * 16 + c8);
                mmag2(ah, bl);
            }
            {
                uint32_t al[2][4];
#pragma unroll
                for (int mi = 0; mi < 2; ++mi)
                    ldsm4t(al[mi], Al + (ks + arow) * 136 + wm * 32 + mi * 16 + acol);
                mmag2(al, bh);
            }
        }
        __syncthreads();
        if (q + 2 < 3) { loadst(st, q + 2); CP_COMMIT(); }
    }

#pragma unroll
    for (int mi = 0; mi < 2; ++mi)
#pragma unroll
        for (int nj = 0; nj < 8; ++nj)
#pragma unroll
            for (int k = 0; k < 4; ++k) acc[mi][nj][k] *= 100.f;

    float* __restrict__ E = g_E[n];
#pragma unroll
    for (int mi = 0; mi < 2; ++mi)
#pragma unroll
        for (int nj = 0; nj < 8; ++nj) {
            int row = m0 + wm * 32 + mi * 16 + (lane >> 2);
            int col = l0 + wn * 64 + nj * 8 + (lane & 3) * 2;
            *(float2*)&E[(size_t)row * HW + col] = make_float2(acc[mi][nj][0], acc[mi][nj][1]);
            *(float2*)&E[(size_t)(row + 8) * HW + col] = make_float2(acc[mi][nj][2], acc[mi][nj][3]);
        }

    // ---- fused softmax partials ----
    float* sM   = (float*)eshm;
    float* sS   = sM + 256;
    float* cMax = sS + 256;
    float* cS   = cMax + 512;

#pragma unroll
    for (int mi = 0; mi < 2; ++mi)
#pragma unroll
        for (int h = 0; h < 2; ++h) {
            float m = -1e30f;
#pragma unroll
            for (int nj = 0; nj < 8; ++nj)
                m = fmaxf(m, fmaxf(acc[mi][nj][2 * h], acc[mi][nj][2 * h + 1]));
            m = fmaxf(m, __shfl_xor_sync(0xFFFFFFFFu, m, 1));
            m = fmaxf(m, __shfl_xor_sync(0xFFFFFFFFu, m, 2));
            float s = 0.f;
#pragma unroll
            for (int nj = 0; nj < 8; ++nj)
                s += __expf(acc[mi][nj][2 * h] - m) + __expf(acc[mi][nj][2 * h + 1] - m);
            s += __shfl_xor_sync(0xFFFFFFFFu, s, 1);
            s += __shfl_xor_sync(0xFFFFFFFFu, s, 2);
            if ((lane & 3) == 0) {
                int r = wm * 32 + mi * 16 + (lane >> 2) + 8 * h;
                sM[wn * 128 + r] = m;
                sS[wn * 128 + r] = s;
            }
        }
    float m16[8][2];
#pragma unroll
    for (int nj = 0; nj < 8; ++nj)
#pragma unroll
        for (int c = 0; c < 2; ++c) {
            float m = fmaxf(fmaxf(acc[0][nj][c], acc[0][nj][2 + c]),
                            fmaxf(acc[1][nj][c], acc[1][nj][2 + c]));
            m = fmaxf(m, __shfl_xor_sync(0xFFFFFFFFu, m, 4));
            m = fmaxf(m, __shfl_xor_sync(0xFFFFFFFFu, m, 8));
            m = fmaxf(m, __shfl_xor_sync(0xFFFFFFFFu, m, 16));
            m16[nj][c] = m;
        }
    if ((lane >> 2) == 0) {
#pragma unroll
        for (int nj = 0; nj < 8; ++nj)
#pragma unroll
            for (int c = 0; c < 2; ++c)
                cMax[wm * 128 + wn * 64 + nj * 8 + (lane & 3) * 2 + c] = m16[nj][c];
    }
    __syncthreads();

    if (tid < 128) {
        float M = sM[tid], S = sS[tid];
        float m2 = sM[128 + tid], s2 = sS[128 + tid];
        float M2 = fmaxf(M, m2);
        S = S * __expf(M - M2) + s2 * __expf(m2 - M2);
        M = M2;
        g_rowPm[n][blockIdx.x][m0 + tid] = M;
        g_rowPs[n][blockIdx.x][m0 + tid] = S;
        float C = fmaxf(fmaxf(cMax[tid], cMax[128 + tid]),
                        fmaxf(cMax[256 + tid], cMax[384 + tid]));
        cMax[tid] = C;
    }
    __syncthreads();

    float s16[8][2];
#pragma unroll
    for (int nj = 0; nj < 8; ++nj)
#pragma unroll
        for (int c = 0; c < 2; ++c) {
            float bm = cMax[wn * 64 + nj * 8 + (lane & 3) * 2 + c];
            float s = __expf(acc[0][nj][c] - bm) + __expf(acc[0][nj][2 + c] - bm)
                    + __expf(acc[1][nj][c] - bm) + __expf(acc[1][nj][2 + c] - bm);
            s += __shfl_xor_sync(0xFFFFFFFFu, s, 4);
            s += __shfl_xor_sync(0xFFFFFFFFu, s, 8);
            s += __shfl_xor_sync(0xFFFFFFFFu, s, 16);
            s16[nj][c] = s;
        }
    if ((lane >> 2) == 0) {
#pragma unroll
        for (int nj = 0; nj < 8; ++nj)
#pragma unroll
            for (int c = 0; c < 2; ++c)
                cS[wm * 128 + wn * 64 + nj * 8 + (lane & 3) * 2 + c] = s16[nj][c];
    }
    __syncthreads();
    if (tid < 128) {
        float S = cS[tid] + cS[128 + tid] + cS[256 + tid] + cS[384 + tid];
        g_colPm[n][blockIdx.y][l0 + tid] = cMax[tid];
        g_colPs[n][blockIdx.y][l0 + tid] = S;
    }
}

// ---------------- K5: combine partial stats (per-n; y: 0=row 1=col) ----------------
__global__ void combine_kernel(int n) {
    const int i = blockIdx.x * 256 + threadIdx.x;
    float M = -1e30f, S = 0.f;
    if (blockIdx.y == 0) {
#pragma unroll
        for (int b = 0; b < 32; ++b) {
            float m = g_rowPm[n][b][i], s = g_rowPs[n][b][i];
            float M2 = fmaxf(M, m);
            S = S * __expf(M - M2) + s * __expf(m - M2);
            M = M2;
        }
        g_rowM[n][i] = M;
        g_rowSinv[n][i] = 1.0f / S;
    } else {
#pragma unroll
        for (int b = 0; b < 32; ++b) {
            float m = g_colPm[n][b][i], s = g_colPs[n][b][i];
            float M2 = fmaxf(M, m);
            S = S * __expf(M - M2) + s * __expf(m - M2);
            M = M2;
        }
        g_colM[n][i] = M;
        g_colSinv[n][i] = 1.0f / S;
    }
}

// ---------------- K6: softmax writeout, vectorized (per-n) ----------------
__global__ void writeout_kernel(int n, float* __restrict__ out_ab, float* __restrict__ out_ba) {
    const int c0 = blockIdx.x * 64, r0 = blockIdx.y * 64;
    const int tid = threadIdx.x;
    const int tx = tid & 15, ty = tid >> 4;
    const float* __restrict__ E = g_E[n];
    __half* __restrict__ Hab = g_corr_h[0][n];
    __half* __restrict__ Hba = g_corr_h[1][n];
    float* __restrict__ Oab = out_ab + (size_t)n * HW * HW;
    float* __restrict__ Oba = out_ba + (size_t)n * HW * HW;

    __shared__ float t_ba[64][68];
    __shared__ float rm_s[64], rsi_s[64];
    if (tid < 64)       rm_s[tid]       = g_rowM[n][r0 + tid];
    else if (tid < 128) rsi_s[tid - 64] = g_rowSinv[n][r0 + tid - 64];
    const float4 cm4  = *(const float4*)&g_colM[n][c0 + tx * 4];
    const float4 csi4 = *(const float4*)&g_colSinv[n][c0 + tx * 4];
    __syncthreads();

#pragma unroll
    for (int it = 0; it < 4; ++it) {
        int r_in = it * 16 + ty;
        int R = r0 + r_in;
        float4 e = *(const float4*)&E[(size_t)R * HW + c0 + tx * 4];
        float rm = rm_s[r_in], rsi = rsi_s[r_in];
        float4 pr = make_float4(__expf(e.x - rm) * rsi, __expf(e.y - rm) * rsi,
                                __expf(e.z - rm) * rsi, __expf(e.w - rm) * rsi);
        float pc0 = __expf(e.x - cm4.x) * csi4.x;
        float pc1 = __expf(e.y - cm4.y) * csi4.y;
        float pc2 = __expf(e.z - cm4.z) * csi4.z;
        float pc3 = __expf(e.w - cm4.w) * csi4.w;
        size_t off = (size_t)R * HW + c0 + tx * 4;
        *(float4*)&Oab[off] = pr;
        __half2 h0 = __floats2half2_rn(pr.x, pr.y);
        __half2 h1 = __floats2half2_rn(pr.z, pr.w);
        *(uint2*)&Hab[off] = make_uint2(*(uint32_t*)&h0, *(uint32_t*)&h1);
        t_ba[tx * 4 + 0][r_in] = pc0;
        t_ba[tx * 4 + 1][r_in] = pc1;
        t_ba[tx * 4 + 2][r_in] = pc2;
        t_ba[tx * 4 + 3][r_in] = pc3;
    }
    __syncthreads();
#pragma unroll
    for (int it = 0; it < 4; ++it) {
        int c_in = it * 16 + ty;
        float4 p = *(const float4*)&t_ba[c_in][tx * 4];
        size_t off = (size_t)(c0 + c_in) * HW + r0 + tx * 4;
        *(float4*)&Oba[off] = p;
        __half2 h0 = __floats2half2_rn(p.x, p.y);
        __half2 h1 = __floats2half2_rn(p.z, p.w);
        *(uint2*)&Hba[off] = make_uint2(*(uint32_t*)&h0, *(uint32_t*)&h1);
    }
}

// ---------------- K7: raw -> fp16 ----------------
__global__ void tohalf_kernel(const float* __restrict__ a_raw, const float* __restrict__ b_raw) {
    const int t = blockIdx.y;
    const float* __restrict__ src = (t == 0 ? a_raw : b_raw);
    __half* __restrict__ dst = &g_raw_h[t][0][0];
    size_t i = ((size_t)blockIdx.x * 256 + threadIdx.x) * 4;
    float4 v = *(const float4*)&src[i];
    __half2* d2 = (__half2*)&dst[i];
    d2[0] = __floats2half2_rn(v.x, v.y);
    d2[1] = __floats2half2_rn(v.z, v.w);
}

// ---------------- K8: warp matmul, 128x128 tile, 256 thr, 2 CTAs/SM, 3-stage (per-n) ----------------
#define G2_AST (128 * 72)
#define G2_BST (64 * 136)
#define G2_NC 64
__global__ __launch_bounds__(256, 2) void wgemm_kernel(int n, float* __restrict__ out) {
    extern __shared__ __align__(16) __half gshm[];
    __half* As = gshm;
    __half* Bs = gshm + 3 * G2_AST;
    const uint32_t su = smaddr(gshm);

    const int dir = blockIdx.z;
    const __half* __restrict__ A = g_raw_h[dir][n];
    const __half* __restrict__ B = g_corr_h[dir ^ 1][n];
    float* __restrict__ C = out + (size_t)4 * HW * HW
                                + (size_t)dir * 2 * CIN * HW + (size_t)n * CIN * HW;
    const int m0 = blockIdx.y * 128, n0 = blockIdx.x * 128;
    const int tid = threadIdx.x, lane = tid & 31, warp = tid >> 5;
    const int wm = warp & 3, wn = warp >> 2;
    const int r16 = lane & 15, c8 = (lane >> 4) << 3;

    float acc[2][8][4];
#pragma unroll
    for (int i = 0; i < 2; ++i)
#pragma unroll
        for (int j = 0; j < 8; ++j)
#pragma unroll
            for (int k = 0; k < 4; ++k) acc[i][j][k] = 0.f;

    auto loadst = [&](int st, int j) {
        const int k0 = j * 64;
#pragma unroll
        for (int i = 0; i < 8; ++i) {
            int idx = tid + i * 256;
            if (idx < 1024) {
                int row = idx >> 3, cp = (idx & 7) * 8;
                int gr = m0 + row;
                int ok = gr < CIN;
                cpa16u(su + (st * G2_AST + row * 72 + cp) * 2,
                       &A[(size_t)(ok ? gr : 0) * HW + k0 + cp], ok ? 16 : 0);
            } else {
                int ix = idx - 1024;
                int row = ix >> 4, cp = (ix & 15) * 8;
                cpa16u(su + (3 * G2_AST + st * G2_BST + row * 136 + cp) * 2,
                       &B[(size_t)(k0 + row) * HW + n0 + cp], 16);
            }
        }
    };

    loadst(0, 0); CP_COMMIT();
    loadst(1, 1); CP_COMMIT();

    for (int j = 0; j < G2_NC; ++j) {
        const int st = j % 3;
        if (j + 1 < G2_NC) CP_WAIT(1); else CP_WAIT(0);
        __syncthreads();
        if (j + 2 < G2_NC) { loadst((j + 2) % 3, j + 2); CP_COMMIT(); }

#pragma unroll
        for (int ks = 0; ks < 64; ks += 16) {
            uint32_t a[2][4], b[4][4];
#pragma unroll
            for (int mi = 0; mi < 2; ++mi)
                ldsm4(a[mi], As + st * G2_AST + (wm * 32 + mi * 16 + r16) * 72 + ks + c8);
#pragma unroll
            for (int nj = 0; nj < 4; ++nj)
                ldsm4t(b[nj], Bs + st * G2_BST + (ks + r16) * 136 + wn * 64 + nj * 16 + c8);
#pragma unroll
            for (int mi = 0; mi < 2; ++mi)
#pragma unroll
                for (int nj = 0; nj < 4; ++nj) {
                    mma16816(acc[mi][nj * 2],     a[mi], &b[nj][0]);
                    mma16816(acc[mi][nj * 2 + 1], a[mi], &b[nj][2]);
                }
        }
        __syncthreads();
    }

#pragma unroll
    for (int mi = 0; mi < 2; ++mi)
#pragma unroll
        for (int nj = 0; nj < 8; ++nj) {
            int row = m0 + wm * 32 + mi * 16 + (lane >> 2);
            int col = n0 + wn * 64 + nj * 8 + (lane & 3) * 2;
            if (row < CIN)
                *(float2*)&C[(size_t)row * HW + col] = make_float2(acc[mi][nj][0], acc[mi][nj][1]);
            if (row + 8 < CIN)
                *(float2*)&C[(size_t)(row + 8) * HW + col] = make_float2(acc[mi][nj][2], acc[mi][nj][3]);
        }
}

// ---------------- launch ----------------
extern "C" void kernel_launch(void* const* d_in, const int* in_sizes, int n_in,
                              void* d_out, int out_size) {
    const float* fa    = (const float*)d_in[0];
    const float* fb    = (const float*)d_in[1];
    const float* a_raw = (const float*)d_in[2];
    const float* b_raw = (const float*)d_in[3];
    const float* Wa    = (const float*)d_in[4];
    const float* ba    = (const float*)d_in[5];
    const float* Wb    = (const float*)d_in[6];
    const float* bb    = (const float*)d_in[7];
    float* out = (float*)d_out;
    float* out_ab = out;
    float* out_ba = out + (size_t)2 * HW * HW;

    const int c_smem = 32 * 256 * 4 + 48 * 32 * 4 + 2 * 32 * 264 * 2 + 2 * 48 * 40 * 2; // 80384
    const int e_smem = 2 * E2_STG * 2;                   // 104448
    const int g_smem = 3 * (G2_AST + G2_BST) * 2;        // 107520
    cudaFuncSetAttribute(conv_mma_kernel, cudaFuncAttributeMaxDynamicSharedMemorySize, c_smem);
    cudaFuncSetAttribute(energy_mma_kernel, cudaFuncAttributeMaxDynamicSharedMemorySize, e_smem);
    cudaFuncSetAttribute(wgemm_kernel, cudaFuncAttributeMaxDynamicSharedMemorySize, g_smem);

    // ONE extra stream (proven capture-safe in R10-R13); the n=1 chain rides it.
    cudaStream_t s2;
    cudaStreamCreate(&s2);
    cudaEvent_t ef, ej, eL, eB;
    cudaEventCreateWithFlags(&ef, cudaEventDisableTiming);
    cudaEventCreateWithFlags(&ej, cudaEventDisableTiming);
    cudaEventCreateWithFlags(&eL, cudaEventDisableTiming);
    cudaEventCreateWithFlags(&eB, cudaEventDisableTiming);

    // fork: tohalf first on s2 (independent of conv chain)
    cudaEventRecord(ef, 0);
    cudaStreamWaitEvent(s2, ef, 0);
    tohalf_kernel<<<dim3(8704, 2), 256, 0, s2>>>(a_raw, b_raw);
    cudaEventRecord(ej, s2);

    // shared prefix on stream 0
    conv_mma_kernel<<<dim3(16, 3, 4), 256, c_smem>>>(fa, fb, Wa, ba, Wb, bb);
    inorm_kernel<<<dim3(CMID, 2, 2), 256>>>();
    l2norm_kernel<<<dim3(HW / 64, 2, 2), 256>>>();
    cudaEventRecord(eL, 0);

    // n=1 chain on s2 (tohalf already done there by stream order)
    cudaStreamWaitEvent(s2, eL, 0);
    energy_mma_kernel<<<dim3(32, 32), 256, e_smem, s2>>>(1);
    combine_kernel<<<dim3(HW / 256, 2), 256, 0, s2>>>(1);
    writeout_kernel<<<dim3(64, 64), 256, 0, s2>>>(1, out_ab, out_ba);
    wgemm_kernel<<<dim3(32, 9, 2), 256, g_smem, s2>>>(1, out);
    cudaEventRecord(eB, s2);

    // n=0 chain on stream 0
    energy_mma_kernel<<<dim3(32, 32), 256, e_smem>>>(0);
    combine_kernel<<<dim3(HW / 256, 2), 256>>>(0);
    writeout_kernel<<<dim3(64, 64), 256>>>(0, out_ab, out_ba);
    cudaStreamWaitEvent(0, ej, 0);
    wgemm_kernel<<<dim3(32, 9, 2), 256, g_smem>>>(0, out);

    // join
    cudaStreamWaitEvent(0, eB, 0);
}

// round 16
// speedup vs baseline: 2.1020x; 1.0410x over previous
#include <cuda_runtime.h>
#include <cuda_fp16.h>
#include <cstdint>
#include <cstddef>

#define HW 4096
#define CIN 1088
#define CMID 136
#define CPAD 144

// ---------------- scratch (device globals; zero-initialized, no allocs) ----------------
__device__ float  g_feat[2][2][(size_t)CMID * HW];        // [a/b][n][c*HW+p]
__device__ float  g_E[2][(size_t)HW * HW];                // energy (already *100)
__device__ __half g_corr_h[2][2][(size_t)HW * HW];        // fp16 corr, [ab/ba][n], [k][l]
__device__ __half g_raw_h[2][2][(size_t)CIN * HW];        // [a/b][n]
__device__ __half g_fh[2][2][2][(size_t)CPAD * HW];       // [a/b][hi/lo][n], [c][p]
__device__ float  g_rowM[2][HW], g_rowSinv[2][HW];
__device__ float  g_colM[2][HW], g_colSinv[2][HW];
__device__ float  g_rowPm[2][32][HW],  g_rowPs[2][32][HW];
__device__ float  g_colPm[2][32][HW],  g_colPs[2][32][HW];

// ---------------- PTX helpers ----------------
__device__ __forceinline__ uint32_t smaddr(const void* p) {
    return (uint32_t)__cvta_generic_to_shared(p);
}
__device__ __forceinline__ void ldsm4(uint32_t r[4], const void* p) {
    asm volatile("ldmatrix.sync.aligned.m8n8.x4.shared.b16 {%0,%1,%2,%3}, [%4];\n"
                 : "=r"(r[0]), "=r"(r[1]), "=r"(r[2]), "=r"(r[3]) : "r"(smaddr(p)));
}
__device__ __forceinline__ void ldsm4t(uint32_t r[4], const void* p) {
    asm volatile("ldmatrix.sync.aligned.m8n8.x4.trans.shared.b16 {%0,%1,%2,%3}, [%4];\n"
                 : "=r"(r[0]), "=r"(r[1]), "=r"(r[2]), "=r"(r[3]) : "r"(smaddr(p)));
}
__device__ __forceinline__ void mma16816(float* d, const uint32_t* a, const uint32_t* b) {
    asm volatile("mma.sync.aligned.m16n8k16.row.col.f32.f16.f16.f32 "
                 "{%0,%1,%2,%3}, {%4,%5,%6,%7}, {%8,%9}, {%0,%1,%2,%3};\n"
                 : "+f"(d[0]), "+f"(d[1]), "+f"(d[2]), "+f"(d[3])
                 : "r"(a[0]), "r"(a[1]), "r"(a[2]), "r"(a[3]), "r"(b[0]), "r"(b[1]));
}
__device__ __forceinline__ void cpa16u(uint32_t sm, const void* g, int bytes) {
    asm volatile("cp.async.cg.shared.global [%0], [%1], 16, %2;\n"
                 :: "r"(sm), "l"(g), "r"(bytes));
}
#define CP_COMMIT() asm volatile("cp.async.commit_group;\n" ::: "memory")
#define CP_WAIT(n)  asm volatile("cp.async.wait_group %0;\n" :: "n"(n) : "memory")

// ---------------- K1: 1x1 conv via split-fp16 HMMA (per-n; z = tensor) ----------------
__global__ __launch_bounds__(256, 2) void conv_mma_kernel(
    int n,
    const float* __restrict__ fa, const float* __restrict__ fb,
    const float* __restrict__ Wa, const float* __restrict__ ba,
    const float* __restrict__ Wb, const float* __restrict__ bb) {
    extern __shared__ __align__(16) char csm[];
    float*  Xf  = (float*)csm;
    float*  Wf  = Xf + 32 * 256;
    __half* Xhl = (__half*)(Wf + 48 * 32);
    __half* Whl = Xhl + 2 * 32 * 264;

    const int t = blockIdx.z;
    const float* __restrict__ X = (t == 0 ? fa : fb) + (size_t)n * CIN * HW;
    const float* __restrict__ W = (t == 0 ? Wa : Wb);
    const float* __restrict__ bias = (t == 0 ? ba : bb);
    const int m0 = blockIdx.y * 48, n0 = blockIdx.x * 256;
    const int tid = threadIdx.x, lane = tid & 31, warp = tid >> 5;
    const int r16 = lane & 15, c8 = (lane >> 4) << 3;

    float acc[3][4][4];
#pragma unroll
    for (int i = 0; i < 3; ++i)
#pragma unroll
        for (int j = 0; j < 4; ++j)
#pragma unroll
            for (int k = 0; k < 4; ++k) acc[i][j][k] = 0.f;

    auto cpX = [&](int kc) {
#pragma unroll
        for (int i = 0; i < 8; ++i) {
            int idx = tid + i * 256;
            int row = idx >> 6, seg = (idx & 63) * 4;
            cpa16u(smaddr(&Xf[row * 256 + seg]), &X[(size_t)(kc + row) * HW + n0 + seg], 16);
        }
#pragma unroll
        for (int i = 0; i < 2; ++i) {
            int idx = tid + i * 256;
            if (idx < 384) {
                int row = idx >> 3, seg = (idx & 7) * 4;
                int o = m0 + row;
                int ok = o < CMID;
                cpa16u(smaddr(&Wf[row * 32 + seg]), &W[(size_t)(ok ? o : 0) * CIN + kc + seg], ok ? 16 : 0);
            }
        }
    };
    auto convert = [&]() {
        __half* Xh = Xhl;
        __half* Xl = Xh + 32 * 264;
#pragma unroll
        for (int i = 0; i < 32; ++i) {
            int idx = tid + i * 256;
            int row = idx >> 8, col = idx & 255;
            float v = Xf[row * 256 + col];
            __half h = __float2half_rn(v);
            Xh[row * 264 + col] = h;
            Xl[row * 264 + col] = __float2half_rn(v - __half2float(h));
        }
        __half* Wh = Whl;
        __half* Wl = Wh + 48 * 40;
#pragma unroll
        for (int i = 0; i < 6; ++i) {
            int idx = tid + i * 256;
            if (idx < 1536) {
                int row = idx >> 5, col = idx & 31;
                float v = Wf[row * 32 + col];
                __half h = __float2half_rn(v);
                Wh[row * 40 + col] = h;
                Wl[row * 40 + col] = __float2half_rn(v - __half2float(h));
            }
        }
    };

    cpX(0); CP_COMMIT();
    for (int j = 0; j < 34; ++j) {
        CP_WAIT(0);
        __syncthreads();
        convert();
        __syncthreads();
        if (j + 1 < 34) cpX((j + 1) * 32);
        CP_COMMIT();

        const __half* Xh = Xhl;
        const __half* Xl = Xh + 32 * 264;
        const __half* Wh = Whl;
        const __half* Wl = Wh + 48 * 40;
#pragma unroll
        for (int ks = 0; ks < 32; ks += 16) {
            uint32_t ah[3][4], al[3][4], bh[2][4], bl[2][4];
#pragma unroll
            for (int mi = 0; mi < 3; ++mi) {
                ldsm4(ah[mi], &Wh[(mi * 16 + r16) * 40 + ks + c8]);
                ldsm4(al[mi], &Wl[(mi * 16 + r16) * 40 + ks + c8]);
            }
#pragma unroll
            for (int nj = 0; nj < 2; ++nj) {
                ldsm4t(bh[nj], &Xh[(ks + r16) * 264 + warp * 32 + nj * 16 + c8]);
                ldsm4t(bl[nj], &Xl[(ks + r16) * 264 + warp * 32 + nj * 16 + c8]);
            }
#pragma unroll
            for (int mi = 0; mi < 3; ++mi)
#pragma unroll
                for (int nj = 0; nj < 2; ++nj) {
                    mma16816(acc[mi][nj * 2],     ah[mi], &bh[nj][0]);
                    mma16816(acc[mi][nj * 2 + 1], ah[mi], &bh[nj][2]);
                    mma16816(acc[mi][nj * 2],     ah[mi], &bl[nj][0]);
                    mma16816(acc[mi][nj * 2 + 1], ah[mi], &bl[nj][2]);
                    mma16816(acc[mi][nj * 2],     al[mi], &bh[nj][0]);
                    mma16816(acc[mi][nj * 2 + 1], al[mi], &bh[nj][2]);
                }
        }
        __syncthreads();
    }

    float* __restrict__ Y = g_feat[t][n];
#pragma unroll
    for (int mi = 0; mi < 3; ++mi)
#pragma unroll
        for (int g = 0; g < 4; ++g) {
            int r0 = m0 + mi * 16 + (lane >> 2);
            int col = n0 + warp * 32 + (g >> 1) * 16 + (g & 1) * 8 + (lane & 3) * 2;
            if (r0 < CMID) {
                float bv = bias[r0];
                *(float2*)&Y[(size_t)r0 * HW + col] =
                    make_float2(acc[mi][g][0] + bv, acc[mi][g][1] + bv);
            }
            if (r0 + 8 < CMID) {
                float bv = bias[r0 + 8];
                *(float2*)&Y[(size_t)(r0 + 8) * HW + col] =
                    make_float2(acc[mi][g][2] + bv, acc[mi][g][3] + bv);
            }
        }
}

// ---------------- K2: InstanceNorm + LeakyReLU + mean-center (per-n; y = tensor) ----------------
__global__ void inorm_kernel(int n) {
    const int c = blockIdx.x, t = blockIdx.y;
    float* __restrict__ Y = &g_feat[t][n][(size_t)c * HW];
    __shared__ float sd[HW];
    __shared__ float r1[256], r2[256];
    const int tid = threadIdx.x;

    float s = 0.f, q = 0.f;
    for (int i = tid; i < HW; i += 256) { float v = Y[i]; sd[i] = v; s += v; q += v * v; }
    r1[tid] = s; r2[tid] = q; __syncthreads();
    for (int st = 128; st > 0; st >>= 1) {
        if (tid < st) { r1[tid] += r1[tid + st]; r2[tid] += r2[tid + st]; }
        __syncthreads();
    }
    const float mean = r1[0] * (1.f / HW);
    const float var  = r2[0] * (1.f / HW) - mean * mean;
    const float inv  = rsqrtf(var + 1e-5f);
    __syncthreads();

    float s2 = 0.f;
    for (int i = tid; i < HW; i += 256) {
        float v = (sd[i] - mean) * inv;
        v = (v >= 0.f) ? v : 0.2f * v;
        sd[i] = v; s2 += v;
    }
    r1[tid] = s2; __syncthreads();
    for (int st = 128; st > 0; st >>= 1) {
        if (tid < st) r1[tid] += r1[tid + st];
        __syncthreads();
    }
    const float mean2 = r1[0] * (1.f / HW);
    for (int i = tid; i < HW; i += 256) Y[i] = sd[i] - mean2;
}

// ---------------- K3: L2-normalize + split hi/lo (per-n; y = tensor) ----------------
__global__ void l2norm_kernel(int n) {
    const int tid = threadIdx.x;
    const int px = tid & 63, cg = tid >> 6;
    const int p = blockIdx.x * 64 + px;
    const int t = blockIdx.y;
    const float* __restrict__ F = g_feat[t][n];
    __shared__ float red[4][64];

    const int cbeg = cg * 34, cend = cbeg + 34;
    float q = 0.f;
    for (int c = cbeg; c < cend; ++c) { float v = F[(size_t)c * HW + p]; q += v * v; }
    red[cg][px] = q;
    __syncthreads();
    const float inv = rsqrtf(red[0][px] + red[1][px] + red[2][px] + red[3][px]);

    __half* __restrict__ hi = g_fh[t][0][n];
    __half* __restrict__ lo = g_fh[t][1][n];
    for (int c = cbeg; c < cend; ++c) {
        float v = F[(size_t)c * HW + p] * inv;
        __half h = __float2half_rn(v);
        hi[(size_t)c * HW + p] = h;
        lo[(size_t)c * HW + p] = __float2half_rn(v - __half2float(h));
    }
}

// ---------------- K4: energy, 128x128 tile, 256 thr, 2 CTAs/SM (per-n) ----------------
#define E2_T   (48 * 136)
#define E2_STG (4 * E2_T)
__global__ __launch_bounds__(256, 2) void energy_mma_kernel(int n) {
    extern __shared__ __align__(16) __half eshm[];

    const int m0 = blockIdx.y * 128, l0 = blockIdx.x * 128;
    const int tid = threadIdx.x, lane = tid & 31, warp = tid >> 5;
    const int wm = warp & 3, wn = warp >> 2;
    const int r16 = lane & 15, c8 = (lane >> 4) << 3;
    const int arow = (lane & 7) + ((lane >> 4) & 1) * 8;
    const int acol = ((lane >> 3) & 1) * 8;

    float acc[2][8][4];
#pragma unroll
    for (int i = 0; i < 2; ++i)
#pragma unroll
        for (int j = 0; j < 8; ++j)
#pragma unroll
            for (int k = 0; k < 4; ++k) acc[i][j][k] = 0.f;

    const uint32_t su = smaddr(eshm);
    auto loadst = [&](int st, int q) {
        const int kc = q * 48;
        const uint32_t SB = su + st * E2_STG * 2;
#pragma unroll
        for (int i = 0; i < 12; ++i) {
            int idx = tid + i * 256;
            int tile = idx / 768, ix = idx % 768;
            int row = ix >> 4, cp = (ix & 15) * 8;
            const __half* src = (tile < 2)
                ? &g_fh[1][tile][n][(size_t)(kc + row) * HW + m0 + cp]
                : &g_fh[0][tile - 2][n][(size_t)(kc + row) * HW + l0 + cp];
            cpa16u(SB + (tile * E2_T + row * 136 + cp) * 2, src, 16);
        }
    };

    auto mmag2 = [&](uint32_t a[2][4], uint32_t b[4][4]) {
#pragma unroll
        for (int mi = 0; mi < 2; ++mi)
#pragma unroll
            for (int nj = 0; nj < 4; ++nj) {
                mma16816(acc[mi][nj * 2],     a[mi], &b[nj][0]);
                mma16816(acc[mi][nj * 2 + 1], a[mi], &b[nj][2]);
            }
    };

    loadst(0, 0); CP_COMMIT();
    loadst(1, 1); CP_COMMIT();
    for (int q = 0; q < 3; ++q) {
        const int st = q & 1;
        if (q == 2) CP_WAIT(0); else CP_WAIT(1);
        __syncthreads();
        const __half* Ah = eshm + st * E2_STG;
        const __half* Al = Ah + E2_T;
        const __half* Bh = Al + E2_T;
        const __half* Bl = Bh + E2_T;
#pragma unroll
        for (int ks = 0; ks < 48; ks += 16) {
            uint32_t ah[2][4], bh[4][4];
#pragma unroll
            for (int mi = 0; mi < 2; ++mi)
                ldsm4t(ah[mi], Ah + (ks + arow) * 136 + wm * 32 + mi * 16 + acol);
#pragma unroll
            for (int nj = 0; nj < 4; ++nj)
                ldsm4t(bh[nj], Bh + (ks + r16) * 136 + wn * 64 + nj * 16 + c8);
            mmag2(ah, bh);
            {
                uint32_t bl[4][4];
#pragma unroll
                for (int nj = 0; nj < 4; ++nj)
                    ldsm4t(bl[nj], Bl + (ks + r16) * 136 + wn * 64 + nj * 16 + c8);
                mmag2(ah, bl);
            }
            {
                uint32_t al[2][4];
#pragma unroll
                for (int mi = 0; mi < 2; ++mi)
                    ldsm4t(al[mi], Al + (ks + arow) * 136 + wm * 32 + mi * 16 + acol);
                mmag2(al, bh);
            }
        }
        __syncthreads();
        if (q + 2 < 3) { loadst(st, q + 2); CP_COMMIT(); }
    }

#pragma unroll
    for (int mi = 0; mi < 2; ++mi)
#pragma unroll
        for (int nj = 0; nj < 8; ++nj)
#pragma unroll
            for (int k = 0; k < 4; ++k) acc[mi][nj][k] *= 100.f;

    float* __restrict__ E = g_E[n];
#pragma unroll
    for (int mi = 0; mi < 2; ++mi)
#pragma unroll
        for (int nj = 0; nj < 8; ++nj) {
            int row = m0 + wm * 32 + mi * 16 + (lane >> 2);
            int col = l0 + wn * 64 + nj * 8 + (lane & 3) * 2;
            *(float2*)&E[(size_t)row * HW + col] = make_float2(acc[mi][nj][0], acc[mi][nj][1]);
            *(float2*)&E[(size_t)(row + 8) * HW + col] = make_float2(acc[mi][nj][2], acc[mi][nj][3]);
        }

    // ---- fused softmax partials ----
    float* sM   = (float*)eshm;
    float* sS   = sM + 256;
    float* cMax = sS + 256;
    float* cS   = cMax + 512;

#pragma unroll
    for (int mi = 0; mi < 2; ++mi)
#pragma unroll
        for (int h = 0; h < 2; ++h) {
            float m = -1e30f;
#pragma unroll
            for (int nj = 0; nj < 8; ++nj)
                m = fmaxf(m, fmaxf(acc[mi][nj][2 * h], acc[mi][nj][2 * h + 1]));
            m = fmaxf(m, __shfl_xor_sync(0xFFFFFFFFu, m, 1));
            m = fmaxf(m, __shfl_xor_sync(0xFFFFFFFFu, m, 2));
            float s = 0.f;
#pragma unroll
            for (int nj = 0; nj < 8; ++nj)
                s += __expf(acc[mi][nj][2 * h] - m) + __expf(acc[mi][nj][2 * h + 1] - m);
            s += __shfl_xor_sync(0xFFFFFFFFu, s, 1);
            s += __shfl_xor_sync(0xFFFFFFFFu, s, 2);
            if ((lane & 3) == 0) {
                int r = wm * 32 + mi * 16 + (lane >> 2) + 8 * h;
                sM[wn * 128 + r] = m;
                sS[wn * 128 + r] = s;
            }
        }
    float m16[8][2];
#pragma unroll
    for (int nj = 0; nj < 8; ++nj)
#pragma unroll
        for (int c = 0; c < 2; ++c) {
            float m = fmaxf(fmaxf(acc[0][nj][c], acc[0][nj][2 + c]),
                            fmaxf(acc[1][nj][c], acc[1][nj][2 + c]));
            m = fmaxf(m, __shfl_xor_sync(0xFFFFFFFFu, m, 4));
            m = fmaxf(m, __shfl_xor_sync(0xFFFFFFFFu, m, 8));
            m = fmaxf(m, __shfl_xor_sync(0xFFFFFFFFu, m, 16));
            m16[nj][c] = m;
        }
    if ((lane >> 2) == 0) {
#pragma unroll
        for (int nj = 0; nj < 8; ++nj)
#pragma unroll
            for (int c = 0; c < 2; ++c)
                cMax[wm * 128 + wn * 64 + nj * 8 + (lane & 3) * 2 + c] = m16[nj][c];
    }
    __syncthreads();

    if (tid < 128) {
        float M = sM[tid], S = sS[tid];
        float m2 = sM[128 + tid], s2 = sS[128 + tid];
        float M2 = fmaxf(M, m2);
        S = S * __expf(M - M2) + s2 * __expf(m2 - M2);
        M = M2;
        g_rowPm[n][blockIdx.x][m0 + tid] = M;
        g_rowPs[n][blockIdx.x][m0 + tid] = S;
        float C = fmaxf(fmaxf(cMax[tid], cMax[128 + tid]),
                        fmaxf(cMax[256 + tid], cMax[384 + tid]));
        cMax[tid] = C;
    }
    __syncthreads();

    float s16[8][2];
#pragma unroll
    for (int nj = 0; nj < 8; ++nj)
#pragma unroll
        for (int c = 0; c < 2; ++c) {
            float bm = cMax[wn * 64 + nj * 8 + (lane & 3) * 2 + c];
            float s = __expf(acc[0][nj][c] - bm) + __expf(acc[0][nj][2 + c] - bm)
                    + __expf(acc[1][nj][c] - bm) + __expf(acc[1][nj][2 + c] - bm);
            s += __shfl_xor_sync(0xFFFFFFFFu, s, 4);
            s += __shfl_xor_sync(0xFFFFFFFFu, s, 8);
            s += __shfl_xor_sync(0xFFFFFFFFu, s, 16);
            s16[nj][c] = s;
        }
    if ((lane >> 2) == 0) {
#pragma unroll
        for (int nj = 0; nj < 8; ++nj)
#pragma unroll
            for (int c = 0; c < 2; ++c)
                cS[wm * 128 + wn * 64 + nj * 8 + (lane & 3) * 2 + c] = s16[nj][c];
    }
    __syncthreads();
    if (tid < 128) {
        float S = cS[tid] + cS[128 + tid] + cS[256 + tid] + cS[384 + tid];
        g_colPm[n][blockIdx.y][l0 + tid] = cMax[tid];
        g_colPs[n][blockIdx.y][l0 + tid] = S;
    }
}

// ---------------- K5: combine partial stats (per-n; y: 0=row 1=col) ----------------
__global__ void combine_kernel(int n) {
    const int i = blockIdx.x * 256 + threadIdx.x;
    float M = -1e30f, S = 0.f;
    if (blockIdx.y == 0) {
#pragma unroll
        for (int b = 0; b < 32; ++b) {
            float m = g_rowPm[n][b][i], s = g_rowPs[n][b][i];
            float M2 = fmaxf(M, m);
            S = S * __expf(M - M2) + s * __expf(m - M2);
            M = M2;
        }
        g_rowM[n][i] = M;
        g_rowSinv[n][i] = 1.0f / S;
    } else {
#pragma unroll
        for (int b = 0; b < 32; ++b) {
            float m = g_colPm[n][b][i], s = g_colPs[n][b][i];
            float M2 = fmaxf(M, m);
            S = S * __expf(M - M2) + s * __expf(m - M2);
            M = M2;
        }
        g_colM[n][i] = M;
        g_colSinv[n][i] = 1.0f / S;
    }
}

// ---------------- K6: softmax writeout, vectorized (per-n) ----------------
__global__ void writeout_kernel(int n, float* __restrict__ out_ab, float* __restrict__ out_ba) {
    const int c0 = blockIdx.x * 64, r0 = blockIdx.y * 64;
    const int tid = threadIdx.x;
    const int tx = tid & 15, ty = tid >> 4;
    const float* __restrict__ E = g_E[n];
    __half* __restrict__ Hab = g_corr_h[0][n];
    __half* __restrict__ Hba = g_corr_h[1][n];
    float* __restrict__ Oab = out_ab + (size_t)n * HW * HW;
    float* __restrict__ Oba = out_ba + (size_t)n * HW * HW;

    __shared__ float t_ba[64][68];
    __shared__ float rm_s[64], rsi_s[64];
    if (tid < 64)       rm_s[tid]       = g_rowM[n][r0 + tid];
    else if (tid < 128) rsi_s[tid - 64] = g_rowSinv[n][r0 + tid - 64];
    const float4 cm4  = *(const float4*)&g_colM[n][c0 + tx * 4];
    const float4 csi4 = *(const float4*)&g_colSinv[n][c0 + tx * 4];
    __syncthreads();

#pragma unroll
    for (int it = 0; it < 4; ++it) {
        int r_in = it * 16 + ty;
        int R = r0 + r_in;
        float4 e = *(const float4*)&E[(size_t)R * HW + c0 + tx * 4];
        float rm = rm_s[r_in], rsi = rsi_s[r_in];
        float4 pr = make_float4(__expf(e.x - rm) * rsi, __expf(e.y - rm) * rsi,
                                __expf(e.z - rm) * rsi, __expf(e.w - rm) * rsi);
        float pc0 = __expf(e.x - cm4.x) * csi4.x;
        float pc1 = __expf(e.y - cm4.y) * csi4.y;
        float pc2 = __expf(e.z - cm4.z) * csi4.z;
        float pc3 = __expf(e.w - cm4.w) * csi4.w;
        size_t off = (size_t)R * HW + c0 + tx * 4;
        *(float4*)&Oab[off] = pr;
        __half2 h0 = __floats2half2_rn(pr.x, pr.y);
        __half2 h1 = __floats2half2_rn(pr.z, pr.w);
        *(uint2*)&Hab[off] = make_uint2(*(uint32_t*)&h0, *(uint32_t*)&h1);
        t_ba[tx * 4 + 0][r_in] = pc0;
        t_ba[tx * 4 + 1][r_in] = pc1;
        t_ba[tx * 4 + 2][r_in] = pc2;
        t_ba[tx * 4 + 3][r_in] = pc3;
    }
    __syncthreads();
#pragma unroll
    for (int it = 0; it < 4; ++it) {
        int c_in = it * 16 + ty;
        float4 p = *(const float4*)&t_ba[c_in][tx * 4];
        size_t off = (size_t)(c0 + c_in) * HW + r0 + tx * 4;
        *(float4*)&Oba[off] = p;
        __half2 h0 = __floats2half2_rn(p.x, p.y);
        __half2 h1 = __floats2half2_rn(p.z, p.w);
        *(uint2*)&Hba[off] = make_uint2(*(uint32_t*)&h0, *(uint32_t*)&h1);
    }
}

// ---------------- K7: raw -> fp16 ----------------
__global__ void tohalf_kernel(const float* __restrict__ a_raw, const float* __restrict__ b_raw) {
    const int t = blockIdx.y;
    const float* __restrict__ src = (t == 0 ? a_raw : b_raw);
    __half* __restrict__ dst = &g_raw_h[t][0][0];
    size_t i = ((size_t)blockIdx.x * 256 + threadIdx.x) * 4;
    float4 v = *(const float4*)&src[i];
    __half2* d2 = (__half2*)&dst[i];
    d2[0] = __floats2half2_rn(v.x, v.y);
    d2[1] = __floats2half2_rn(v.z, v.w);
}

// ---------------- K8: warp matmul, 128x128 tile, 256 thr, 2 CTAs/SM, 3-stage (per-n) ----------------
#define G2_AST (128 * 72)
#define G2_BST (64 * 136)
#define G2_NC 64
__global__ __launch_bounds__(256, 2) void wgemm_kernel(int n, float* __restrict__ out) {
    extern __shared__ __align__(16) __half gshm[];
    __half* As = gshm;
    __half* Bs = gshm + 3 * G2_AST;
    const uint32_t su = smaddr(gshm);

    const int dir = blockIdx.z;
    const __half* __restrict__ A = g_raw_h[dir][n];
    const __half* __restrict__ B = g_corr_h[dir ^ 1][n];
    float* __restrict__ C = out + (size_t)4 * HW * HW
                                + (size_t)dir * 2 * CIN * HW + (size_t)n * CIN * HW;
    const int m0 = blockIdx.y * 128, n0 = blockIdx.x * 128;
    const int tid = threadIdx.x, lane = tid & 31, warp = tid >> 5;
    const int wm = warp & 3, wn = warp >> 2;
    const int r16 = lane & 15, c8 = (lane >> 4) << 3;

    float acc[2][8][4];
#pragma unroll
    for (int i = 0; i < 2; ++i)
#pragma unroll
        for (int j = 0; j < 8; ++j)
#pragma unroll
            for (int k = 0; k < 4; ++k) acc[i][j][k] = 0.f;

    auto loadst = [&](int st, int j) {
        const int k0 = j * 64;
#pragma unroll
        for (int i = 0; i < 8; ++i) {
            int idx = tid + i * 256;
            if (idx < 1024) {
                int row = idx >> 3, cp = (idx & 7) * 8;
                int gr = m0 + row;
                int ok = gr < CIN;
                cpa16u(su + (st * G2_AST + row * 72 + cp) * 2,
                       &A[(size_t)(ok ? gr : 0) * HW + k0 + cp], ok ? 16 : 0);
            } else {
                int ix = idx - 1024;
                int row = ix >> 4, cp = (ix & 15) * 8;
                cpa16u(su + (3 * G2_AST + st * G2_BST + row * 136 + cp) * 2,
                       &B[(size_t)(k0 + row) * HW + n0 + cp], 16);
            }
        }
    };

    loadst(0, 0); CP_COMMIT();
    loadst(1, 1); CP_COMMIT();

    for (int j = 0; j < G2_NC; ++j) {
        const int st = j % 3;
        if (j + 1 < G2_NC) CP_WAIT(1); else CP_WAIT(0);
        __syncthreads();
        if (j + 2 < G2_NC) { loadst((j + 2) % 3, j + 2); CP_COMMIT(); }

#pragma unroll
        for (int ks = 0; ks < 64; ks += 16) {
            uint32_t a[2][4], b[4][4];
#pragma unroll
            for (int mi = 0; mi < 2; ++mi)
                ldsm4(a[mi], As + st * G2_AST + (wm * 32 + mi * 16 + r16) * 72 + ks + c8);
#pragma unroll
            for (int nj = 0; nj < 4; ++nj)
                ldsm4t(b[nj], Bs + st * G2_BST + (ks + r16) * 136 + wn * 64 + nj * 16 + c8);
#pragma unroll
            for (int mi = 0; mi < 2; ++mi)
#pragma unroll
                for (int nj = 0; nj < 4; ++nj) {
                    mma16816(acc[mi][nj * 2],     a[mi], &b[nj][0]);
                    mma16816(acc[mi][nj * 2 + 1], a[mi], &b[nj][2]);
                }
        }
        __syncthreads();
    }

#pragma unroll
    for (int mi = 0; mi < 2; ++mi)
#pragma unroll
        for (int nj = 0; nj < 8; ++nj) {
            int row = m0 + wm * 32 + mi * 16 + (lane >> 2);
            int col = n0 + wn * 64 + nj * 8 + (lane & 3) * 2;
            if (row < CIN)
                *(float2*)&C[(size_t)row * HW + col] = make_float2(acc[mi][nj][0], acc[mi][nj][1]);
            if (row + 8 < CIN)
                *(float2*)&C[(size_t)(row + 8) * HW + col] = make_float2(acc[mi][nj][2], acc[mi][nj][3]);
        }
}

// ---------------- launch ----------------
extern "C" void kernel_launch(void* const* d_in, const int* in_sizes, int n_in,
                              void* d_out, int out_size) {
    const float* fa    = (const float*)d_in[0];
    const float* fb    = (const float*)d_in[1];
    const float* a_raw = (const float*)d_in[2];
    const float* b_raw = (const float*)d_in[3];
    const float* Wa    = (const float*)d_in[4];
    const float* ba    = (const float*)d_in[5];
    const float* Wb    = (const float*)d_in[6];
    const float* bb    = (const float*)d_in[7];
    float* out = (float*)d_out;
    float* out_ab = out;
    float* out_ba = out + (size_t)2 * HW * HW;

    const int c_smem = 32 * 256 * 4 + 48 * 32 * 4 + 2 * 32 * 264 * 2 + 2 * 48 * 40 * 2; // 80384
    const int e_smem = 2 * E2_STG * 2;                   // 104448
    const int g_smem = 3 * (G2_AST + G2_BST) * 2;        // 107520
    cudaFuncSetAttribute(conv_mma_kernel, cudaFuncAttributeMaxDynamicSharedMemorySize, c_smem);
    cudaFuncSetAttribute(energy_mma_kernel, cudaFuncAttributeMaxDynamicSharedMemorySize, e_smem);
    cudaFuncSetAttribute(wgemm_kernel, cudaFuncAttributeMaxDynamicSharedMemorySize, g_smem);

    // ONE extra stream (proven capture-safe); full n=1 chain rides it.
    cudaStream_t s2;
    cudaStreamCreate(&s2);
    cudaEvent_t ef, eT, eB;
    cudaEventCreateWithFlags(&ef, cudaEventDisableTiming);
    cudaEventCreateWithFlags(&eT, cudaEventDisableTiming);
    cudaEventCreateWithFlags(&eB, cudaEventDisableTiming);

    // fork s2 from the capture stream
    cudaEventRecord(ef, 0);
    cudaStreamWaitEvent(s2, ef, 0);

    // stream 0: tohalf first (feeds both wgemms), then the full n=0 chain
    tohalf_kernel<<<dim3(8704, 2), 256>>>(a_raw, b_raw);
    cudaEventRecord(eT, 0);
    conv_mma_kernel<<<dim3(16, 3, 2), 256, c_smem>>>(0, fa, fb, Wa, ba, Wb, bb);
    inorm_kernel<<<dim3(CMID, 2), 256>>>(0);
    l2norm_kernel<<<dim3(HW / 64, 2), 256>>>(0);
    energy_mma_kernel<<<dim3(32, 32), 256, e_smem>>>(0);
    combine_kernel<<<dim3(HW / 256, 2), 256>>>(0);
    writeout_kernel<<<dim3(64, 64), 256>>>(0, out_ab, out_ba);
    wgemm_kernel<<<dim3(32, 9, 2), 256, g_smem>>>(0, out);

    // s2: full n=1 chain (waits on eT only before its wgemm)
    conv_mma_kernel<<<dim3(16, 3, 2), 256, c_smem, s2>>>(1, fa, fb, Wa, ba, Wb, bb);
    inorm_kernel<<<dim3(CMID, 2), 256, 0, s2>>>(1);
    l2norm_kernel<<<dim3(HW / 64, 2), 256, 0, s2>>>(1);
    energy_mma_kernel<<<dim3(32, 32), 256, e_smem, s2>>>(1);
    combine_kernel<<<dim3(HW / 256, 2), 256, 0, s2>>>(1);
    writeout_kernel<<<dim3(64, 64), 256, 0, s2>>>(1, out_ab, out_ba);
    cudaStreamWaitEvent(s2, eT, 0);
    wgemm_kernel<<<dim3(32, 9, 2), 256, g_smem, s2>>>(1, out);
    cudaEventRecord(eB, s2);

    // join
    cudaStreamWaitEvent(0, eB, 0);
}